// round 5
// baseline (speedup 1.0000x reference)
#include <cuda_runtime.h>
#include <cuda_bf16.h>
#include <cstdint>

#define N_NODESC 50000
#define N_EDGESC 500000
#define DIMC     128
#define A_DIMC   64
#define NPADC    50048      // 391 * 128
#define MBLKS    391
#define STRIPS   26
#define TCNT     17

// ---------------- device scratch (no allocation allowed) ----------------
__device__ __align__(16) __nv_bfloat16 g_hh[(size_t)NPADC * DIMC];     // h hi (bf16)
__device__ __align__(16) __nv_bfloat16 g_hl[(size_t)NPADC * DIMC];     // h lo (bf16)
__device__ __align__(16) __nv_bfloat16 g_Bh[(size_t)TCNT * DIMC * DIMC]; // [t][n][k]
__device__ __align__(16) __nv_bfloat16 g_Bl[(size_t)TCNT * DIMC * DIMC];
__device__ __align__(16) __nv_bfloat16 g_projb[(size_t)16 * N_NODESC * DIMC]; // 204.8MB
__device__ __align__(16) float g_q[(size_t)N_NODESC * DIMC];   // cols 0..63 qd, 64..127 qs
__device__ __align__(16) float g_hN[(size_t)N_NODESC * DIMC];
__device__ float g_ex[N_EDGESC];
__device__ float g_denom[N_NODESC];
__device__ __align__(16) float g_WlT[2 * DIMC * DIMC];

// ---------------- ptx helpers ----------------
__device__ __forceinline__ uint32_t smem_u32(const void* p) {
    uint32_t a;
    asm("{ .reg .u64 t; cvta.to.shared.u64 t, %1; cvt.u32.u64 %0, t; }" : "=r"(a) : "l"(p));
    return a;
}
__device__ __forceinline__ void cp16(uint32_t dst, const void* src) {
    asm volatile("cp.async.cg.shared.global [%0], [%1], 16;" :: "r"(dst), "l"(src));
}
#define CP_COMMIT() asm volatile("cp.async.commit_group;" ::: "memory")
#define CP_WAIT(n)  asm volatile("cp.async.wait_group %0;" :: "n"(n) : "memory")

__device__ __forceinline__ void ldmx4(uint32_t* r, uint32_t addr) {
    asm volatile("ldmatrix.sync.aligned.m8n8.x4.shared.b16 {%0,%1,%2,%3}, [%4];"
                 : "=r"(r[0]), "=r"(r[1]), "=r"(r[2]), "=r"(r[3]) : "r"(addr));
}
__device__ __forceinline__ void mma16816(float* d, const uint32_t* a, uint32_t b0, uint32_t b1) {
    asm volatile("mma.sync.aligned.m16n8k16.row.col.f32.bf16.bf16.f32 "
                 "{%0,%1,%2,%3}, {%4,%5,%6,%7}, {%8,%9}, {%0,%1,%2,%3};"
                 : "+f"(d[0]), "+f"(d[1]), "+f"(d[2]), "+f"(d[3])
                 : "r"(a[0]), "r"(a[1]), "r"(a[2]), "r"(a[3]), "r"(b0), "r"(b1));
}

// ---------------- prep kernels ----------------
__global__ void k_zero() {
    size_t i = (size_t)blockIdx.x * blockDim.x + threadIdx.x;
    if (i < (size_t)N_NODESC * DIMC) g_hN[i] = 0.0f;
    if (i < N_NODESC) g_denom[i] = 0.0f;
}

__global__ void k_cvtA(const float* __restrict__ h) {
    int i = blockIdx.x * 256 + threadIdx.x;
    if (i < N_NODESC * DIMC) {
        float v = h[i];
        __nv_bfloat16 hi = __float2bfloat16(v);
        g_hh[i] = hi;
        g_hl[i] = __float2bfloat16(v - __bfloat162float(hi));
    }
}

__global__ void k_prepB(const float* __restrict__ rel, const float* __restrict__ W_a,
                        const float* __restrict__ W_lin) {
    int i = blockIdx.x * 256 + threadIdx.x;
    if (i < TCNT * DIMC * DIMC) {
        int t = i >> 14, n = (i >> 7) & 127, k = i & 127;
        float v;
        if (t < 16) {
            int side = t >> 3, r = t & 7;
            v = rel[((size_t)(r * 256 + side * 128 + k)) * 128 + n];
        } else {
            v = (n < A_DIMC) ? W_a[n * 256 + k] : W_a[(n - A_DIMC) * 256 + DIMC + k];
        }
        __nv_bfloat16 hi = __float2bfloat16(v);
        g_Bh[i] = hi;
        g_Bl[i] = __float2bfloat16(v - __bfloat162float(hi));
    }
    if (i < 2 * DIMC * DIMC) {
        int k = i >> 7, o = i & 127;
        g_WlT[i] = W_lin[o * 256 + k];
    }
}

// ---------------- persistent-strip 17-way GEMM on mma.sync ----------------
// grid (STRIPS, TCNT), 256 threads. B resident; A double-buffered via cp.async.
// t<16: 2-term split (ah*bh + ah*bl). t=16: 3-term (+ al*bh).
#define ROWB 272
#define TILEB 34816                 // 128 * 272
#define SM_TOTAL (6 * TILEB)        // Bh, Bl, Ah0, Ah1, Al0, Al1

__global__ void __launch_bounds__(256, 1) k_tgemm() {
    extern __shared__ char smem[];
    const uint32_t sb  = smem_u32(smem);
    const uint32_t sBh = sb;
    const uint32_t sBl = sb + TILEB;
    const uint32_t sAh0 = sb + 2 * TILEB;
    const uint32_t sAh1 = sb + 3 * TILEB;
    const uint32_t sAl0 = sb + 4 * TILEB;
    const uint32_t sAl1 = sb + 5 * TILEB;

    const int tid = threadIdx.x;
    const int lane = tid & 31;
    const int wid = tid >> 5;
    const int t = blockIdx.y;
    const int strip = blockIdx.x;
    const int n_m = (MBLKS - strip + STRIPS - 1) / STRIPS;
    const bool use3 = (t == 16);

    // ---- B tiles once ----
    {
        const __nv_bfloat16* Bh = g_Bh + (size_t)t * DIMC * DIMC;
        const __nv_bfloat16* Bl = g_Bl + (size_t)t * DIMC * DIMC;
        for (int idx = tid; idx < 2048; idx += 256) {
            int row = idx >> 4, c = idx & 15;
            uint32_t doff = row * ROWB + c * 16;
            size_t soff = (size_t)row * DIMC + c * 8;
            cp16(sBh + doff, Bh + soff);
            cp16(sBl + doff, Bl + soff);
        }
        // A tile 0 into buffer 0
        const size_t mbase = (size_t)strip * 128 * DIMC;
        for (int idx = tid; idx < 2048; idx += 256) {
            int row = idx >> 4, c = idx & 15;
            uint32_t doff = row * ROWB + c * 16;
            size_t soff = mbase + (size_t)row * DIMC + c * 8;
            cp16(sAh0 + doff, g_hh + soff);
            if (use3) cp16(sAl0 + doff, g_hl + soff);
        }
    }
    CP_COMMIT();

    const int wm = wid & 3;          // m 32-block
    const int wn = wid >> 2;         // n 64-block
    const int mb = wm * 32;
    const int nb = wn * 64;

    // ldmatrix lane addressing
    const int a_row = (lane & 7) + 8 * ((lane >> 3) & 1);
    const int a_kh  = (lane >> 4) * 16;             // bytes
    const int b_row = (lane & 7) + 8 * (lane >> 4);
    const int b_kh  = ((lane >> 3) & 1) * 16;       // bytes

    const int rb_local = mb + (lane >> 2);
    const int cbase = nb + 2 * (lane & 3);

    for (int it = 0; it < n_m; it++) {
        const uint32_t sAh = (it & 1) ? sAh1 : sAh0;
        const uint32_t sAl = (it & 1) ? sAl1 : sAl0;

        // prefetch next A tile into the other buffer
        if (it + 1 < n_m) {
            const uint32_t dAh = (it & 1) ? sAh0 : sAh1;
            const uint32_t dAl = (it & 1) ? sAl0 : sAl1;
            const size_t mbase = (size_t)(strip + (it + 1) * STRIPS) * 128 * DIMC;
            for (int idx = tid; idx < 2048; idx += 256) {
                int row = idx >> 4, c = idx & 15;
                uint32_t doff = row * ROWB + c * 16;
                size_t soff = mbase + (size_t)row * DIMC + c * 8;
                cp16(dAh + doff, g_hh + soff);
                if (use3) cp16(dAl + doff, g_hl + soff);
            }
            CP_COMMIT();
            CP_WAIT(1);       // current tile (and B) complete; next in flight
        } else {
            CP_WAIT(0);
        }
        __syncthreads();

        float acc[2][8][4];
#pragma unroll
        for (int i = 0; i < 2; i++)
#pragma unroll
            for (int j = 0; j < 8; j++)
#pragma unroll
                for (int v = 0; v < 4; v++) acc[i][j][v] = 0.0f;

#pragma unroll
        for (int k0 = 0; k0 < 8; k0++) {
            const uint32_t kbyte = k0 * 32;
            uint32_t ah[2][4], al[2][4], bh[4][4], bl[4][4];
#pragma unroll
            for (int mt = 0; mt < 2; mt++) {
                uint32_t ar = (mb + mt * 16 + a_row) * ROWB + kbyte + a_kh;
                ldmx4(ah[mt], sAh + ar);
                if (use3) ldmx4(al[mt], sAl + ar);
            }
#pragma unroll
            for (int q = 0; q < 4; q++) {
                uint32_t br = (nb + q * 16 + b_row) * ROWB + kbyte + b_kh;
                ldmx4(bh[q], sBh + br);
                ldmx4(bl[q], sBl + br);
            }
#pragma unroll
            for (int mt = 0; mt < 2; mt++) {
#pragma unroll
                for (int nf = 0; nf < 8; nf++) {
                    uint32_t h0 = bh[nf >> 1][(nf & 1) * 2], h1 = bh[nf >> 1][(nf & 1) * 2 + 1];
                    uint32_t l0 = bl[nf >> 1][(nf & 1) * 2], l1 = bl[nf >> 1][(nf & 1) * 2 + 1];
                    mma16816(acc[mt][nf], ah[mt], h0, h1);
                    mma16816(acc[mt][nf], ah[mt], l0, l1);
                    if (use3) mma16816(acc[mt][nf], al[mt], h0, h1);
                }
            }
        }

        // ---- epilogue for this tile ----
        const int m0 = (strip + it * STRIPS) * 128;
#pragma unroll
        for (int mt = 0; mt < 2; mt++) {
#pragma unroll
            for (int pair = 0; pair < 2; pair++) {
                int m = m0 + rb_local + mt * 16 + pair * 8;
                if (m >= N_NODESC) continue;
                if (t < 16) {
                    __nv_bfloat16* dp = g_projb + ((size_t)t * N_NODESC + m) * DIMC;
#pragma unroll
                    for (int nf = 0; nf < 8; nf++) {
                        float v0 = acc[mt][nf][pair * 2 + 0];
                        float v1 = acc[mt][nf][pair * 2 + 1];
                        uint32_t pk;
                        asm("cvt.rn.satfinite.bf16x2.f32 %0, %1, %2;" : "=r"(pk) : "f"(v1), "f"(v0));
                        *(uint32_t*)(dp + cbase + nf * 8) = pk;
                    }
                } else {
                    float* dp = g_q + (size_t)m * DIMC;
#pragma unroll
                    for (int nf = 0; nf < 8; nf++) {
                        *(float2*)(dp + cbase + nf * 8) =
                            make_float2(acc[mt][nf][pair * 2], acc[mt][nf][pair * 2 + 1]);
                    }
                }
            }
        }
        __syncthreads();   // all reads of this A buffer done before it is refilled
    }
}

// ---------------- per-edge attention score ----------------
__global__ void k_score(const int* __restrict__ src, const int* __restrict__ dst,
                        const float* __restrict__ rel_att, const float* __restrict__ b_a) {
    int e = blockIdx.x * 8 + threadIdx.y;
    int lane = threadIdx.x;
    int s = __ldg(&src[e]);
    int d = __ldg(&dst[e]);
    float2 qd = *(const float2*)&g_q[(size_t)d * DIMC + lane * 2];
    float2 qs = *(const float2*)&g_q[(size_t)s * DIMC + A_DIMC + lane * 2];
    float2 ba = *(const float2*)&b_a[lane * 2];
    float2 ra = *(const float2*)&rel_att[lane * 2];
    float x0 = qd.x + qs.x + ba.x;
    x0 = x0 > 0.f ? x0 : 0.01f * x0;
    float x1 = qd.y + qs.y + ba.y;
    x1 = x1 > 0.f ? x1 : 0.01f * x1;
    float p = ra.x * x0 + ra.y * x1;
#pragma unroll
    for (int o = 16; o > 0; o >>= 1) p += __shfl_xor_sync(0xffffffffu, p, o);
    if (lane == 0) {
        float ex = expf(p);
        g_ex[e] = ex;
        atomicAdd(&g_denom[d], ex);
    }
}

// ---------------- per-edge message (bf16 proj table, vector RED) ----------------
__global__ void k_msg(const float* __restrict__ h, const int* __restrict__ src,
                      const int* __restrict__ dst, const int* __restrict__ etype) {
    int e = blockIdx.x * 8 + threadIdx.y;
    int lane = threadIdx.x;
    int s = __ldg(&src[e]);
    int d = __ldg(&dst[e]);
    int r = __ldg(&etype[e]);
    float attn = __fdividef(g_ex[e], g_denom[d]);
    uint2 pdw = *(const uint2*)(g_projb + ((size_t)r * N_NODESC + d) * DIMC + lane * 4);
    uint2 psw = *(const uint2*)(g_projb + ((size_t)(8 + r) * N_NODESC + s) * DIMC + lane * 4);
    float2 pd0 = __bfloat1622float2(*(__nv_bfloat162*)&pdw.x);
    float2 pd1 = __bfloat1622float2(*(__nv_bfloat162*)&pdw.y);
    float2 ps0 = __bfloat1622float2(*(__nv_bfloat162*)&psw.x);
    float2 ps1 = __bfloat1622float2(*(__nv_bfloat162*)&psw.y);
    float4 hs = *(const float4*)&h[(size_t)s * DIMC + lane * 4];
    float g0 = 1.0f / (1.0f + expf(-(pd0.x + ps0.x)));
    float g1 = 1.0f / (1.0f + expf(-(pd0.y + ps0.y)));
    float g2 = 1.0f / (1.0f + expf(-(pd1.x + ps1.x)));
    float g3 = 1.0f / (1.0f + expf(-(pd1.y + ps1.y)));
    float m0 = hs.x * attn * g0;
    float m1 = hs.y * attn * g1;
    float m2 = hs.z * attn * g2;
    float m3 = hs.w * attn * g3;
    float* o = &g_hN[(size_t)d * DIMC + lane * 4];
    asm volatile("red.global.add.v4.f32 [%0], {%1, %2, %3, %4};"
                 :: "l"(o), "f"(m0), "f"(m1), "f"(m2), "f"(m3) : "memory");
}

// ---------------- f32x2 packed-FMA helpers for final GEMM ----------------
__device__ __forceinline__ unsigned long long pack2(float x) {
    unsigned long long r;
    asm("mov.b64 %0, {%1, %1};" : "=l"(r) : "f"(x));
    return r;
}
__device__ __forceinline__ void ffma2(unsigned long long& acc, unsigned long long a,
                                      unsigned long long b) {
    asm("fma.rn.f32x2 %0, %1, %2, %0;" : "+l"(acc) : "l"(a), "l"(b));
}
__device__ __forceinline__ float2 unpack2(unsigned long long v) {
    float2 r;
    asm("mov.b64 {%0, %1}, %2;" : "=f"(r.x), "=f"(r.y) : "l"(v));
    return r;
}

// ---------------- final: out = leaky([h ; h_N] @ W_lin^T + b_lin) ----------------
__global__ __launch_bounds__(256) void k_final(const float* __restrict__ h,
                                               const float* __restrict__ b_lin,
                                               float* __restrict__ out) {
    __shared__ float As[16][132];
    __shared__ float Bs[16][128];

    const int tid = threadIdx.x;
    const int m0 = blockIdx.x * 128;
    const int tr = tid >> 4;
    const int tc = tid & 15;
    const int a_row = tid >> 2;
    const int a_col = (tid & 3) << 2;
    const int b_row = tid >> 5;
    const int b_col = (tid & 31) << 2;

    unsigned long long acc[8][4];
#pragma unroll
    for (int i = 0; i < 8; i++)
#pragma unroll
        for (int j = 0; j < 4; j++) acc[i][j] = 0ull;

    for (int k0 = 0; k0 < 2 * DIMC; k0 += 16) {
        const float* Asrc = (k0 < DIMC) ? (h + k0) : (g_hN + (k0 - DIMC));
#pragma unroll
        for (int half = 0; half < 2; half++) {
            int m = a_row + half * 64;
            float4 v = make_float4(0.f, 0.f, 0.f, 0.f);
            if (m0 + m < N_NODESC)
                v = *(const float4*)(Asrc + (size_t)(m0 + m) * DIMC + a_col);
            As[a_col + 0][m] = v.x;
            As[a_col + 1][m] = v.y;
            As[a_col + 2][m] = v.z;
            As[a_col + 3][m] = v.w;
        }
#pragma unroll
        for (int half = 0; half < 2; half++) {
            int kk = b_row + half * 8;
            *(float4*)&Bs[kk][b_col] =
                *(const float4*)(g_WlT + (size_t)(k0 + kk) * DIMC + b_col);
        }
        __syncthreads();

#pragma unroll
        for (int k = 0; k < 16; k++) {
            float4 a0 = *(const float4*)&As[k][tr * 8];
            float4 a1 = *(const float4*)&As[k][tr * 8 + 4];
            unsigned long long ap[8];
            ap[0] = pack2(a0.x); ap[1] = pack2(a0.y); ap[2] = pack2(a0.z); ap[3] = pack2(a0.w);
            ap[4] = pack2(a1.x); ap[5] = pack2(a1.y); ap[6] = pack2(a1.z); ap[7] = pack2(a1.w);
            ulonglong2 bq0 = *(const ulonglong2*)&Bs[k][tc * 8];
            ulonglong2 bq1 = *(const ulonglong2*)&Bs[k][tc * 8 + 4];
            unsigned long long bp[4] = {bq0.x, bq0.y, bq1.x, bq1.y};
#pragma unroll
            for (int i = 0; i < 8; i++)
#pragma unroll
                for (int j = 0; j < 4; j++) ffma2(acc[i][j], ap[i], bp[j]);
        }
        __syncthreads();
    }

#pragma unroll
    for (int i = 0; i < 8; i++) {
        int m = m0 + tr * 8 + i;
        if (m < N_NODESC) {
            float* cp = out + (size_t)m * DIMC + tc * 8;
#pragma unroll
            for (int j = 0; j < 4; j++) {
                float2 p = unpack2(acc[i][j]);
                float2 bl = *(const float2*)&b_lin[tc * 8 + j * 2];
                float v0 = p.x + bl.x;
                float v1 = p.y + bl.y;
                v0 = v0 > 0.f ? v0 : 0.01f * v0;
                v1 = v1 > 0.f ? v1 : 0.01f * v1;
                *(float2*)(cp + j * 2) = make_float2(v0, v1);
            }
        }
    }
}

// ---------------- launch ----------------
extern "C" void kernel_launch(void* const* d_in, const int* in_sizes, int n_in,
                              void* d_out, int out_size) {
    const float* h      = (const float*)d_in[0];
    const float* rel    = (const float*)d_in[1];
    const float* relatt = (const float*)d_in[2];
    const float* W_a    = (const float*)d_in[3];
    const float* b_a    = (const float*)d_in[4];
    const float* W_lin  = (const float*)d_in[5];
    const float* b_lin  = (const float*)d_in[6];
    const int* src   = (const int*)d_in[7];
    const int* dst   = (const int*)d_in[8];
    const int* etype = (const int*)d_in[9];
    float* out = (float*)d_out;

    cudaFuncSetAttribute(k_tgemm, cudaFuncAttributeMaxDynamicSharedMemorySize, SM_TOTAL);

    k_zero<<<(N_NODESC * DIMC + 1023) / 1024, 1024>>>();
    k_cvtA<<<(N_NODESC * DIMC + 255) / 256, 256>>>(h);
    k_prepB<<<(TCNT * DIMC * DIMC + 255) / 256, 256>>>(rel, W_a, W_lin);

    dim3 gg(STRIPS, TCNT);
    k_tgemm<<<gg, 256, SM_TOTAL>>>();

    dim3 be(32, 8);
    k_score<<<N_EDGESC / 8, be>>>(src, dst, relatt, b_a);
    k_msg<<<N_EDGESC / 8, be>>>(h, src, dst, etype);

    k_final<<<(N_NODESC + 127) / 128, 256>>>(h, b_lin, out);
}

// round 6
// speedup vs baseline: 1.4045x; 1.4045x over previous
#include <cuda_runtime.h>
#include <cuda_bf16.h>
#include <cstdint>

#define N_NODESC 50000
#define N_EDGESC 500000
#define DIMC     128
#define A_DIMC   64
#define NPADC    50048      // 391 * 128
#define MBLKS    391
#define STRIPS2  37         // 37*16 = 592 CTAs = 4 exact waves on 148 SMs
#define TCNT     17

// ---------------- device scratch (no allocation allowed) ----------------
__device__ __align__(16) __nv_bfloat16 g_hh[(size_t)NPADC * DIMC];     // h hi (bf16)
__device__ __align__(16) __nv_bfloat16 g_hl[(size_t)NPADC * DIMC];     // h lo (bf16)
__device__ __align__(16) __nv_bfloat16 g_Bh[(size_t)TCNT * DIMC * DIMC]; // [t][n][k]
__device__ __align__(16) __nv_bfloat16 g_Bl[(size_t)TCNT * DIMC * DIMC];
__device__ __align__(16) __nv_bfloat16 g_projb[(size_t)16 * N_NODESC * DIMC]; // 204.8MB
__device__ __align__(16) float g_q[(size_t)N_NODESC * DIMC];   // cols 0..63 qd, 64..127 qs
__device__ __align__(16) float g_hN[(size_t)N_NODESC * DIMC];
__device__ float g_ex[N_EDGESC];
__device__ float g_denom[N_NODESC];
__device__ __align__(16) float g_WlT[2 * DIMC * DIMC];

// ---------------- ptx helpers ----------------
__device__ __forceinline__ uint32_t smem_u32(const void* p) {
    uint32_t a;
    asm("{ .reg .u64 t; cvta.to.shared.u64 t, %1; cvt.u32.u64 %0, t; }" : "=r"(a) : "l"(p));
    return a;
}
__device__ __forceinline__ void cp16(uint32_t dst, const void* src) {
    asm volatile("cp.async.cg.shared.global [%0], [%1], 16;" :: "r"(dst), "l"(src));
}
#define CP_COMMIT() asm volatile("cp.async.commit_group;" ::: "memory")
#define CP_WAIT(n)  asm volatile("cp.async.wait_group %0;" :: "n"(n) : "memory")

__device__ __forceinline__ void ldmx4(uint32_t* r, uint32_t addr) {
    asm volatile("ldmatrix.sync.aligned.m8n8.x4.shared.b16 {%0,%1,%2,%3}, [%4];"
                 : "=r"(r[0]), "=r"(r[1]), "=r"(r[2]), "=r"(r[3]) : "r"(addr));
}
__device__ __forceinline__ void mma16816(float* d, const uint32_t* a, uint32_t b0, uint32_t b1) {
    asm volatile("mma.sync.aligned.m16n8k16.row.col.f32.bf16.bf16.f32 "
                 "{%0,%1,%2,%3}, {%4,%5,%6,%7}, {%8,%9}, {%0,%1,%2,%3};"
                 : "+f"(d[0]), "+f"(d[1]), "+f"(d[2]), "+f"(d[3])
                 : "r"(a[0]), "r"(a[1]), "r"(a[2]), "r"(a[3]), "r"(b0), "r"(b1));
}

// ---------------- prep kernels ----------------
__global__ void k_zero() {
    size_t i = (size_t)blockIdx.x * blockDim.x + threadIdx.x;
    if (i < (size_t)N_NODESC * DIMC) g_hN[i] = 0.0f;
    if (i < N_NODESC) g_denom[i] = 0.0f;
}

__global__ void k_cvtA(const float* __restrict__ h) {
    int i = blockIdx.x * 256 + threadIdx.x;
    if (i < N_NODESC * DIMC) {
        float v = h[i];
        __nv_bfloat16 hi = __float2bfloat16(v);
        g_hh[i] = hi;
        g_hl[i] = __float2bfloat16(v - __bfloat162float(hi));
    }
}

__global__ void k_prepB(const float* __restrict__ rel, const float* __restrict__ W_a,
                        const float* __restrict__ W_lin) {
    int i = blockIdx.x * 256 + threadIdx.x;
    if (i < TCNT * DIMC * DIMC) {
        int t = i >> 14, n = (i >> 7) & 127, k = i & 127;
        float v;
        if (t < 16) {
            int side = t >> 3, r = t & 7;
            v = rel[((size_t)(r * 256 + side * 128 + k)) * 128 + n];
        } else {
            v = (n < A_DIMC) ? W_a[n * 256 + k] : W_a[(n - A_DIMC) * 256 + DIMC + k];
        }
        __nv_bfloat16 hi = __float2bfloat16(v);
        g_Bh[i] = hi;
        g_Bl[i] = __float2bfloat16(v - __bfloat162float(hi));
    }
    if (i < 2 * DIMC * DIMC) {
        int k = i >> 7, o = i & 127;
        g_WlT[i] = W_lin[o * 256 + k];
    }
}

#define ROWB 272
#define TILEB 34816                 // 128 * 272
#define SM_GEMM (4 * TILEB)         // 136 KB both kernels

// ---------------- gate GEMMs (t<16), 2-term split, persistent strips ----------------
// grid (STRIPS2, 16), 256 threads. B resident in SMEM; A double-buffered cp.async.
__global__ void __launch_bounds__(256, 1) k_tgemm2() {
    extern __shared__ char smem[];
    const uint32_t sb  = smem_u32(smem);
    const uint32_t sBh  = sb;
    const uint32_t sBl  = sb + TILEB;
    const uint32_t sAh0 = sb + 2 * TILEB;
    const uint32_t sAh1 = sb + 3 * TILEB;

    const int tid = threadIdx.x;
    const int lane = tid & 31;
    const int wid = tid >> 5;
    const int t = blockIdx.y;
    const int strip = blockIdx.x;
    const int n_m = (MBLKS - strip + STRIPS2 - 1) / STRIPS2;

    // B tiles once + A tile 0
    {
        const __nv_bfloat16* Bh = g_Bh + (size_t)t * DIMC * DIMC;
        const __nv_bfloat16* Bl = g_Bl + (size_t)t * DIMC * DIMC;
        const size_t mbase = (size_t)strip * 128 * DIMC;
        for (int idx = tid; idx < 2048; idx += 256) {
            int row = idx >> 4, c = idx & 15;
            uint32_t doff = row * ROWB + c * 16;
            size_t soff = (size_t)row * DIMC + c * 8;
            cp16(sBh + doff, Bh + soff);
            cp16(sBl + doff, Bl + soff);
            cp16(sAh0 + doff, g_hh + mbase + soff);
        }
    }
    CP_COMMIT();

    const int mb = (wid & 3) * 32;
    const int nb = (wid >> 2) * 64;
    const int a_row = (lane & 7) + 8 * ((lane >> 3) & 1);
    const int a_kh  = (lane >> 4) * 16;
    const int b_row = (lane & 7) + 8 * (lane >> 4);
    const int b_kh  = ((lane >> 3) & 1) * 16;
    const int rb_local = mb + (lane >> 2);
    const int cbase = nb + 2 * (lane & 3);

    for (int it = 0; it < n_m; it++) {
        const uint32_t sAh = (it & 1) ? sAh1 : sAh0;

        if (it + 1 < n_m) {
            const uint32_t dAh = (it & 1) ? sAh0 : sAh1;
            const size_t mbase = (size_t)(strip + (it + 1) * STRIPS2) * 128 * DIMC;
            for (int idx = tid; idx < 2048; idx += 256) {
                int row = idx >> 4, c = idx & 15;
                cp16(dAh + row * ROWB + c * 16, g_hh + mbase + (size_t)row * DIMC + c * 8);
            }
            CP_COMMIT();
            CP_WAIT(1);
        } else {
            CP_WAIT(0);
        }
        __syncthreads();

        float acc[2][8][4];
#pragma unroll
        for (int i = 0; i < 2; i++)
#pragma unroll
            for (int j = 0; j < 8; j++)
#pragma unroll
                for (int v = 0; v < 4; v++) acc[i][j][v] = 0.0f;

#pragma unroll
        for (int k0 = 0; k0 < 8; k0++) {
            const uint32_t kbyte = k0 * 32;
            uint32_t ah[2][4], bh[4][4], bl[4][4];
#pragma unroll
            for (int mt = 0; mt < 2; mt++)
                ldmx4(ah[mt], sAh + (mb + mt * 16 + a_row) * ROWB + kbyte + a_kh);
#pragma unroll
            for (int q = 0; q < 4; q++) {
                uint32_t br = (nb + q * 16 + b_row) * ROWB + kbyte + b_kh;
                ldmx4(bh[q], sBh + br);
                ldmx4(bl[q], sBl + br);
            }
#pragma unroll
            for (int mt = 0; mt < 2; mt++) {
#pragma unroll
                for (int nf = 0; nf < 8; nf++) {
                    uint32_t h0 = bh[nf >> 1][(nf & 1) * 2], h1 = bh[nf >> 1][(nf & 1) * 2 + 1];
                    uint32_t l0 = bl[nf >> 1][(nf & 1) * 2], l1 = bl[nf >> 1][(nf & 1) * 2 + 1];
                    mma16816(acc[mt][nf], ah[mt], h0, h1);
                    mma16816(acc[mt][nf], ah[mt], l0, l1);
                }
            }
        }

        const int m0 = (strip + it * STRIPS2) * 128;
#pragma unroll
        for (int mt = 0; mt < 2; mt++) {
#pragma unroll
            for (int pair = 0; pair < 2; pair++) {
                int m = m0 + rb_local + mt * 16 + pair * 8;
                if (m >= N_NODESC) continue;
                __nv_bfloat16* dp = g_projb + ((size_t)t * N_NODESC + m) * DIMC;
#pragma unroll
                for (int nf = 0; nf < 8; nf++) {
                    float v0 = acc[mt][nf][pair * 2 + 0];
                    float v1 = acc[mt][nf][pair * 2 + 1];
                    uint32_t pk;
                    asm("cvt.rn.satfinite.bf16x2.f32 %0, %1, %2;" : "=r"(pk) : "f"(v1), "f"(v0));
                    *(uint32_t*)(dp + cbase + nf * 8) = pk;
                }
            }
        }
        __syncthreads();
    }
}

// ---------------- attention GEMM (t=16), 3-term, non-persistent ----------------
__global__ void __launch_bounds__(256, 1) k_tgemm3() {
    extern __shared__ char smem[];
    const uint32_t sb = smem_u32(smem);
    const uint32_t sAh = sb, sAl = sb + TILEB, sBh = sb + 2 * TILEB, sBl = sb + 3 * TILEB;

    const int tid = threadIdx.x;
    const int lane = tid & 31;
    const int wid = tid >> 5;
    const int m0 = blockIdx.x * 128;

    {
        const __nv_bfloat16* Bh = g_Bh + (size_t)16 * DIMC * DIMC;
        const __nv_bfloat16* Bl = g_Bl + (size_t)16 * DIMC * DIMC;
        const size_t mbase = (size_t)m0 * DIMC;
        for (int idx = tid; idx < 2048; idx += 256) {
            int row = idx >> 4, c = idx & 15;
            uint32_t doff = row * ROWB + c * 16;
            size_t soff = (size_t)row * DIMC + c * 8;
            cp16(sAh + doff, g_hh + mbase + soff);
            cp16(sAl + doff, g_hl + mbase + soff);
            cp16(sBh + doff, Bh + soff);
            cp16(sBl + doff, Bl + soff);
        }
    }
    CP_COMMIT();
    CP_WAIT(0);
    __syncthreads();

    const int mb = (wid & 3) * 32;
    const int nb = (wid >> 2) * 64;
    const int a_row = (lane & 7) + 8 * ((lane >> 3) & 1);
    const int a_kh  = (lane >> 4) * 16;
    const int b_row = (lane & 7) + 8 * (lane >> 4);
    const int b_kh  = ((lane >> 3) & 1) * 16;

    float acc[2][8][4];
#pragma unroll
    for (int i = 0; i < 2; i++)
#pragma unroll
        for (int j = 0; j < 8; j++)
#pragma unroll
            for (int v = 0; v < 4; v++) acc[i][j][v] = 0.0f;

#pragma unroll
    for (int k0 = 0; k0 < 8; k0++) {
        const uint32_t kbyte = k0 * 32;
        uint32_t ah[2][4], al[2][4], bh[4][4], bl[4][4];
#pragma unroll
        for (int mt = 0; mt < 2; mt++) {
            uint32_t ar = (mb + mt * 16 + a_row) * ROWB + kbyte + a_kh;
            ldmx4(ah[mt], sAh + ar);
            ldmx4(al[mt], sAl + ar);
        }
#pragma unroll
        for (int q = 0; q < 4; q++) {
            uint32_t br = (nb + q * 16 + b_row) * ROWB + kbyte + b_kh;
            ldmx4(bh[q], sBh + br);
            ldmx4(bl[q], sBl + br);
        }
#pragma unroll
        for (int mt = 0; mt < 2; mt++) {
#pragma unroll
            for (int nf = 0; nf < 8; nf++) {
                uint32_t h0 = bh[nf >> 1][(nf & 1) * 2], h1 = bh[nf >> 1][(nf & 1) * 2 + 1];
                uint32_t l0 = bl[nf >> 1][(nf & 1) * 2], l1 = bl[nf >> 1][(nf & 1) * 2 + 1];
                mma16816(acc[mt][nf], ah[mt], h0, h1);
                mma16816(acc[mt][nf], ah[mt], l0, l1);
                mma16816(acc[mt][nf], al[mt], h0, h1);
            }
        }
    }

    const int rbase = m0 + mb + (lane >> 2);
    const int cbase = nb + 2 * (lane & 3);
#pragma unroll
    for (int mt = 0; mt < 2; mt++) {
#pragma unroll
        for (int pair = 0; pair < 2; pair++) {
            int m = rbase + mt * 16 + pair * 8;
            if (m >= N_NODESC) continue;
            float* dp = g_q + (size_t)m * DIMC;
#pragma unroll
            for (int nf = 0; nf < 8; nf++)
                *(float2*)(dp + cbase + nf * 8) =
                    make_float2(acc[mt][nf][pair * 2], acc[mt][nf][pair * 2 + 1]);
        }
    }
}

// ---------------- per-edge attention score ----------------
__global__ void k_score(const int* __restrict__ src, const int* __restrict__ dst,
                        const float* __restrict__ rel_att, const float* __restrict__ b_a) {
    int e = blockIdx.x * 8 + threadIdx.y;
    int lane = threadIdx.x;
    int s = __ldg(&src[e]);
    int d = __ldg(&dst[e]);
    float2 qd = *(const float2*)&g_q[(size_t)d * DIMC + lane * 2];
    float2 qs = *(const float2*)&g_q[(size_t)s * DIMC + A_DIMC + lane * 2];
    float2 ba = *(const float2*)&b_a[lane * 2];
    float2 ra = *(const float2*)&rel_att[lane * 2];
    float x0 = qd.x + qs.x + ba.x;
    x0 = x0 > 0.f ? x0 : 0.01f * x0;
    float x1 = qd.y + qs.y + ba.y;
    x1 = x1 > 0.f ? x1 : 0.01f * x1;
    float p = ra.x * x0 + ra.y * x1;
#pragma unroll
    for (int o = 16; o > 0; o >>= 1) p += __shfl_xor_sync(0xffffffffu, p, o);
    if (lane == 0) {
        float ex = expf(p);
        g_ex[e] = ex;
        atomicAdd(&g_denom[d], ex);
    }
}

// ---------------- per-edge message (bf16 proj table) ----------------
__global__ void k_msg(const float* __restrict__ h, const int* __restrict__ src,
                      const int* __restrict__ dst, const int* __restrict__ etype) {
    int e = blockIdx.x * 8 + threadIdx.y;
    int lane = threadIdx.x;
    int s = __ldg(&src[e]);
    int d = __ldg(&dst[e]);
    int r = __ldg(&etype[e]);
    float attn = __fdividef(g_ex[e], g_denom[d]);
    uint2 pdw = *(const uint2*)(g_projb + ((size_t)r * N_NODESC + d) * DIMC + lane * 4);
    uint2 psw = *(const uint2*)(g_projb + ((size_t)(8 + r) * N_NODESC + s) * DIMC + lane * 4);
    float2 pd0 = __bfloat1622float2(*(__nv_bfloat162*)&pdw.x);
    float2 pd1 = __bfloat1622float2(*(__nv_bfloat162*)&pdw.y);
    float2 ps0 = __bfloat1622float2(*(__nv_bfloat162*)&psw.x);
    float2 ps1 = __bfloat1622float2(*(__nv_bfloat162*)&psw.y);
    float4 hs = *(const float4*)&h[(size_t)s * DIMC + lane * 4];
    float g0 = 1.0f / (1.0f + expf(-(pd0.x + ps0.x)));
    float g1 = 1.0f / (1.0f + expf(-(pd0.y + ps0.y)));
    float g2 = 1.0f / (1.0f + expf(-(pd1.x + ps1.x)));
    float g3 = 1.0f / (1.0f + expf(-(pd1.y + ps1.y)));
    float* o = &g_hN[(size_t)d * DIMC + lane * 4];
    atomicAdd(o + 0, hs.x * attn * g0);
    atomicAdd(o + 1, hs.y * attn * g1);
    atomicAdd(o + 2, hs.z * attn * g2);
    atomicAdd(o + 3, hs.w * attn * g3);
}

// ---------------- f32x2 packed-FMA helpers for final GEMM ----------------
__device__ __forceinline__ unsigned long long pack2(float x) {
    unsigned long long r;
    asm("mov.b64 %0, {%1, %1};" : "=l"(r) : "f"(x));
    return r;
}
__device__ __forceinline__ void ffma2(unsigned long long& acc, unsigned long long a,
                                      unsigned long long b) {
    asm("fma.rn.f32x2 %0, %1, %2, %0;" : "+l"(acc) : "l"(a), "l"(b));
}
__device__ __forceinline__ float2 unpack2(unsigned long long v) {
    float2 r;
    asm("mov.b64 {%0, %1}, %2;" : "=f"(r.x), "=f"(r.y) : "l"(v));
    return r;
}

// ---------------- final: out = leaky([h ; h_N] @ W_lin^T + b_lin) ----------------
__global__ __launch_bounds__(256) void k_final(const float* __restrict__ h,
                                               const float* __restrict__ b_lin,
                                               float* __restrict__ out) {
    __shared__ float As[16][132];
    __shared__ float Bs[16][128];

    const int tid = threadIdx.x;
    const int m0 = blockIdx.x * 128;
    const int tr = tid >> 4;
    const int tc = tid & 15;
    const int a_row = tid >> 2;
    const int a_col = (tid & 3) << 2;
    const int b_row = tid >> 5;
    const int b_col = (tid & 31) << 2;

    unsigned long long acc[8][4];
#pragma unroll
    for (int i = 0; i < 8; i++)
#pragma unroll
        for (int j = 0; j < 4; j++) acc[i][j] = 0ull;

    for (int k0 = 0; k0 < 2 * DIMC; k0 += 16) {
        const float* Asrc = (k0 < DIMC) ? (h + k0) : (g_hN + (k0 - DIMC));
#pragma unroll
        for (int half = 0; half < 2; half++) {
            int m = a_row + half * 64;
            float4 v = make_float4(0.f, 0.f, 0.f, 0.f);
            if (m0 + m < N_NODESC)
                v = *(const float4*)(Asrc + (size_t)(m0 + m) * DIMC + a_col);
            As[a_col + 0][m] = v.x;
            As[a_col + 1][m] = v.y;
            As[a_col + 2][m] = v.z;
            As[a_col + 3][m] = v.w;
        }
#pragma unroll
        for (int half = 0; half < 2; half++) {
            int kk = b_row + half * 8;
            *(float4*)&Bs[kk][b_col] =
                *(const float4*)(g_WlT + (size_t)(k0 + kk) * DIMC + b_col);
        }
        __syncthreads();

#pragma unroll
        for (int k = 0; k < 16; k++) {
            float4 a0 = *(const float4*)&As[k][tr * 8];
            float4 a1 = *(const float4*)&As[k][tr * 8 + 4];
            unsigned long long ap[8];
            ap[0] = pack2(a0.x); ap[1] = pack2(a0.y); ap[2] = pack2(a0.z); ap[3] = pack2(a0.w);
            ap[4] = pack2(a1.x); ap[5] = pack2(a1.y); ap[6] = pack2(a1.z); ap[7] = pack2(a1.w);
            ulonglong2 bq0 = *(const ulonglong2*)&Bs[k][tc * 8];
            ulonglong2 bq1 = *(const ulonglong2*)&Bs[k][tc * 8 + 4];
            unsigned long long bp[4] = {bq0.x, bq0.y, bq1.x, bq1.y};
#pragma unroll
            for (int i = 0; i < 8; i++)
#pragma unroll
                for (int j = 0; j < 4; j++) ffma2(acc[i][j], ap[i], bp[j]);
        }
        __syncthreads();
    }

#pragma unroll
    for (int i = 0; i < 8; i++) {
        int m = m0 + tr * 8 + i;
        if (m < N_NODESC) {
            float* cp = out + (size_t)m * DIMC + tc * 8;
#pragma unroll
            for (int j = 0; j < 4; j++) {
                float2 p = unpack2(acc[i][j]);
                float2 bl = *(const float2*)&b_lin[tc * 8 + j * 2];
                float v0 = p.x + bl.x;
                float v1 = p.y + bl.y;
                v0 = v0 > 0.f ? v0 : 0.01f * v0;
                v1 = v1 > 0.f ? v1 : 0.01f * v1;
                *(float2*)(cp + j * 2) = make_float2(v0, v1);
            }
        }
    }
}

// ---------------- launch ----------------
extern "C" void kernel_launch(void* const* d_in, const int* in_sizes, int n_in,
                              void* d_out, int out_size) {
    const float* h      = (const float*)d_in[0];
    const float* rel    = (const float*)d_in[1];
    const float* relatt = (const float*)d_in[2];
    const float* W_a    = (const float*)d_in[3];
    const float* b_a    = (const float*)d_in[4];
    const float* W_lin  = (const float*)d_in[5];
    const float* b_lin  = (const float*)d_in[6];
    const int* src   = (const int*)d_in[7];
    const int* dst   = (const int*)d_in[8];
    const int* etype = (const int*)d_in[9];
    float* out = (float*)d_out;

    cudaFuncSetAttribute(k_tgemm2, cudaFuncAttributeMaxDynamicSharedMemorySize, SM_GEMM);
    cudaFuncSetAttribute(k_tgemm3, cudaFuncAttributeMaxDynamicSharedMemorySize, SM_GEMM);

    k_zero<<<(N_NODESC * DIMC + 1023) / 1024, 1024>>>();
    k_cvtA<<<(N_NODESC * DIMC + 255) / 256, 256>>>(h);
    k_prepB<<<(TCNT * DIMC * DIMC + 255) / 256, 256>>>(rel, W_a, W_lin);

    k_tgemm3<<<MBLKS, 256, SM_GEMM>>>();
    dim3 gg(STRIPS2, 16);
    k_tgemm2<<<gg, 256, SM_GEMM>>>();

    dim3 be(32, 8);
    k_score<<<N_EDGESC / 8, be>>>(src, dst, relatt, b_a);
    k_msg<<<N_EDGESC / 8, be>>>(h, src, dst, etype);

    k_final<<<(N_NODESC + 127) / 128, 256>>>(h, b_lin, out);
}

// round 8
// speedup vs baseline: 1.7211x; 1.2254x over previous
#include <cuda_runtime.h>
#include <cuda_bf16.h>
#include <cstdint>

#define N_NODESC 50000
#define N_EDGESC 500000
#define DIMC     128
#define A_DIMC   64
#define NPADC    50048      // 391 * 128
#define MBLKS    391
#define STRIPS2  37
#define TCNT     17

// ---------------- device scratch ----------------
__device__ __align__(16) __nv_bfloat16 g_hh[(size_t)NPADC * DIMC];
__device__ __align__(16) __nv_bfloat16 g_hl[(size_t)NPADC * DIMC];
__device__ __align__(16) __nv_bfloat16 g_Bh[(size_t)TCNT * DIMC * DIMC]; // [t][n][k]
__device__ __align__(16) __nv_bfloat16 g_Bl[(size_t)TCNT * DIMC * DIMC];
__device__ __align__(16) __nv_bfloat16 g_projb[(size_t)16 * N_NODESC * DIMC]; // 204.8MB
__device__ __align__(16) float g_q[(size_t)N_NODESC * DIMC];
__device__ __align__(16) float g_hN[(size_t)N_NODESC * DIMC];
__device__ float g_denom[N_NODESC];
__device__ __align__(16) float g_WlT[2 * DIMC * DIMC];

// ---------------- ptx helpers ----------------
__device__ __forceinline__ uint32_t smem_u32(const void* p) {
    uint32_t a;
    asm("{ .reg .u64 t; cvta.to.shared.u64 t, %1; cvt.u32.u64 %0, t; }" : "=r"(a) : "l"(p));
    return a;
}
__device__ __forceinline__ void cp16(uint32_t dst, const void* src) {
    asm volatile("cp.async.cg.shared.global [%0], [%1], 16;" :: "r"(dst), "l"(src));
}
#define CP_COMMIT() asm volatile("cp.async.commit_group;" ::: "memory")
#define CP_WAIT(n)  asm volatile("cp.async.wait_group %0;" :: "n"(n) : "memory")

__device__ __forceinline__ void ldmx4(uint32_t* r, uint32_t addr) {
    asm volatile("ldmatrix.sync.aligned.m8n8.x4.shared.b16 {%0,%1,%2,%3}, [%4];"
                 : "=r"(r[0]), "=r"(r[1]), "=r"(r[2]), "=r"(r[3]) : "r"(addr));
}
__device__ __forceinline__ void mma16816(float* d, const uint32_t* a, uint32_t b0, uint32_t b1) {
    asm volatile("mma.sync.aligned.m16n8k16.row.col.f32.bf16.bf16.f32 "
                 "{%0,%1,%2,%3}, {%4,%5,%6,%7}, {%8,%9}, {%0,%1,%2,%3};"
                 : "+f"(d[0]), "+f"(d[1]), "+f"(d[2]), "+f"(d[3])
                 : "r"(a[0]), "r"(a[1]), "r"(a[2]), "r"(a[3]), "r"(b0), "r"(b1));
}

// ---------------- prep kernels ----------------
__global__ void k_zero() {
    size_t i = (size_t)blockIdx.x * blockDim.x + threadIdx.x;
    if (i < (size_t)N_NODESC * DIMC) g_hN[i] = 0.0f;
    if (i < N_NODESC) g_denom[i] = 0.0f;
}

__global__ void k_cvtA(const float* __restrict__ h) {
    int i = blockIdx.x * 256 + threadIdx.x;
    if (i < N_NODESC * DIMC) {
        float v = h[i];
        __nv_bfloat16 hi = __float2bfloat16(v);
        g_hh[i] = hi;
        g_hl[i] = __float2bfloat16(v - __bfloat162float(hi));
    }
}

__global__ void k_prepB(const float* __restrict__ rel, const float* __restrict__ W_a,
                        const float* __restrict__ W_lin) {
    int i = blockIdx.x * 256 + threadIdx.x;
    if (i < TCNT * DIMC * DIMC) {
        int t = i >> 14, n = (i >> 7) & 127, k = i & 127;
        float v;
        if (t < 16) {
            int side = t >> 3, r = t & 7;
            v = rel[((size_t)(r * 256 + side * 128 + k)) * 128 + n];
        } else {
            v = (n < A_DIMC) ? W_a[n * 256 + k] : W_a[(n - A_DIMC) * 256 + DIMC + k];
        }
        __nv_bfloat16 hi = __float2bfloat16(v);
        g_Bh[i] = hi;
        g_Bl[i] = __float2bfloat16(v - __bfloat162float(hi));
    }
    if (i < 2 * DIMC * DIMC) {
        int k = i >> 7, o = i & 127;
        g_WlT[i] = W_lin[o * 256 + k];
    }
}

#define ROWB 272
#define TILEB 34816                 // 128 * 272
#define SM_GEMM2 (3 * TILEB)        // Bh + 2 A buffers = 102 KB -> 2 CTAs/SM
#define SM_GEMM3 (4 * TILEB)

// ---------------- gate GEMMs (t<16), plain bf16, persistent strips ----------------
__global__ void __launch_bounds__(256, 2) k_tgemm2() {
    extern __shared__ char smem[];
    const uint32_t sb  = smem_u32(smem);
    const uint32_t sBh  = sb;
    const uint32_t sAh0 = sb + TILEB;
    const uint32_t sAh1 = sb + 2 * TILEB;

    const int tid = threadIdx.x;
    const int lane = tid & 31;
    const int wid = tid >> 5;
    const int t = blockIdx.y;
    const int strip = blockIdx.x;
    const int n_m = (MBLKS - strip + STRIPS2 - 1) / STRIPS2;

    {
        const __nv_bfloat16* Bh = g_Bh + (size_t)t * DIMC * DIMC;
        const size_t mbase = (size_t)strip * 128 * DIMC;
        for (int idx = tid; idx < 2048; idx += 256) {
            int row = idx >> 4, c = idx & 15;
            uint32_t doff = row * ROWB + c * 16;
            size_t soff = (size_t)row * DIMC + c * 8;
            cp16(sBh + doff, Bh + soff);
            cp16(sAh0 + doff, g_hh + mbase + soff);
        }
    }
    CP_COMMIT();

    const int mb = (wid & 3) * 32;
    const int nb = (wid >> 2) * 64;
    const int a_row = (lane & 7) + 8 * ((lane >> 3) & 1);
    const int a_kh  = (lane >> 4) * 16;
    const int b_row = (lane & 7) + 8 * (lane >> 4);
    const int b_kh  = ((lane >> 3) & 1) * 16;
    const int rb_local = mb + (lane >> 2);
    const int cbase = nb + 2 * (lane & 3);

    for (int it = 0; it < n_m; it++) {
        const uint32_t sAh = (it & 1) ? sAh1 : sAh0;

        if (it + 1 < n_m) {
            const uint32_t dAh = (it & 1) ? sAh0 : sAh1;
            const size_t mbase = (size_t)(strip + (it + 1) * STRIPS2) * 128 * DIMC;
            for (int idx = tid; idx < 2048; idx += 256) {
                int row = idx >> 4, c = idx & 15;
                cp16(dAh + row * ROWB + c * 16, g_hh + mbase + (size_t)row * DIMC + c * 8);
            }
            CP_COMMIT();
            CP_WAIT(1);
        } else {
            CP_WAIT(0);
        }
        __syncthreads();

        float acc[2][8][4];
#pragma unroll
        for (int i = 0; i < 2; i++)
#pragma unroll
            for (int j = 0; j < 8; j++)
#pragma unroll
                for (int v = 0; v < 4; v++) acc[i][j][v] = 0.0f;

#pragma unroll
        for (int k0 = 0; k0 < 8; k0++) {
            const uint32_t kbyte = k0 * 32;
            uint32_t ah[2][4], bh[4][4];
#pragma unroll
            for (int mt = 0; mt < 2; mt++)
                ldmx4(ah[mt], sAh + (mb + mt * 16 + a_row) * ROWB + kbyte + a_kh);
#pragma unroll
            for (int q = 0; q < 4; q++)
                ldmx4(bh[q], sBh + (nb + q * 16 + b_row) * ROWB + kbyte + b_kh);
#pragma unroll
            for (int mt = 0; mt < 2; mt++) {
#pragma unroll
                for (int nf = 0; nf < 8; nf++) {
                    mma16816(acc[mt][nf], ah[mt],
                             bh[nf >> 1][(nf & 1) * 2], bh[nf >> 1][(nf & 1) * 2 + 1]);
                }
            }
        }

        const int m0 = (strip + it * STRIPS2) * 128;
#pragma unroll
        for (int mt = 0; mt < 2; mt++) {
#pragma unroll
            for (int pair = 0; pair < 2; pair++) {
                int m = m0 + rb_local + mt * 16 + pair * 8;
                if (m >= N_NODESC) continue;
                __nv_bfloat16* dp = g_projb + ((size_t)t * N_NODESC + m) * DIMC;
#pragma unroll
                for (int nf = 0; nf < 8; nf++) {
                    float v0 = acc[mt][nf][pair * 2 + 0];
                    float v1 = acc[mt][nf][pair * 2 + 1];
                    uint32_t pk;
                    asm("cvt.rn.satfinite.bf16x2.f32 %0, %1, %2;" : "=r"(pk) : "f"(v1), "f"(v0));
                    *(uint32_t*)(dp + cbase + nf * 8) = pk;
                }
            }
        }
        __syncthreads();
    }
}

// ---------------- attention GEMM (t=16), 3-term, non-persistent ----------------
__global__ void __launch_bounds__(256, 1) k_tgemm3() {
    extern __shared__ char smem[];
    const uint32_t sb = smem_u32(smem);
    const uint32_t sAh = sb, sAl = sb + TILEB, sBh = sb + 2 * TILEB, sBl = sb + 3 * TILEB;

    const int tid = threadIdx.x;
    const int lane = tid & 31;
    const int wid = tid >> 5;
    const int m0 = blockIdx.x * 128;

    {
        const __nv_bfloat16* Bh = g_Bh + (size_t)16 * DIMC * DIMC;
        const __nv_bfloat16* Bl = g_Bl + (size_t)16 * DIMC * DIMC;
        const size_t mbase = (size_t)m0 * DIMC;
        for (int idx = tid; idx < 2048; idx += 256) {
            int row = idx >> 4, c = idx & 15;
            uint32_t doff = row * ROWB + c * 16;
            size_t soff = (size_t)row * DIMC + c * 8;
            cp16(sAh + doff, g_hh + mbase + soff);
            cp16(sAl + doff, g_hl + mbase + soff);
            cp16(sBh + doff, Bh + soff);
            cp16(sBl + doff, Bl + soff);
        }
    }
    CP_COMMIT();
    CP_WAIT(0);
    __syncthreads();

    const int mb = (wid & 3) * 32;
    const int nb = (wid >> 2) * 64;
    const int a_row = (lane & 7) + 8 * ((lane >> 3) & 1);
    const int a_kh  = (lane >> 4) * 16;
    const int b_row = (lane & 7) + 8 * (lane >> 4);
    const int b_kh  = ((lane >> 3) & 1) * 16;

    float acc[2][8][4];
#pragma unroll
    for (int i = 0; i < 2; i++)
#pragma unroll
        for (int j = 0; j < 8; j++)
#pragma unroll
            for (int v = 0; v < 4; v++) acc[i][j][v] = 0.0f;

#pragma unroll
    for (int k0 = 0; k0 < 8; k0++) {
        const uint32_t kbyte = k0 * 32;
        uint32_t ah[2][4], al[2][4], bh[4][4], bl[4][4];
#pragma unroll
        for (int mt = 0; mt < 2; mt++) {
            uint32_t ar = (mb + mt * 16 + a_row) * ROWB + kbyte + a_kh;
            ldmx4(ah[mt], sAh + ar);
            ldmx4(al[mt], sAl + ar);
        }
#pragma unroll
        for (int q = 0; q < 4; q++) {
            uint32_t br = (nb + q * 16 + b_row) * ROWB + kbyte + b_kh;
            ldmx4(bh[q], sBh + br);
            ldmx4(bl[q], sBl + br);
        }
#pragma unroll
        for (int mt = 0; mt < 2; mt++) {
#pragma unroll
            for (int nf = 0; nf < 8; nf++) {
                uint32_t h0 = bh[nf >> 1][(nf & 1) * 2], h1 = bh[nf >> 1][(nf & 1) * 2 + 1];
                uint32_t l0 = bl[nf >> 1][(nf & 1) * 2], l1 = bl[nf >> 1][(nf & 1) * 2 + 1];
                mma16816(acc[mt][nf], ah[mt], h0, h1);
                mma16816(acc[mt][nf], ah[mt], l0, l1);
                mma16816(acc[mt][nf], al[mt], h0, h1);
            }
        }
    }

    const int rbase = m0 + mb + (lane >> 2);
    const int cbase = nb + 2 * (lane & 3);
#pragma unroll
    for (int mt = 0; mt < 2; mt++) {
#pragma unroll
        for (int pair = 0; pair < 2; pair++) {
            int m = rbase + mt * 16 + pair * 8;
            if (m >= N_NODESC) continue;
            float* dp = g_q + (size_t)m * DIMC;
#pragma unroll
            for (int nf = 0; nf < 8; nf++)
                *(float2*)(dp + cbase + nf * 8) =
                    make_float2(acc[mt][nf][pair * 2], acc[mt][nf][pair * 2 + 1]);
        }
    }
}

// ---------------- fused edge kernel: score + unnormalized message ----------------
// h_N_unnorm[d] += ex * gate * h[src];  denom[d] += ex.  (divide in k_final)
__global__ void k_edge(const float* __restrict__ h, const int* __restrict__ src,
                       const int* __restrict__ dst, const int* __restrict__ etype,
                       const float* __restrict__ rel_att, const float* __restrict__ b_a) {
    int e = blockIdx.x * 8 + threadIdx.y;
    int lane = threadIdx.x;
    int s = __ldg(&src[e]);
    int d = __ldg(&dst[e]);
    int r = __ldg(&etype[e]);

    // ---- attention score (A_DIM=64, 2 per lane) ----
    float2 qd = *(const float2*)&g_q[(size_t)d * DIMC + lane * 2];
    float2 qs = *(const float2*)&g_q[(size_t)s * DIMC + A_DIMC + lane * 2];
    float2 ba = *(const float2*)&b_a[lane * 2];
    float2 ra = *(const float2*)&rel_att[lane * 2];
    float x0 = qd.x + qs.x + ba.x;
    x0 = x0 > 0.f ? x0 : 0.01f * x0;
    float x1 = qd.y + qs.y + ba.y;
    x1 = x1 > 0.f ? x1 : 0.01f * x1;
    float p = ra.x * x0 + ra.y * x1;
#pragma unroll
    for (int o = 16; o > 0; o >>= 1) p += __shfl_xor_sync(0xffffffffu, p, o);
    float ex = expf(p);
    if (lane == 0) atomicAdd(&g_denom[d], ex);

    // ---- gate + message (4 dims per lane) ----
    uint2 pdw = *(const uint2*)(g_projb + ((size_t)r * N_NODESC + d) * DIMC + lane * 4);
    uint2 psw = *(const uint2*)(g_projb + ((size_t)(8 + r) * N_NODESC + s) * DIMC + lane * 4);
    float2 pd0 = __bfloat1622float2(*(__nv_bfloat162*)&pdw.x);
    float2 pd1 = __bfloat1622float2(*(__nv_bfloat162*)&pdw.y);
    float2 ps0 = __bfloat1622float2(*(__nv_bfloat162*)&psw.x);
    float2 ps1 = __bfloat1622float2(*(__nv_bfloat162*)&psw.y);
    float4 hs = *(const float4*)&h[(size_t)s * DIMC + lane * 4];
    float g0 = 1.0f / (1.0f + expf(-(pd0.x + ps0.x)));
    float g1 = 1.0f / (1.0f + expf(-(pd0.y + ps0.y)));
    float g2 = 1.0f / (1.0f + expf(-(pd1.x + ps1.x)));
    float g3 = 1.0f / (1.0f + expf(-(pd1.y + ps1.y)));
    float* o = &g_hN[(size_t)d * DIMC + lane * 4];
    atomicAdd(o + 0, hs.x * ex * g0);
    atomicAdd(o + 1, hs.y * ex * g1);
    atomicAdd(o + 2, hs.z * ex * g2);
    atomicAdd(o + 3, hs.w * ex * g3);
}

// ---------------- f32x2 packed-FMA helpers ----------------
__device__ __forceinline__ unsigned long long pack2(float x) {
    unsigned long long r;
    asm("mov.b64 %0, {%1, %1};" : "=l"(r) : "f"(x));
    return r;
}
__device__ __forceinline__ void ffma2(unsigned long long& acc, unsigned long long a,
                                      unsigned long long b) {
    asm("fma.rn.f32x2 %0, %1, %2, %0;" : "+l"(acc) : "l"(a), "l"(b));
}
__device__ __forceinline__ float2 unpack2(unsigned long long v) {
    float2 r;
    asm("mov.b64 {%0, %1}, %2;" : "=f"(r.x), "=f"(r.y) : "l"(v));
    return r;
}

// ---------------- final: out = leaky([h ; h_N/denom] @ W_lin^T + b_lin) ----------------
__global__ __launch_bounds__(256) void k_final(const float* __restrict__ h,
                                               const float* __restrict__ b_lin,
                                               float* __restrict__ out) {
    __shared__ float As[16][132];
    __shared__ float Bs[16][128];

    const int tid = threadIdx.x;
    const int m0 = blockIdx.x * 128;
    const int tr = tid >> 4;
    const int tc = tid & 15;
    const int a_row = tid >> 2;
    const int a_col = (tid & 3) << 2;
    const int b_row = tid >> 5;
    const int b_col = (tid & 31) << 2;

    unsigned long long acc[8][4];
#pragma unroll
    for (int i = 0; i < 8; i++)
#pragma unroll
        for (int j = 0; j < 4; j++) acc[i][j] = 0ull;

    for (int k0 = 0; k0 < 2 * DIMC; k0 += 16) {
        const bool isHN = (k0 >= DIMC);
        const float* Asrc = isHN ? (g_hN + (k0 - DIMC)) : (h + k0);
#pragma unroll
        for (int half = 0; half < 2; half++) {
            int m = a_row + half * 64;
            float4 v = make_float4(0.f, 0.f, 0.f, 0.f);
            if (m0 + m < N_NODESC) {
                v = *(const float4*)(Asrc + (size_t)(m0 + m) * DIMC + a_col);
                if (isHN) {
                    float den = __ldg(&g_denom[m0 + m]);
                    float inv = (den > 0.0f) ? __frcp_rn(den) : 0.0f;  // no-edge nodes: h_N = 0
                    v.x *= inv; v.y *= inv; v.z *= inv; v.w *= inv;
                }
            }
            As[a_col + 0][m] = v.x;
            As[a_col + 1][m] = v.y;
            As[a_col + 2][m] = v.z;
            As[a_col + 3][m] = v.w;
        }
#pragma unroll
        for (int half = 0; half < 2; half++) {
            int kk = b_row + half * 8;
            *(float4*)&Bs[kk][b_col] =
                *(const float4*)(g_WlT + (size_t)(k0 + kk) * DIMC + b_col);
        }
        __syncthreads();

#pragma unroll
        for (int k = 0; k < 16; k++) {
            float4 a0 = *(const float4*)&As[k][tr * 8];
            float4 a1 = *(const float4*)&As[k][tr * 8 + 4];
            unsigned long long ap[8];
            ap[0] = pack2(a0.x); ap[1] = pack2(a0.y); ap[2] = pack2(a0.z); ap[3] = pack2(a0.w);
            ap[4] = pack2(a1.x); ap[5] = pack2(a1.y); ap[6] = pack2(a1.z); ap[7] = pack2(a1.w);
            ulonglong2 bq0 = *(const ulonglong2*)&Bs[k][tc * 8];
            ulonglong2 bq1 = *(const ulonglong2*)&Bs[k][tc * 8 + 4];
            unsigned long long bp[4] = {bq0.x, bq0.y, bq1.x, bq1.y};
#pragma unroll
            for (int i = 0; i < 8; i++)
#pragma unroll
                for (int j = 0; j < 4; j++) ffma2(acc[i][j], ap[i], bp[j]);
        }
        __syncthreads();
    }

#pragma unroll
    for (int i = 0; i < 8; i++) {
        int m = m0 + tr * 8 + i;
        if (m < N_NODESC) {
            float* cp = out + (size_t)m * DIMC + tc * 8;
#pragma unroll
            for (int j = 0; j < 4; j++) {
                float2 p = unpack2(acc[i][j]);
                float2 bl = *(const float2*)&b_lin[tc * 8 + j * 2];
                float v0 = p.x + bl.x;
                float v1 = p.y + bl.y;
                v0 = v0 > 0.f ? v0 : 0.01f * v0;
                v1 = v1 > 0.f ? v1 : 0.01f * v1;
                *(float2*)(cp + j * 2) = make_float2(v0, v1);
            }
        }
    }
}

// ---------------- launch ----------------
extern "C" void kernel_launch(void* const* d_in, const int* in_sizes, int n_in,
                              void* d_out, int out_size) {
    const float* h      = (const float*)d_in[0];
    const float* rel    = (const float*)d_in[1];
    const float* relatt = (const float*)d_in[2];
    const float* W_a    = (const float*)d_in[3];
    const float* b_a    = (const float*)d_in[4];
    const float* W_lin  = (const float*)d_in[5];
    const float* b_lin  = (const float*)d_in[6];
    const int* src   = (const int*)d_in[7];
    const int* dst   = (const int*)d_in[8];
    const int* etype = (const int*)d_in[9];
    float* out = (float*)d_out;

    cudaFuncSetAttribute(k_tgemm2, cudaFuncAttributeMaxDynamicSharedMemorySize, SM_GEMM2);
    cudaFuncSetAttribute(k_tgemm3, cudaFuncAttributeMaxDynamicSharedMemorySize, SM_GEMM3);

    k_zero<<<(N_NODESC * DIMC + 1023) / 1024, 1024>>>();
    k_cvtA<<<(N_NODESC * DIMC + 255) / 256, 256>>>(h);
    k_prepB<<<(TCNT * DIMC * DIMC + 255) / 256, 256>>>(rel, W_a, W_lin);

    k_tgemm3<<<MBLKS, 256, SM_GEMM3>>>();
    dim3 gg(STRIPS2, 16);
    k_tgemm2<<<gg, 256, SM_GEMM2>>>();

    dim3 be(32, 8);
    k_edge<<<N_EDGESC / 8, be>>>(h, src, dst, etype, relatt, b_a);

    k_final<<<(N_NODESC + 127) / 128, 256>>>(h, b_lin, out);
}

// round 9
// speedup vs baseline: 1.8231x; 1.0592x over previous
#include <cuda_runtime.h>
#include <cuda_bf16.h>
#include <cstdint>

#define N_NODESC 50000
#define N_EDGESC 500000
#define DIMC     128
#define A_DIMC   64
#define NPADC    50048      // 391 * 128
#define MBLKS    391
#define STRIPS2  37
#define TCNT     17
#define SCANBLKS 98         // 98 * 512 >= 50000

// ---------------- device scratch ----------------
__device__ __align__(16) __nv_bfloat16 g_hh[(size_t)NPADC * DIMC];
__device__ __align__(16) __nv_bfloat16 g_hl[(size_t)NPADC * DIMC];
__device__ __align__(16) __nv_bfloat16 g_Bh[(size_t)TCNT * DIMC * DIMC]; // [t][n][k]
__device__ __align__(16) __nv_bfloat16 g_Bl[(size_t)TCNT * DIMC * DIMC];
__device__ __align__(16) __nv_bfloat16 g_projb[(size_t)16 * N_NODESC * DIMC]; // 204.8MB
__device__ __align__(16) float g_q[(size_t)N_NODESC * DIMC];
__device__ __align__(16) float g_hN[(size_t)N_NODESC * DIMC];
__device__ __align__(16) float g_WlT[2 * DIMC * DIMC];
// CSR scratch
__device__ int g_cnt[N_NODESC];
__device__ int g_rowpre[N_NODESC];
__device__ int g_rowptr[N_NODESC + 1];
__device__ int g_bsum[SCANBLKS];
__device__ int g_epack[N_EDGESC];   // (etype<<16) | src

// ---------------- ptx helpers ----------------
__device__ __forceinline__ uint32_t smem_u32(const void* p) {
    uint32_t a;
    asm("{ .reg .u64 t; cvta.to.shared.u64 t, %1; cvt.u32.u64 %0, t; }" : "=r"(a) : "l"(p));
    return a;
}
__device__ __forceinline__ void cp16(uint32_t dst, const void* src) {
    asm volatile("cp.async.cg.shared.global [%0], [%1], 16;" :: "r"(dst), "l"(src));
}
#define CP_COMMIT() asm volatile("cp.async.commit_group;" ::: "memory")
#define CP_WAIT(n)  asm volatile("cp.async.wait_group %0;" :: "n"(n) : "memory")

__device__ __forceinline__ void ldmx4(uint32_t* r, uint32_t addr) {
    asm volatile("ldmatrix.sync.aligned.m8n8.x4.shared.b16 {%0,%1,%2,%3}, [%4];"
                 : "=r"(r[0]), "=r"(r[1]), "=r"(r[2]), "=r"(r[3]) : "r"(addr));
}
__device__ __forceinline__ void mma16816(float* d, const uint32_t* a, uint32_t b0, uint32_t b1) {
    asm volatile("mma.sync.aligned.m16n8k16.row.col.f32.bf16.bf16.f32 "
                 "{%0,%1,%2,%3}, {%4,%5,%6,%7}, {%8,%9}, {%0,%1,%2,%3};"
                 : "+f"(d[0]), "+f"(d[1]), "+f"(d[2]), "+f"(d[3])
                 : "r"(a[0]), "r"(a[1]), "r"(a[2]), "r"(a[3]), "r"(b0), "r"(b1));
}

// ---------------- prep kernels ----------------
__global__ void k_cvtA(const float* __restrict__ h) {
    int i = blockIdx.x * 256 + threadIdx.x;
    if (i < N_NODESC * DIMC) {
        float v = h[i];
        __nv_bfloat16 hi = __float2bfloat16(v);
        g_hh[i] = hi;
        g_hl[i] = __float2bfloat16(v - __bfloat162float(hi));
    }
}

__global__ void k_prepB(const float* __restrict__ rel, const float* __restrict__ W_a,
                        const float* __restrict__ W_lin) {
    int i = blockIdx.x * 256 + threadIdx.x;
    if (i < TCNT * DIMC * DIMC) {
        int t = i >> 14, n = (i >> 7) & 127, k = i & 127;
        float v;
        if (t < 16) {
            int side = t >> 3, r = t & 7;
            v = rel[((size_t)(r * 256 + side * 128 + k)) * 128 + n];
        } else {
            v = (n < A_DIMC) ? W_a[n * 256 + k] : W_a[(n - A_DIMC) * 256 + DIMC + k];
        }
        __nv_bfloat16 hi = __float2bfloat16(v);
        g_Bh[i] = hi;
        g_Bl[i] = __float2bfloat16(v - __bfloat162float(hi));
    }
    if (i < 2 * DIMC * DIMC) {
        int k = i >> 7, o = i & 127;
        g_WlT[i] = W_lin[o * 256 + k];
    }
}

// ---------------- CSR build ----------------
__global__ void k_csr0() {
    int i = blockIdx.x * 1024 + threadIdx.x;
    if (i < N_NODESC) g_cnt[i] = 0;
}
__global__ void k_hist(const int* __restrict__ dst) {
    int i = blockIdx.x * 1024 + threadIdx.x;
    if (i < N_EDGESC) atomicAdd(&g_cnt[dst[i]], 1);
}
__global__ void k_scan1() {
    __shared__ int sh[512];
    int i = blockIdx.x * 512 + threadIdx.x;
    int v = (i < N_NODESC) ? g_cnt[i] : 0;
    sh[threadIdx.x] = v;
    __syncthreads();
    for (int off = 1; off < 512; off <<= 1) {
        int t = (threadIdx.x >= off) ? sh[threadIdx.x - off] : 0;
        __syncthreads();
        sh[threadIdx.x] += t;
        __syncthreads();
    }
    if (i < N_NODESC) g_rowpre[i] = sh[threadIdx.x] - v;   // exclusive within block
    if (threadIdx.x == 511) g_bsum[blockIdx.x] = sh[511];
}
__global__ void k_scan2() {
    if (threadIdx.x == 0) {
        int acc = 0;
        for (int b = 0; b < SCANBLKS; b++) { int v = g_bsum[b]; g_bsum[b] = acc; acc += v; }
        g_rowptr[N_NODESC] = N_EDGESC;
    }
}
__global__ void k_scan3() {
    int i = blockIdx.x * 512 + threadIdx.x;
    if (i < N_NODESC) {
        g_rowptr[i] = g_rowpre[i] + g_bsum[i >> 9];
        g_cnt[i] = 0;   // reuse as scatter cursor
    }
}
__global__ void k_scatter(const int* __restrict__ src, const int* __restrict__ dst,
                          const int* __restrict__ etype) {
    int i = blockIdx.x * 1024 + threadIdx.x;
    if (i < N_EDGESC) {
        int d = dst[i];
        int pos = g_rowptr[d] + atomicAdd(&g_cnt[d], 1);
        g_epack[pos] = (etype[i] << 16) | src[i];
    }
}

#define ROWB 272
#define TILEB 34816                 // 128 * 272
#define SM_GEMM2 (3 * TILEB)        // Bh + 2 A buffers = 102 KB -> 2 CTAs/SM
#define SM_GEMM3 (4 * TILEB)

// ---------------- gate GEMMs (t<16), plain bf16, persistent strips ----------------
__global__ void __launch_bounds__(256, 2) k_tgemm2() {
    extern __shared__ char smem[];
    const uint32_t sb  = smem_u32(smem);
    const uint32_t sBh  = sb;
    const uint32_t sAh0 = sb + TILEB;
    const uint32_t sAh1 = sb + 2 * TILEB;

    const int tid = threadIdx.x;
    const int lane = tid & 31;
    const int wid = tid >> 5;
    const int t = blockIdx.y;
    const int strip = blockIdx.x;
    const int n_m = (MBLKS - strip + STRIPS2 - 1) / STRIPS2;

    {
        const __nv_bfloat16* Bh = g_Bh + (size_t)t * DIMC * DIMC;
        const size_t mbase = (size_t)strip * 128 * DIMC;
        for (int idx = tid; idx < 2048; idx += 256) {
            int row = idx >> 4, c = idx & 15;
            uint32_t doff = row * ROWB + c * 16;
            size_t soff = (size_t)row * DIMC + c * 8;
            cp16(sBh + doff, Bh + soff);
            cp16(sAh0 + doff, g_hh + mbase + soff);
        }
    }
    CP_COMMIT();

    const int mb = (wid & 3) * 32;
    const int nb = (wid >> 2) * 64;
    const int a_row = (lane & 7) + 8 * ((lane >> 3) & 1);
    const int a_kh  = (lane >> 4) * 16;
    const int b_row = (lane & 7) + 8 * (lane >> 4);
    const int b_kh  = ((lane >> 3) & 1) * 16;
    const int rb_local = mb + (lane >> 2);
    const int cbase = nb + 2 * (lane & 3);

    for (int it = 0; it < n_m; it++) {
        const uint32_t sAh = (it & 1) ? sAh1 : sAh0;

        if (it + 1 < n_m) {
            const uint32_t dAh = (it & 1) ? sAh0 : sAh1;
            const size_t mbase = (size_t)(strip + (it + 1) * STRIPS2) * 128 * DIMC;
            for (int idx = tid; idx < 2048; idx += 256) {
                int row = idx >> 4, c = idx & 15;
                cp16(dAh + row * ROWB + c * 16, g_hh + mbase + (size_t)row * DIMC + c * 8);
            }
            CP_COMMIT();
            CP_WAIT(1);
        } else {
            CP_WAIT(0);
        }
        __syncthreads();

        float acc[2][8][4];
#pragma unroll
        for (int i = 0; i < 2; i++)
#pragma unroll
            for (int j = 0; j < 8; j++)
#pragma unroll
                for (int v = 0; v < 4; v++) acc[i][j][v] = 0.0f;

#pragma unroll
        for (int k0 = 0; k0 < 8; k0++) {
            const uint32_t kbyte = k0 * 32;
            uint32_t ah[2][4], bh[4][4];
#pragma unroll
            for (int mt = 0; mt < 2; mt++)
                ldmx4(ah[mt], sAh + (mb + mt * 16 + a_row) * ROWB + kbyte + a_kh);
#pragma unroll
            for (int q = 0; q < 4; q++)
                ldmx4(bh[q], sBh + (nb + q * 16 + b_row) * ROWB + kbyte + b_kh);
#pragma unroll
            for (int mt = 0; mt < 2; mt++) {
#pragma unroll
                for (int nf = 0; nf < 8; nf++) {
                    mma16816(acc[mt][nf], ah[mt],
                             bh[nf >> 1][(nf & 1) * 2], bh[nf >> 1][(nf & 1) * 2 + 1]);
                }
            }
        }

        const int m0 = (strip + it * STRIPS2) * 128;
#pragma unroll
        for (int mt = 0; mt < 2; mt++) {
#pragma unroll
            for (int pair = 0; pair < 2; pair++) {
                int m = m0 + rb_local + mt * 16 + pair * 8;
                if (m >= N_NODESC) continue;
                __nv_bfloat16* dp = g_projb + ((size_t)t * N_NODESC + m) * DIMC;
#pragma unroll
                for (int nf = 0; nf < 8; nf++) {
                    float v0 = acc[mt][nf][pair * 2 + 0];
                    float v1 = acc[mt][nf][pair * 2 + 1];
                    uint32_t pk;
                    asm("cvt.rn.satfinite.bf16x2.f32 %0, %1, %2;" : "=r"(pk) : "f"(v1), "f"(v0));
                    *(uint32_t*)(dp + cbase + nf * 8) = pk;
                }
            }
        }
        __syncthreads();
    }
}

// ---------------- attention GEMM (t=16), 3-term, non-persistent ----------------
__global__ void __launch_bounds__(256, 1) k_tgemm3() {
    extern __shared__ char smem[];
    const uint32_t sb = smem_u32(smem);
    const uint32_t sAh = sb, sAl = sb + TILEB, sBh = sb + 2 * TILEB, sBl = sb + 3 * TILEB;

    const int tid = threadIdx.x;
    const int lane = tid & 31;
    const int wid = tid >> 5;
    const int m0 = blockIdx.x * 128;

    {
        const __nv_bfloat16* Bh = g_Bh + (size_t)16 * DIMC * DIMC;
        const __nv_bfloat16* Bl = g_Bl + (size_t)16 * DIMC * DIMC;
        const size_t mbase = (size_t)m0 * DIMC;
        for (int idx = tid; idx < 2048; idx += 256) {
            int row = idx >> 4, c = idx & 15;
            uint32_t doff = row * ROWB + c * 16;
            size_t soff = (size_t)row * DIMC + c * 8;
            cp16(sAh + doff, g_hh + mbase + soff);
            cp16(sAl + doff, g_hl + mbase + soff);
            cp16(sBh + doff, Bh + soff);
            cp16(sBl + doff, Bl + soff);
        }
    }
    CP_COMMIT();
    CP_WAIT(0);
    __syncthreads();

    const int mb = (wid & 3) * 32;
    const int nb = (wid >> 2) * 64;
    const int a_row = (lane & 7) + 8 * ((lane >> 3) & 1);
    const int a_kh  = (lane >> 4) * 16;
    const int b_row = (lane & 7) + 8 * (lane >> 4);
    const int b_kh  = ((lane >> 3) & 1) * 16;

    float acc[2][8][4];
#pragma unroll
    for (int i = 0; i < 2; i++)
#pragma unroll
        for (int j = 0; j < 8; j++)
#pragma unroll
            for (int v = 0; v < 4; v++) acc[i][j][v] = 0.0f;

#pragma unroll
    for (int k0 = 0; k0 < 8; k0++) {
        const uint32_t kbyte = k0 * 32;
        uint32_t ah[2][4], al[2][4], bh[4][4], bl[4][4];
#pragma unroll
        for (int mt = 0; mt < 2; mt++) {
            uint32_t ar = (mb + mt * 16 + a_row) * ROWB + kbyte + a_kh;
            ldmx4(ah[mt], sAh + ar);
            ldmx4(al[mt], sAl + ar);
        }
#pragma unroll
        for (int q = 0; q < 4; q++) {
            uint32_t br = (nb + q * 16 + b_row) * ROWB + kbyte + b_kh;
            ldmx4(bh[q], sBh + br);
            ldmx4(bl[q], sBl + br);
        }
#pragma unroll
        for (int mt = 0; mt < 2; mt++) {
#pragma unroll
            for (int nf = 0; nf < 8; nf++) {
                uint32_t h0 = bh[nf >> 1][(nf & 1) * 2], h1 = bh[nf >> 1][(nf & 1) * 2 + 1];
                uint32_t l0 = bl[nf >> 1][(nf & 1) * 2], l1 = bl[nf >> 1][(nf & 1) * 2 + 1];
                mma16816(acc[mt][nf], ah[mt], h0, h1);
                mma16816(acc[mt][nf], ah[mt], l0, l1);
                mma16816(acc[mt][nf], al[mt], h0, h1);
            }
        }
    }

    const int rbase = m0 + mb + (lane >> 2);
    const int cbase = nb + 2 * (lane & 3);
#pragma unroll
    for (int mt = 0; mt < 2; mt++) {
#pragma unroll
        for (int pair = 0; pair < 2; pair++) {
            int m = rbase + mt * 16 + pair * 8;
            if (m >= N_NODESC) continue;
            float* dp = g_q + (size_t)m * DIMC;
#pragma unroll
            for (int nf = 0; nf < 8; nf++)
                *(float2*)(dp + cbase + nf * 8) =
                    make_float2(acc[mt][nf][pair * 2], acc[mt][nf][pair * 2 + 1]);
        }
    }
}

// ---------------- warp-per-node message kernel (no atomics) ----------------
__global__ void __launch_bounds__(256) k_msg2(const float* __restrict__ h,
                                              const float* __restrict__ rel_att,
                                              const float* __restrict__ b_a) {
    const int lane = threadIdx.x & 31;
    const int n = blockIdx.x * 8 + (threadIdx.x >> 5);
    if (n >= N_NODESC) return;
    const int beg = g_rowptr[n];
    const int end = g_rowptr[n + 1];

    float2 qd = *(const float2*)&g_q[(size_t)n * DIMC + lane * 2];
    float2 ba = *(const float2*)&b_a[lane * 2];
    float2 ra = *(const float2*)&rel_att[lane * 2];
    const __nv_bfloat16* pdbase = g_projb + (size_t)n * DIMC + lane * 4;

    float a0 = 0.f, a1 = 0.f, a2 = 0.f, a3 = 0.f, den = 0.f;

    for (int e = beg; e < end; e++) {
        int pack = __ldg(&g_epack[e]);
        int s = pack & 0xFFFF;
        int r = pack >> 16;

        // score
        float2 qs = *(const float2*)&g_q[(size_t)s * DIMC + A_DIMC + lane * 2];
        float x0 = qd.x + qs.x + ba.x;
        x0 = x0 > 0.f ? x0 : 0.01f * x0;
        float x1 = qd.y + qs.y + ba.y;
        x1 = x1 > 0.f ? x1 : 0.01f * x1;
        float p = ra.x * x0 + ra.y * x1;
#pragma unroll
        for (int o = 16; o > 0; o >>= 1) p += __shfl_xor_sync(0xffffffffu, p, o);
        float ex = expf(p);

        // gate + message
        uint2 pdw = *(const uint2*)(pdbase + (size_t)r * N_NODESC * DIMC);
        uint2 psw = *(const uint2*)(g_projb + ((size_t)(8 + r) * N_NODESC + s) * DIMC + lane * 4);
        float2 pd0 = __bfloat1622float2(*(__nv_bfloat162*)&pdw.x);
        float2 pd1 = __bfloat1622float2(*(__nv_bfloat162*)&pdw.y);
        float2 ps0 = __bfloat1622float2(*(__nv_bfloat162*)&psw.x);
        float2 ps1 = __bfloat1622float2(*(__nv_bfloat162*)&psw.y);
        float4 hs = *(const float4*)&h[(size_t)s * DIMC + lane * 4];
        float g0 = 1.0f / (1.0f + expf(-(pd0.x + ps0.x)));
        float g1 = 1.0f / (1.0f + expf(-(pd0.y + ps0.y)));
        float g2 = 1.0f / (1.0f + expf(-(pd1.x + ps1.x)));
        float g3 = 1.0f / (1.0f + expf(-(pd1.y + ps1.y)));
        a0 += hs.x * ex * g0;
        a1 += hs.y * ex * g1;
        a2 += hs.z * ex * g2;
        a3 += hs.w * ex * g3;
        den += ex;
    }

    float inv = (den > 0.f) ? __frcp_rn(den) : 0.f;
    *(float4*)&g_hN[(size_t)n * DIMC + lane * 4] =
        make_float4(a0 * inv, a1 * inv, a2 * inv, a3 * inv);
}

// ---------------- f32x2 packed-FMA helpers ----------------
__device__ __forceinline__ unsigned long long pack2(float x) {
    unsigned long long r;
    asm("mov.b64 %0, {%1, %1};" : "=l"(r) : "f"(x));
    return r;
}
__device__ __forceinline__ void ffma2(unsigned long long& acc, unsigned long long a,
                                      unsigned long long b) {
    asm("fma.rn.f32x2 %0, %1, %2, %0;" : "+l"(acc) : "l"(a), "l"(b));
}
__device__ __forceinline__ float2 unpack2(unsigned long long v) {
    float2 r;
    asm("mov.b64 {%0, %1}, %2;" : "=f"(r.x), "=f"(r.y) : "l"(v));
    return r;
}

// ---------------- final: out = leaky([h ; h_N] @ W_lin^T + b_lin) ----------------
__global__ __launch_bounds__(256) void k_final(const float* __restrict__ h,
                                               const float* __restrict__ b_lin,
                                               float* __restrict__ out) {
    __shared__ float As[16][132];
    __shared__ float Bs[16][128];

    const int tid = threadIdx.x;
    const int m0 = blockIdx.x * 128;
    const int tr = tid >> 4;
    const int tc = tid & 15;
    const int a_row = tid >> 2;
    const int a_col = (tid & 3) << 2;
    const int b_row = tid >> 5;
    const int b_col = (tid & 31) << 2;

    unsigned long long acc[8][4];
#pragma unroll
    for (int i = 0; i < 8; i++)
#pragma unroll
        for (int j = 0; j < 4; j++) acc[i][j] = 0ull;

    for (int k0 = 0; k0 < 2 * DIMC; k0 += 16) {
        const float* Asrc = (k0 < DIMC) ? (h + k0) : (g_hN + (k0 - DIMC));
#pragma unroll
        for (int half = 0; half < 2; half++) {
            int m = a_row + half * 64;
            float4 v = make_float4(0.f, 0.f, 0.f, 0.f);
            if (m0 + m < N_NODESC)
                v = *(const float4*)(Asrc + (size_t)(m0 + m) * DIMC + a_col);
            As[a_col + 0][m] = v.x;
            As[a_col + 1][m] = v.y;
            As[a_col + 2][m] = v.z;
            As[a_col + 3][m] = v.w;
        }
#pragma unroll
        for (int half = 0; half < 2; half++) {
            int kk = b_row + half * 8;
            *(float4*)&Bs[kk][b_col] =
                *(const float4*)(g_WlT + (size_t)(k0 + kk) * DIMC + b_col);
        }
        __syncthreads();

#pragma unroll
        for (int k = 0; k < 16; k++) {
            float4 a0 = *(const float4*)&As[k][tr * 8];
            float4 a1 = *(const float4*)&As[k][tr * 8 + 4];
            unsigned long long ap[8];
            ap[0] = pack2(a0.x); ap[1] = pack2(a0.y); ap[2] = pack2(a0.z); ap[3] = pack2(a0.w);
            ap[4] = pack2(a1.x); ap[5] = pack2(a1.y); ap[6] = pack2(a1.z); ap[7] = pack2(a1.w);
            ulonglong2 bq0 = *(const ulonglong2*)&Bs[k][tc * 8];
            ulonglong2 bq1 = *(const ulonglong2*)&Bs[k][tc * 8 + 4];
            unsigned long long bp[4] = {bq0.x, bq0.y, bq1.x, bq1.y};
#pragma unroll
            for (int i = 0; i < 8; i++)
#pragma unroll
                for (int j = 0; j < 4; j++) ffma2(acc[i][j], ap[i], bp[j]);
        }
        __syncthreads();
    }

#pragma unroll
    for (int i = 0; i < 8; i++) {
        int m = m0 + tr * 8 + i;
        if (m < N_NODESC) {
            float* cp = out + (size_t)m * DIMC + tc * 8;
#pragma unroll
            for (int j = 0; j < 4; j++) {
                float2 p = unpack2(acc[i][j]);
                float2 bl = *(const float2*)&b_lin[tc * 8 + j * 2];
                float v0 = p.x + bl.x;
                float v1 = p.y + bl.y;
                v0 = v0 > 0.f ? v0 : 0.01f * v0;
                v1 = v1 > 0.f ? v1 : 0.01f * v1;
                *(float2*)(cp + j * 2) = make_float2(v0, v1);
            }
        }
    }
}

// ---------------- launch ----------------
extern "C" void kernel_launch(void* const* d_in, const int* in_sizes, int n_in,
                              void* d_out, int out_size) {
    const float* h      = (const float*)d_in[0];
    const float* rel    = (const float*)d_in[1];
    const float* relatt = (const float*)d_in[2];
    const float* W_a    = (const float*)d_in[3];
    const float* b_a    = (const float*)d_in[4];
    const float* W_lin  = (const float*)d_in[5];
    const float* b_lin  = (const float*)d_in[6];
    const int* src   = (const int*)d_in[7];
    const int* dst   = (const int*)d_in[8];
    const int* etype = (const int*)d_in[9];
    float* out = (float*)d_out;

    cudaFuncSetAttribute(k_tgemm2, cudaFuncAttributeMaxDynamicSharedMemorySize, SM_GEMM2);
    cudaFuncSetAttribute(k_tgemm3, cudaFuncAttributeMaxDynamicSharedMemorySize, SM_GEMM3);

    // prep
    k_cvtA<<<(N_NODESC * DIMC + 255) / 256, 256>>>(h);
    k_prepB<<<(TCNT * DIMC * DIMC + 255) / 256, 256>>>(rel, W_a, W_lin);

    // CSR build
    k_csr0<<<(N_NODESC + 1023) / 1024, 1024>>>();
    k_hist<<<(N_EDGESC + 1023) / 1024, 1024>>>(dst);
    k_scan1<<<SCANBLKS, 512>>>();
    k_scan2<<<1, 32>>>();
    k_scan3<<<SCANBLKS, 512>>>();
    k_scatter<<<(N_EDGESC + 1023) / 1024, 1024>>>(src, dst, etype);

    // GEMMs
    k_tgemm3<<<MBLKS, 256, SM_GEMM3>>>();
    dim3 gg(STRIPS2, 16);
    k_tgemm2<<<gg, 256, SM_GEMM2>>>();

    // message passing (atomic-free)
    k_msg2<<<(N_NODESC + 7) / 8, 256>>>(h, relatt, b_a);

    k_final<<<(N_NODESC + 127) / 128, 256>>>(h, b_lin, out);
}

// round 10
// speedup vs baseline: 2.0818x; 1.1419x over previous
#include <cuda_runtime.h>
#include <cuda_bf16.h>
#include <cstdint>

#define N_NODESC 50000
#define N_EDGESC 500000
#define DIMC     128
#define A_DIMC   64
#define NPADC    50048      // 391 * 128
#define MBLKS    391
#define STRIPS2  37
#define TCNT     17
#define SCANBLKS 98         // 98 * 512 >= 50000

// ---------------- device scratch ----------------
__device__ __align__(16) __nv_bfloat16 g_hh[(size_t)NPADC * DIMC];
__device__ __align__(16) __nv_bfloat16 g_hl[(size_t)NPADC * DIMC];
__device__ __align__(16) __nv_bfloat16 g_Bh[(size_t)TCNT * DIMC * DIMC]; // [t][n][k]
__device__ __align__(16) __nv_bfloat16 g_Bl[(size_t)TCNT * DIMC * DIMC];
__device__ __align__(16) __nv_bfloat16 g_projb[(size_t)16 * N_NODESC * DIMC]; // 204.8MB
__device__ __align__(16) float g_q[(size_t)N_NODESC * DIMC];
__device__ __align__(16) float g_hN[(size_t)N_NODESC * DIMC];
__device__ __align__(16) float g_WlT[2 * DIMC * DIMC];
// CSR scratch
__device__ int g_cnt[N_NODESC];
__device__ int g_rowpre[N_NODESC];
__device__ int g_rowptr[N_NODESC + 1];
__device__ int g_bsum[SCANBLKS];
__device__ int g_epack[N_EDGESC];   // (etype<<16) | src

// ---------------- ptx helpers ----------------
__device__ __forceinline__ uint32_t smem_u32(const void* p) {
    uint32_t a;
    asm("{ .reg .u64 t; cvta.to.shared.u64 t, %1; cvt.u32.u64 %0, t; }" : "=r"(a) : "l"(p));
    return a;
}
__device__ __forceinline__ void cp16(uint32_t dst, const void* src) {
    asm volatile("cp.async.cg.shared.global [%0], [%1], 16;" :: "r"(dst), "l"(src));
}
#define CP_COMMIT() asm volatile("cp.async.commit_group;" ::: "memory")
#define CP_WAIT(n)  asm volatile("cp.async.wait_group %0;" :: "n"(n) : "memory")

__device__ __forceinline__ void ldmx4(uint32_t* r, uint32_t addr) {
    asm volatile("ldmatrix.sync.aligned.m8n8.x4.shared.b16 {%0,%1,%2,%3}, [%4];"
                 : "=r"(r[0]), "=r"(r[1]), "=r"(r[2]), "=r"(r[3]) : "r"(addr));
}
__device__ __forceinline__ void mma16816(float* d, const uint32_t* a, uint32_t b0, uint32_t b1) {
    asm volatile("mma.sync.aligned.m16n8k16.row.col.f32.bf16.bf16.f32 "
                 "{%0,%1,%2,%3}, {%4,%5,%6,%7}, {%8,%9}, {%0,%1,%2,%3};"
                 : "+f"(d[0]), "+f"(d[1]), "+f"(d[2]), "+f"(d[3])
                 : "r"(a[0]), "r"(a[1]), "r"(a[2]), "r"(a[3]), "r"(b0), "r"(b1));
}

__device__ __forceinline__ float fsig(float x) {          // fast sigmoid
    return __frcp_rn(1.0f + __expf(-x));
}

// ---------------- prep kernels ----------------
__global__ void k_cvtA(const float* __restrict__ h) {
    int i = blockIdx.x * 256 + threadIdx.x;
    if (i < N_NODESC * DIMC) {
        float v = h[i];
        __nv_bfloat16 hi = __float2bfloat16(v);
        g_hh[i] = hi;
        g_hl[i] = __float2bfloat16(v - __bfloat162float(hi));
    }
    if (i < N_NODESC) g_cnt[i] = 0;
}

__global__ void k_prepB(const float* __restrict__ rel, const float* __restrict__ W_a,
                        const float* __restrict__ W_lin) {
    int i = blockIdx.x * 256 + threadIdx.x;
    if (i < TCNT * DIMC * DIMC) {
        int t = i >> 14, n = (i >> 7) & 127, k = i & 127;
        float v;
        if (t < 16) {
            int side = t >> 3, r = t & 7;
            v = rel[((size_t)(r * 256 + side * 128 + k)) * 128 + n];
        } else {
            v = (n < A_DIMC) ? W_a[n * 256 + k] : W_a[(n - A_DIMC) * 256 + DIMC + k];
        }
        __nv_bfloat16 hi = __float2bfloat16(v);
        g_Bh[i] = hi;
        g_Bl[i] = __float2bfloat16(v - __bfloat162float(hi));
    }
    if (i < 2 * DIMC * DIMC) {
        int k = i >> 7, o = i & 127;
        g_WlT[i] = W_lin[o * 256 + k];
    }
}

// ---------------- CSR build ----------------
__global__ void k_hist(const int* __restrict__ dst) {
    int i = blockIdx.x * 1024 + threadIdx.x;
    if (i < N_EDGESC) atomicAdd(&g_cnt[dst[i]], 1);
}
__global__ void k_scan1() {
    __shared__ int sh[512];
    int i = blockIdx.x * 512 + threadIdx.x;
    int v = (i < N_NODESC) ? g_cnt[i] : 0;
    sh[threadIdx.x] = v;
    __syncthreads();
    for (int off = 1; off < 512; off <<= 1) {
        int t = (threadIdx.x >= off) ? sh[threadIdx.x - off] : 0;
        __syncthreads();
        sh[threadIdx.x] += t;
        __syncthreads();
    }
    if (i < N_NODESC) g_rowpre[i] = sh[threadIdx.x] - v;
    if (threadIdx.x == 511) g_bsum[blockIdx.x] = sh[511];
}
__global__ void k_scan2() {
    if (threadIdx.x == 0) {
        int acc = 0;
        for (int b = 0; b < SCANBLKS; b++) { int v = g_bsum[b]; g_bsum[b] = acc; acc += v; }
        g_rowptr[N_NODESC] = N_EDGESC;
    }
}
__global__ void k_scan3() {
    int i = blockIdx.x * 512 + threadIdx.x;
    if (i < N_NODESC) {
        g_rowptr[i] = g_rowpre[i] + g_bsum[i >> 9];
        g_cnt[i] = 0;
    }
}
__global__ void k_scatter(const int* __restrict__ src, const int* __restrict__ dst,
                          const int* __restrict__ etype) {
    int i = blockIdx.x * 1024 + threadIdx.x;
    if (i < N_EDGESC) {
        int d = dst[i];
        int pos = g_rowptr[d] + atomicAdd(&g_cnt[d], 1);
        g_epack[pos] = (etype[i] << 16) | src[i];
    }
}

#define ROWB 272
#define TILEB 34816
#define SM_GEMM2 (3 * TILEB)
#define SM_GEMM3 (4 * TILEB)

// ---------------- gate GEMMs (t<16), plain bf16, persistent strips ----------------
__global__ void __launch_bounds__(256, 2) k_tgemm2() {
    extern __shared__ char smem[];
    const uint32_t sb  = smem_u32(smem);
    const uint32_t sBh  = sb;
    const uint32_t sAh0 = sb + TILEB;
    const uint32_t sAh1 = sb + 2 * TILEB;

    const int tid = threadIdx.x;
    const int lane = tid & 31;
    const int wid = tid >> 5;
    const int t = blockIdx.y;
    const int strip = blockIdx.x;
    const int n_m = (MBLKS - strip + STRIPS2 - 1) / STRIPS2;

    {
        const __nv_bfloat16* Bh = g_Bh + (size_t)t * DIMC * DIMC;
        const size_t mbase = (size_t)strip * 128 * DIMC;
        for (int idx = tid; idx < 2048; idx += 256) {
            int row = idx >> 4, c = idx & 15;
            uint32_t doff = row * ROWB + c * 16;
            size_t soff = (size_t)row * DIMC + c * 8;
            cp16(sBh + doff, Bh + soff);
            cp16(sAh0 + doff, g_hh + mbase + soff);
        }
    }
    CP_COMMIT();

    const int mb = (wid & 3) * 32;
    const int nb = (wid >> 2) * 64;
    const int a_row = (lane & 7) + 8 * ((lane >> 3) & 1);
    const int a_kh  = (lane >> 4) * 16;
    const int b_row = (lane & 7) + 8 * (lane >> 4);
    const int b_kh  = ((lane >> 3) & 1) * 16;
    const int rb_local = mb + (lane >> 2);
    const int cbase = nb + 2 * (lane & 3);

    for (int it = 0; it < n_m; it++) {
        const uint32_t sAh = (it & 1) ? sAh1 : sAh0;

        if (it + 1 < n_m) {
            const uint32_t dAh = (it & 1) ? sAh0 : sAh1;
            const size_t mbase = (size_t)(strip + (it + 1) * STRIPS2) * 128 * DIMC;
            for (int idx = tid; idx < 2048; idx += 256) {
                int row = idx >> 4, c = idx & 15;
                cp16(dAh + row * ROWB + c * 16, g_hh + mbase + (size_t)row * DIMC + c * 8);
            }
            CP_COMMIT();
            CP_WAIT(1);
        } else {
            CP_WAIT(0);
        }
        __syncthreads();

        float acc[2][8][4];
#pragma unroll
        for (int i = 0; i < 2; i++)
#pragma unroll
            for (int j = 0; j < 8; j++)
#pragma unroll
                for (int v = 0; v < 4; v++) acc[i][j][v] = 0.0f;

#pragma unroll
        for (int k0 = 0; k0 < 8; k0++) {
            const uint32_t kbyte = k0 * 32;
            uint32_t ah[2][4], bh[4][4];
#pragma unroll
            for (int mt = 0; mt < 2; mt++)
                ldmx4(ah[mt], sAh + (mb + mt * 16 + a_row) * ROWB + kbyte + a_kh);
#pragma unroll
            for (int q = 0; q < 4; q++)
                ldmx4(bh[q], sBh + (nb + q * 16 + b_row) * ROWB + kbyte + b_kh);
#pragma unroll
            for (int mt = 0; mt < 2; mt++) {
#pragma unroll
                for (int nf = 0; nf < 8; nf++) {
                    mma16816(acc[mt][nf], ah[mt],
                             bh[nf >> 1][(nf & 1) * 2], bh[nf >> 1][(nf & 1) * 2 + 1]);
                }
            }
        }

        const int m0 = (strip + it * STRIPS2) * 128;
#pragma unroll
        for (int mt = 0; mt < 2; mt++) {
#pragma unroll
            for (int pair = 0; pair < 2; pair++) {
                int m = m0 + rb_local + mt * 16 + pair * 8;
                if (m >= N_NODESC) continue;
                __nv_bfloat16* dp = g_projb + ((size_t)t * N_NODESC + m) * DIMC;
#pragma unroll
                for (int nf = 0; nf < 8; nf++) {
                    float v0 = acc[mt][nf][pair * 2 + 0];
                    float v1 = acc[mt][nf][pair * 2 + 1];
                    uint32_t pk;
                    asm("cvt.rn.satfinite.bf16x2.f32 %0, %1, %2;" : "=r"(pk) : "f"(v1), "f"(v0));
                    *(uint32_t*)(dp + cbase + nf * 8) = pk;
                }
            }
        }
        __syncthreads();
    }
}

// ---------------- attention GEMM (t=16), 3-term ----------------
__global__ void __launch_bounds__(256, 1) k_tgemm3() {
    extern __shared__ char smem[];
    const uint32_t sb = smem_u32(smem);
    const uint32_t sAh = sb, sAl = sb + TILEB, sBh = sb + 2 * TILEB, sBl = sb + 3 * TILEB;

    const int tid = threadIdx.x;
    const int lane = tid & 31;
    const int wid = tid >> 5;
    const int m0 = blockIdx.x * 128;

    {
        const __nv_bfloat16* Bh = g_Bh + (size_t)16 * DIMC * DIMC;
        const __nv_bfloat16* Bl = g_Bl + (size_t)16 * DIMC * DIMC;
        const size_t mbase = (size_t)m0 * DIMC;
        for (int idx = tid; idx < 2048; idx += 256) {
            int row = idx >> 4, c = idx & 15;
            uint32_t doff = row * ROWB + c * 16;
            size_t soff = (size_t)row * DIMC + c * 8;
            cp16(sAh + doff, g_hh + mbase + soff);
            cp16(sAl + doff, g_hl + mbase + soff);
            cp16(sBh + doff, Bh + soff);
            cp16(sBl + doff, Bl + soff);
        }
    }
    CP_COMMIT();
    CP_WAIT(0);
    __syncthreads();

    const int mb = (wid & 3) * 32;
    const int nb = (wid >> 2) * 64;
    const int a_row = (lane & 7) + 8 * ((lane >> 3) & 1);
    const int a_kh  = (lane >> 4) * 16;
    const int b_row = (lane & 7) + 8 * (lane >> 4);
    const int b_kh  = ((lane >> 3) & 1) * 16;

    float acc[2][8][4];
#pragma unroll
    for (int i = 0; i < 2; i++)
#pragma unroll
        for (int j = 0; j < 8; j++)
#pragma unroll
            for (int v = 0; v < 4; v++) acc[i][j][v] = 0.0f;

#pragma unroll
    for (int k0 = 0; k0 < 8; k0++) {
        const uint32_t kbyte = k0 * 32;
        uint32_t ah[2][4], al[2][4], bh[4][4], bl[4][4];
#pragma unroll
        for (int mt = 0; mt < 2; mt++) {
            uint32_t ar = (mb + mt * 16 + a_row) * ROWB + kbyte + a_kh;
            ldmx4(ah[mt], sAh + ar);
            ldmx4(al[mt], sAl + ar);
        }
#pragma unroll
        for (int q = 0; q < 4; q++) {
            uint32_t br = (nb + q * 16 + b_row) * ROWB + kbyte + b_kh;
            ldmx4(bh[q], sBh + br);
            ldmx4(bl[q], sBl + br);
        }
#pragma unroll
        for (int mt = 0; mt < 2; mt++) {
#pragma unroll
            for (int nf = 0; nf < 8; nf++) {
                uint32_t h0 = bh[nf >> 1][(nf & 1) * 2], h1 = bh[nf >> 1][(nf & 1) * 2 + 1];
                uint32_t l0 = bl[nf >> 1][(nf & 1) * 2], l1 = bl[nf >> 1][(nf & 1) * 2 + 1];
                mma16816(acc[mt][nf], ah[mt], h0, h1);
                mma16816(acc[mt][nf], ah[mt], l0, l1);
                mma16816(acc[mt][nf], al[mt], h0, h1);
            }
        }
    }

    const int rbase = m0 + mb + (lane >> 2);
    const int cbase = nb + 2 * (lane & 3);
#pragma unroll
    for (int mt = 0; mt < 2; mt++) {
#pragma unroll
        for (int pair = 0; pair < 2; pair++) {
            int m = rbase + mt * 16 + pair * 8;
            if (m >= N_NODESC) continue;
            float* dp = g_q + (size_t)m * DIMC;
#pragma unroll
            for (int nf = 0; nf < 8; nf++)
                *(float2*)(dp + cbase + nf * 8) =
                    make_float2(acc[mt][nf][pair * 2], acc[mt][nf][pair * 2 + 1]);
        }
    }
}

// ---------------- warp-per-node message kernel: 2-edge ILP + fast exp ----------------
__global__ void __launch_bounds__(256) k_msg2(const float* __restrict__ h,
                                              const float* __restrict__ rel_att,
                                              const float* __restrict__ b_a) {
    const int lane = threadIdx.x & 31;
    const int n = blockIdx.x * 8 + (threadIdx.x >> 5);
    if (n >= N_NODESC) return;
    const int beg = g_rowptr[n];
    const int end = g_rowptr[n + 1];

    float2 qd = *(const float2*)&g_q[(size_t)n * DIMC + lane * 2];
    float2 ba = *(const float2*)&b_a[lane * 2];
    float2 ra = *(const float2*)&rel_att[lane * 2];
    const float qdx = qd.x + ba.x, qdy = qd.y + ba.y;
    const __nv_bfloat16* pdbase = g_projb + (size_t)n * DIMC + lane * 4;

    float a0 = 0.f, a1 = 0.f, a2 = 0.f, a3 = 0.f, den = 0.f;

    int e = beg;
    for (; e + 2 <= end; e += 2) {
        // ---- issue both edges' gathers up front ----
        int pack0 = __ldg(&g_epack[e]);
        int pack1 = __ldg(&g_epack[e + 1]);
        int s0 = pack0 & 0xFFFF, r0 = pack0 >> 16;
        int s1 = pack1 & 0xFFFF, r1 = pack1 >> 16;

        float2 qs0 = *(const float2*)&g_q[(size_t)s0 * DIMC + A_DIMC + lane * 2];
        float2 qs1 = *(const float2*)&g_q[(size_t)s1 * DIMC + A_DIMC + lane * 2];
        uint2 pdw0 = *(const uint2*)(pdbase + (size_t)r0 * N_NODESC * DIMC);
        uint2 pdw1 = *(const uint2*)(pdbase + (size_t)r1 * N_NODESC * DIMC);
        uint2 psw0 = *(const uint2*)(g_projb + ((size_t)(8 + r0) * N_NODESC + s0) * DIMC + lane * 4);
        uint2 psw1 = *(const uint2*)(g_projb + ((size_t)(8 + r1) * N_NODESC + s1) * DIMC + lane * 4);
        float4 hs0 = *(const float4*)&h[(size_t)s0 * DIMC + lane * 4];
        float4 hs1 = *(const float4*)&h[(size_t)s1 * DIMC + lane * 4];

        // ---- scores, interleaved reduce ----
        float u0 = qdx + qs0.x, v0 = qdy + qs0.y;
        float u1 = qdx + qs1.x, v1 = qdy + qs1.y;
        u0 = fmaxf(u0, 0.01f * u0); v0 = fmaxf(v0, 0.01f * v0);
        u1 = fmaxf(u1, 0.01f * u1); v1 = fmaxf(v1, 0.01f * v1);
        float p0 = ra.x * u0 + ra.y * v0;
        float p1 = ra.x * u1 + ra.y * v1;
#pragma unroll
        for (int o = 16; o > 0; o >>= 1) {
            p0 += __shfl_xor_sync(0xffffffffu, p0, o);
            p1 += __shfl_xor_sync(0xffffffffu, p1, o);
        }
        float ex0 = __expf(p0);
        float ex1 = __expf(p1);

        // ---- gates + accumulate ----
        float2 pd00 = __bfloat1622float2(*(__nv_bfloat162*)&pdw0.x);
        float2 pd01 = __bfloat1622float2(*(__nv_bfloat162*)&pdw0.y);
        float2 ps00 = __bfloat1622float2(*(__nv_bfloat162*)&psw0.x);
        float2 ps01 = __bfloat1622float2(*(__nv_bfloat162*)&psw0.y);
        a0 += hs0.x * ex0 * fsig(pd00.x + ps00.x);
        a1 += hs0.y * ex0 * fsig(pd00.y + ps00.y);
        a2 += hs0.z * ex0 * fsig(pd01.x + ps01.x);
        a3 += hs0.w * ex0 * fsig(pd01.y + ps01.y);

        float2 pd10 = __bfloat1622float2(*(__nv_bfloat162*)&pdw1.x);
        float2 pd11 = __bfloat1622float2(*(__nv_bfloat162*)&pdw1.y);
        float2 ps10 = __bfloat1622float2(*(__nv_bfloat162*)&psw1.x);
        float2 ps11 = __bfloat1622float2(*(__nv_bfloat162*)&psw1.y);
        a0 += hs1.x * ex1 * fsig(pd10.x + ps10.x);
        a1 += hs1.y * ex1 * fsig(pd10.y + ps10.y);
        a2 += hs1.z * ex1 * fsig(pd11.x + ps11.x);
        a3 += hs1.w * ex1 * fsig(pd11.y + ps11.y);

        den += ex0 + ex1;
    }
    if (e < end) {
        int pack0 = __ldg(&g_epack[e]);
        int s0 = pack0 & 0xFFFF, r0 = pack0 >> 16;
        float2 qs0 = *(const float2*)&g_q[(size_t)s0 * DIMC + A_DIMC + lane * 2];
        uint2 pdw0 = *(const uint2*)(pdbase + (size_t)r0 * N_NODESC * DIMC);
        uint2 psw0 = *(const uint2*)(g_projb + ((size_t)(8 + r0) * N_NODESC + s0) * DIMC + lane * 4);
        float4 hs0 = *(const float4*)&h[(size_t)s0 * DIMC + lane * 4];
        float u0 = qdx + qs0.x, v0 = qdy + qs0.y;
        u0 = fmaxf(u0, 0.01f * u0); v0 = fmaxf(v0, 0.01f * v0);
        float p0 = ra.x * u0 + ra.y * v0;
#pragma unroll
        for (int o = 16; o > 0; o >>= 1) p0 += __shfl_xor_sync(0xffffffffu, p0, o);
        float ex0 = __expf(p0);
        float2 pd00 = __bfloat1622float2(*(__nv_bfloat162*)&pdw0.x);
        float2 pd01 = __bfloat1622float2(*(__nv_bfloat162*)&pdw0.y);
        float2 ps00 = __bfloat1622float2(*(__nv_bfloat162*)&psw0.x);
        float2 ps01 = __bfloat1622float2(*(__nv_bfloat162*)&psw0.y);
        a0 += hs0.x * ex0 * fsig(pd00.x + ps00.x);
        a1 += hs0.y * ex0 * fsig(pd00.y + ps00.y);
        a2 += hs0.z * ex0 * fsig(pd01.x + ps01.x);
        a3 += hs0.w * ex0 * fsig(pd01.y + ps01.y);
        den += ex0;
    }

    float inv = (den > 0.f) ? __frcp_rn(den) : 0.f;
    *(float4*)&g_hN[(size_t)n * DIMC + lane * 4] =
        make_float4(a0 * inv, a1 * inv, a2 * inv, a3 * inv);
}

// ---------------- f32x2 packed-FMA helpers ----------------
__device__ __forceinline__ unsigned long long pack2(float x) {
    unsigned long long r;
    asm("mov.b64 %0, {%1, %1};" : "=l"(r) : "f"(x));
    return r;
}
__device__ __forceinline__ void ffma2(unsigned long long& acc, unsigned long long a,
                                      unsigned long long b) {
    asm("fma.rn.f32x2 %0, %1, %2, %0;" : "+l"(acc) : "l"(a), "l"(b));
}
__device__ __forceinline__ float2 unpack2(unsigned long long v) {
    float2 r;
    asm("mov.b64 {%0, %1}, %2;" : "=f"(r.x), "=f"(r.y) : "l"(v));
    return r;
}

// ---------------- final: out = leaky([h ; h_N] @ W_lin^T + b_lin) ----------------
__global__ __launch_bounds__(256) void k_final(const float* __restrict__ h,
                                               const float* __restrict__ b_lin,
                                               float* __restrict__ out) {
    __shared__ float As[16][132];
    __shared__ float Bs[16][128];

    const int tid = threadIdx.x;
    const int m0 = blockIdx.x * 128;
    const int tr = tid >> 4;
    const int tc = tid & 15;
    const int a_row = tid >> 2;
    const int a_col = (tid & 3) << 2;
    const int b_row = tid >> 5;
    const int b_col = (tid & 31) << 2;

    unsigned long long acc[8][4];
#pragma unroll
    for (int i = 0; i < 8; i++)
#pragma unroll
        for (int j = 0; j < 4; j++) acc[i][j] = 0ull;

    for (int k0 = 0; k0 < 2 * DIMC; k0 += 16) {
        const float* Asrc = (k0 < DIMC) ? (h + k0) : (g_hN + (k0 - DIMC));
#pragma unroll
        for (int half = 0; half < 2; half++) {
            int m = a_row + half * 64;
            float4 v = make_float4(0.f, 0.f, 0.f, 0.f);
            if (m0 + m < N_NODESC)
                v = *(const float4*)(Asrc + (size_t)(m0 + m) * DIMC + a_col);
            As[a_col + 0][m] = v.x;
            As[a_col + 1][m] = v.y;
            As[a_col + 2][m] = v.z;
            As[a_col + 3][m] = v.w;
        }
#pragma unroll
        for (int half = 0; half < 2; half++) {
            int kk = b_row + half * 8;
            *(float4*)&Bs[kk][b_col] =
                *(const float4*)(g_WlT + (size_t)(k0 + kk) * DIMC + b_col);
        }
        __syncthreads();

#pragma unroll
        for (int k = 0; k < 16; k++) {
            float4 a0 = *(const float4*)&As[k][tr * 8];
            float4 a1 = *(const float4*)&As[k][tr * 8 + 4];
            unsigned long long ap[8];
            ap[0] = pack2(a0.x); ap[1] = pack2(a0.y); ap[2] = pack2(a0.z); ap[3] = pack2(a0.w);
            ap[4] = pack2(a1.x); ap[5] = pack2(a1.y); ap[6] = pack2(a1.z); ap[7] = pack2(a1.w);
            ulonglong2 bq0 = *(const ulonglong2*)&Bs[k][tc * 8];
            ulonglong2 bq1 = *(const ulonglong2*)&Bs[k][tc * 8 + 4];
            unsigned long long bp[4] = {bq0.x, bq0.y, bq1.x, bq1.y};
#pragma unroll
            for (int i = 0; i < 8; i++)
#pragma unroll
                for (int j = 0; j < 4; j++) ffma2(acc[i][j], ap[i], bp[j]);
        }
        __syncthreads();
    }

#pragma unroll
    for (int i = 0; i < 8; i++) {
        int m = m0 + tr * 8 + i;
        if (m < N_NODESC) {
            float* cp = out + (size_t)m * DIMC + tc * 8;
#pragma unroll
            for (int j = 0; j < 4; j++) {
                float2 p = unpack2(acc[i][j]);
                float2 bl = *(const float2*)&b_lin[tc * 8 + j * 2];
                float v0 = p.x + bl.x;
                float v1 = p.y + bl.y;
                v0 = v0 > 0.f ? v0 : 0.01f * v0;
                v1 = v1 > 0.f ? v1 : 0.01f * v1;
                *(float2*)(cp + j * 2) = make_float2(v0, v1);
            }
        }
    }
}

// ---------------- launch ----------------
extern "C" void kernel_launch(void* const* d_in, const int* in_sizes, int n_in,
                              void* d_out, int out_size) {
    const float* h      = (const float*)d_in[0];
    const float* rel    = (const float*)d_in[1];
    const float* relatt = (const float*)d_in[2];
    const float* W_a    = (const float*)d_in[3];
    const float* b_a    = (const float*)d_in[4];
    const float* W_lin  = (const float*)d_in[5];
    const float* b_lin  = (const float*)d_in[6];
    const int* src   = (const int*)d_in[7];
    const int* dst   = (const int*)d_in[8];
    const int* etype = (const int*)d_in[9];
    float* out = (float*)d_out;

    cudaFuncSetAttribute(k_tgemm2, cudaFuncAttributeMaxDynamicSharedMemorySize, SM_GEMM2);
    cudaFuncSetAttribute(k_tgemm3, cudaFuncAttributeMaxDynamicSharedMemorySize, SM_GEMM3);

    // prep (+ cnt zeroing)
    k_cvtA<<<(N_NODESC * DIMC + 255) / 256, 256>>>(h);
    k_prepB<<<(TCNT * DIMC * DIMC + 255) / 256, 256>>>(rel, W_a, W_lin);

    // CSR build
    k_hist<<<(N_EDGESC + 1023) / 1024, 1024>>>(dst);
    k_scan1<<<SCANBLKS, 512>>>();
    k_scan2<<<1, 32>>>();
    k_scan3<<<SCANBLKS, 512>>>();
    k_scatter<<<(N_EDGESC + 1023) / 1024, 1024>>>(src, dst, etype);

    // GEMMs
    k_tgemm3<<<MBLKS, 256, SM_GEMM3>>>();
    dim3 gg(STRIPS2, 16);
    k_tgemm2<<<gg, 256, SM_GEMM2>>>();

    // message passing (atomic-free, 2-edge ILP)
    k_msg2<<<(N_NODESC + 7) / 8, 256>>>(h, relatt, b_a);

    k_final<<<(N_NODESC + 127) / 128, 256>>>(h, b_lin, out);
}

// round 12
// speedup vs baseline: 2.3129x; 1.1110x over previous
#include <cuda_runtime.h>
#include <cuda_bf16.h>
#include <cstdint>

#define N_NODESC 50000
#define N_EDGESC 500000
#define DIMC     128
#define A_DIMC   64
#define NPADC    50048      // 391 * 128
#define MBLKS    391
#define STRIPS2  37
#define TCNT     17
#define SCANBLKS 98         // 98 * 512 >= 50000

// ---------------- device scratch ----------------
__device__ __align__(16) __nv_bfloat16 g_hh[(size_t)NPADC * DIMC];
__device__ __align__(16) __nv_bfloat16 g_hl[(size_t)NPADC * DIMC];
__device__ __align__(16) __nv_bfloat16 g_Bh[(size_t)TCNT * DIMC * DIMC]; // [t][n][k]
__device__ __align__(16) __nv_bfloat16 g_Bl[(size_t)TCNT * DIMC * DIMC];
__device__ __align__(16) __nv_bfloat16 g_projb[(size_t)16 * N_NODESC * DIMC]; // 204.8MB
__device__ __align__(16) float g_q[(size_t)N_NODESC * DIMC];
__device__ __align__(16) __nv_bfloat16 g_hNh[(size_t)NPADC * DIMC];  // h_N hi (bf16)
__device__ __align__(16) __nv_bfloat16 g_hNl[(size_t)NPADC * DIMC];  // h_N lo (bf16)
__device__ __align__(16) __nv_bfloat16 g_Wlh[2 * DIMC * DIMC];       // [kt][n][k]
__device__ __align__(16) __nv_bfloat16 g_Wll[2 * DIMC * DIMC];
// CSR scratch
__device__ int g_cnt[N_NODESC];
__device__ int g_rowpre[N_NODESC];
__device__ int g_rowptr[N_NODESC + 1];
__device__ int g_bsum[SCANBLKS];
__device__ int g_epack[N_EDGESC];   // (etype<<16) | src

// ---------------- ptx helpers ----------------
__device__ __forceinline__ uint32_t smem_u32(const void* p) {
    uint32_t a;
    asm("{ .reg .u64 t; cvta.to.shared.u64 t, %1; cvt.u32.u64 %0, t; }" : "=r"(a) : "l"(p));
    return a;
}
__device__ __forceinline__ void cp16(uint32_t dst, const void* src) {
    asm volatile("cp.async.cg.shared.global [%0], [%1], 16;" :: "r"(dst), "l"(src));
}
#define CP_COMMIT() asm volatile("cp.async.commit_group;" ::: "memory")
#define CP_WAIT(n)  asm volatile("cp.async.wait_group %0;" :: "n"(n) : "memory")

__device__ __forceinline__ void ldmx4(uint32_t* r, uint32_t addr) {
    asm volatile("ldmatrix.sync.aligned.m8n8.x4.shared.b16 {%0,%1,%2,%3}, [%4];"
                 : "=r"(r[0]), "=r"(r[1]), "=r"(r[2]), "=r"(r[3]) : "r"(addr));
}
__device__ __forceinline__ void mma16816(float* d, const uint32_t* a, uint32_t b0, uint32_t b1) {
    asm volatile("mma.sync.aligned.m16n8k16.row.col.f32.bf16.bf16.f32 "
                 "{%0,%1,%2,%3}, {%4,%5,%6,%7}, {%8,%9}, {%0,%1,%2,%3};"
                 : "+f"(d[0]), "+f"(d[1]), "+f"(d[2]), "+f"(d[3])
                 : "r"(a[0]), "r"(a[1]), "r"(a[2]), "r"(a[3]), "r"(b0), "r"(b1));
}

__device__ __forceinline__ float fsig(float x) {          // fast sigmoid
    return __frcp_rn(1.0f + __expf(-x));
}

// ---------------- prep kernels ----------------
__global__ void k_cvtA(const float* __restrict__ h) {
    int i = blockIdx.x * 256 + threadIdx.x;
    if (i < N_NODESC * DIMC) {
        float v = h[i];
        __nv_bfloat16 hi = __float2bfloat16(v);
        g_hh[i] = hi;
        g_hl[i] = __float2bfloat16(v - __bfloat162float(hi));
    }
    if (i < N_NODESC) g_cnt[i] = 0;
}

__global__ void k_prepB(const float* __restrict__ rel, const float* __restrict__ W_a,
                        const float* __restrict__ W_lin) {
    int i = blockIdx.x * 256 + threadIdx.x;
    if (i < TCNT * DIMC * DIMC) {
        int t = i >> 14, n = (i >> 7) & 127, k = i & 127;
        float v;
        if (t < 16) {
            int side = t >> 3, r = t & 7;
            v = rel[((size_t)(r * 256 + side * 128 + k)) * 128 + n];
        } else {
            v = (n < A_DIMC) ? W_a[n * 256 + k] : W_a[(n - A_DIMC) * 256 + DIMC + k];
        }
        __nv_bfloat16 hi = __float2bfloat16(v);
        g_Bh[i] = hi;
        g_Bl[i] = __float2bfloat16(v - __bfloat162float(hi));
    }
    if (i < 2 * DIMC * DIMC) {
        int kt = i >> 14, n = (i >> 7) & 127, k = i & 127;
        float v = W_lin[n * 256 + kt * 128 + k];
        __nv_bfloat16 hi = __float2bfloat16(v);
        g_Wlh[i] = hi;
        g_Wll[i] = __float2bfloat16(v - __bfloat162float(hi));
    }
}

// ---------------- CSR build ----------------
__global__ void k_hist(const int* __restrict__ dst) {
    int i = blockIdx.x * 1024 + threadIdx.x;
    if (i < N_EDGESC) atomicAdd(&g_cnt[dst[i]], 1);
}
__global__ void k_scan1() {
    __shared__ int sh[512];
    int i = blockIdx.x * 512 + threadIdx.x;
    int v = (i < N_NODESC) ? g_cnt[i] : 0;
    sh[threadIdx.x] = v;
    __syncthreads();
    for (int off = 1; off < 512; off <<= 1) {
        int t = (threadIdx.x >= off) ? sh[threadIdx.x - off] : 0;
        __syncthreads();
        sh[threadIdx.x] += t;
        __syncthreads();
    }
    if (i < N_NODESC) g_rowpre[i] = sh[threadIdx.x] - v;
    if (threadIdx.x == 511) g_bsum[blockIdx.x] = sh[511];
}
__global__ void k_scan2() {
    if (threadIdx.x == 0) {
        int acc = 0;
        for (int b = 0; b < SCANBLKS; b++) { int v = g_bsum[b]; g_bsum[b] = acc; acc += v; }
        g_rowptr[N_NODESC] = N_EDGESC;
    }
}
__global__ void k_scan3() {
    int i = blockIdx.x * 512 + threadIdx.x;
    if (i < N_NODESC) {
        g_rowptr[i] = g_rowpre[i] + g_bsum[i >> 9];
        g_cnt[i] = 0;
    }
}
__global__ void k_scatter(const int* __restrict__ src, const int* __restrict__ dst,
                          const int* __restrict__ etype) {
    int i = blockIdx.x * 1024 + threadIdx.x;
    if (i < N_EDGESC) {
        int d = dst[i];
        int pos = g_rowptr[d] + atomicAdd(&g_cnt[d], 1);
        g_epack[pos] = (etype[i] << 16) | src[i];
    }
}

#define ROWB 272
#define TILEB 34816
#define SM_GEMM2 (3 * TILEB)
#define SM_GEMM3 (4 * TILEB)

// ---------------- gate GEMMs (t<16), plain bf16, persistent strips ----------------
__global__ void __launch_bounds__(256, 2) k_tgemm2() {
    extern __shared__ char smem[];
    const uint32_t sb  = smem_u32(smem);
    const uint32_t sBh  = sb;
    const uint32_t sAh0 = sb + TILEB;
    const uint32_t sAh1 = sb + 2 * TILEB;

    const int tid = threadIdx.x;
    const int lane = tid & 31;
    const int wid = tid >> 5;
    const int t = blockIdx.y;
    const int strip = blockIdx.x;
    const int n_m = (MBLKS - strip + STRIPS2 - 1) / STRIPS2;

    {
        const __nv_bfloat16* Bh = g_Bh + (size_t)t * DIMC * DIMC;
        const size_t mbase = (size_t)strip * 128 * DIMC;
        for (int idx = tid; idx < 2048; idx += 256) {
            int row = idx >> 4, c = idx & 15;
            uint32_t doff = row * ROWB + c * 16;
            size_t soff = (size_t)row * DIMC + c * 8;
            cp16(sBh + doff, Bh + soff);
            cp16(sAh0 + doff, g_hh + mbase + soff);
        }
    }
    CP_COMMIT();

    const int mb = (wid & 3) * 32;
    const int nb = (wid >> 2) * 64;
    const int a_row = (lane & 7) + 8 * ((lane >> 3) & 1);
    const int a_kh  = (lane >> 4) * 16;
    const int b_row = (lane & 7) + 8 * (lane >> 4);
    const int b_kh  = ((lane >> 3) & 1) * 16;
    const int rb_local = mb + (lane >> 2);
    const int cbase = nb + 2 * (lane & 3);

    for (int it = 0; it < n_m; it++) {
        const uint32_t sAh = (it & 1) ? sAh1 : sAh0;

        if (it + 1 < n_m) {
            const uint32_t dAh = (it & 1) ? sAh0 : sAh1;
            const size_t mbase = (size_t)(strip + (it + 1) * STRIPS2) * 128 * DIMC;
            for (int idx = tid; idx < 2048; idx += 256) {
                int row = idx >> 4, c = idx & 15;
                cp16(dAh + row * ROWB + c * 16, g_hh + mbase + (size_t)row * DIMC + c * 8);
            }
            CP_COMMIT();
            CP_WAIT(1);
        } else {
            CP_WAIT(0);
        }
        __syncthreads();

        float acc[2][8][4];
#pragma unroll
        for (int i = 0; i < 2; i++)
#pragma unroll
            for (int j = 0; j < 8; j++)
#pragma unroll
                for (int v = 0; v < 4; v++) acc[i][j][v] = 0.0f;

#pragma unroll
        for (int k0 = 0; k0 < 8; k0++) {
            const uint32_t kbyte = k0 * 32;
            uint32_t ah[2][4], bh[4][4];
#pragma unroll
            for (int mt = 0; mt < 2; mt++)
                ldmx4(ah[mt], sAh + (mb + mt * 16 + a_row) * ROWB + kbyte + a_kh);
#pragma unroll
            for (int q = 0; q < 4; q++)
                ldmx4(bh[q], sBh + (nb + q * 16 + b_row) * ROWB + kbyte + b_kh);
#pragma unroll
            for (int mt = 0; mt < 2; mt++) {
#pragma unroll
                for (int nf = 0; nf < 8; nf++) {
                    mma16816(acc[mt][nf], ah[mt],
                             bh[nf >> 1][(nf & 1) * 2], bh[nf >> 1][(nf & 1) * 2 + 1]);
                }
            }
        }

        const int m0 = (strip + it * STRIPS2) * 128;
#pragma unroll
        for (int mt = 0; mt < 2; mt++) {
#pragma unroll
            for (int pair = 0; pair < 2; pair++) {
                int m = m0 + rb_local + mt * 16 + pair * 8;
                if (m >= N_NODESC) continue;
                __nv_bfloat16* dp = g_projb + ((size_t)t * N_NODESC + m) * DIMC;
#pragma unroll
                for (int nf = 0; nf < 8; nf++) {
                    float v0 = acc[mt][nf][pair * 2 + 0];
                    float v1 = acc[mt][nf][pair * 2 + 1];
                    uint32_t pk;
                    asm("cvt.rn.satfinite.bf16x2.f32 %0, %1, %2;" : "=r"(pk) : "f"(v1), "f"(v0));
                    *(uint32_t*)(dp + cbase + nf * 8) = pk;
                }
            }
        }
        __syncthreads();
    }
}

// ---------------- attention GEMM (t=16), 3-term ----------------
__global__ void __launch_bounds__(256, 1) k_tgemm3() {
    extern __shared__ char smem[];
    const uint32_t sb = smem_u32(smem);
    const uint32_t sAh = sb, sAl = sb + TILEB, sBh = sb + 2 * TILEB, sBl = sb + 3 * TILEB;

    const int tid = threadIdx.x;
    const int lane = tid & 31;
    const int wid = tid >> 5;
    const int m0 = blockIdx.x * 128;

    {
        const __nv_bfloat16* Bh = g_Bh + (size_t)16 * DIMC * DIMC;
        const __nv_bfloat16* Bl = g_Bl + (size_t)16 * DIMC * DIMC;
        const size_t mbase = (size_t)m0 * DIMC;
        for (int idx = tid; idx < 2048; idx += 256) {
            int row = idx >> 4, c = idx & 15;
            uint32_t doff = row * ROWB + c * 16;
            size_t soff = (size_t)row * DIMC + c * 8;
            cp16(sAh + doff, g_hh + mbase + soff);
            cp16(sAl + doff, g_hl + mbase + soff);
            cp16(sBh + doff, Bh + soff);
            cp16(sBl + doff, Bl + soff);
        }
    }
    CP_COMMIT();
    CP_WAIT(0);
    __syncthreads();

    const int mb = (wid & 3) * 32;
    const int nb = (wid >> 2) * 64;
    const int a_row = (lane & 7) + 8 * ((lane >> 3) & 1);
    const int a_kh  = (lane >> 4) * 16;
    const int b_row = (lane & 7) + 8 * (lane >> 4);
    const int b_kh  = ((lane >> 3) & 1) * 16;

    float acc[2][8][4];
#pragma unroll
    for (int i = 0; i < 2; i++)
#pragma unroll
        for (int j = 0; j < 8; j++)
#pragma unroll
            for (int v = 0; v < 4; v++) acc[i][j][v] = 0.0f;

#pragma unroll
    for (int k0 = 0; k0 < 8; k0++) {
        const uint32_t kbyte = k0 * 32;
        uint32_t ah[2][4], al[2][4], bh[4][4], bl[4][4];
#pragma unroll
        for (int mt = 0; mt < 2; mt++) {
            uint32_t ar = (mb + mt * 16 + a_row) * ROWB + kbyte + a_kh;
            ldmx4(ah[mt], sAh + ar);
            ldmx4(al[mt], sAl + ar);
        }
#pragma unroll
        for (int q = 0; q < 4; q++) {
            uint32_t br = (nb + q * 16 + b_row) * ROWB + kbyte + b_kh;
            ldmx4(bh[q], sBh + br);
            ldmx4(bl[q], sBl + br);
        }
#pragma unroll
        for (int mt = 0; mt < 2; mt++) {
#pragma unroll
            for (int nf = 0; nf < 8; nf++) {
                uint32_t h0 = bh[nf >> 1][(nf & 1) * 2], h1 = bh[nf >> 1][(nf & 1) * 2 + 1];
                uint32_t l0 = bl[nf >> 1][(nf & 1) * 2], l1 = bl[nf >> 1][(nf & 1) * 2 + 1];
                mma16816(acc[mt][nf], ah[mt], h0, h1);
                mma16816(acc[mt][nf], ah[mt], l0, l1);
                mma16816(acc[mt][nf], al[mt], h0, h1);
            }
        }
    }

    const int rbase = m0 + mb + (lane >> 2);
    const int cbase = nb + 2 * (lane & 3);
#pragma unroll
    for (int mt = 0; mt < 2; mt++) {
#pragma unroll
        for (int pair = 0; pair < 2; pair++) {
            int m = rbase + mt * 16 + pair * 8;
            if (m >= N_NODESC) continue;
            float* dp = g_q + (size_t)m * DIMC;
#pragma unroll
            for (int nf = 0; nf < 8; nf++)
                *(float2*)(dp + cbase + nf * 8) =
                    make_float2(acc[mt][nf][pair * 2], acc[mt][nf][pair * 2 + 1]);
        }
    }
}

// ---------------- warp-per-node message kernel: 4-edge ILP, bf16-split output ----------------
__global__ void __launch_bounds__(256) k_msg2(const float* __restrict__ h,
                                              const float* __restrict__ rel_att,
                                              const float* __restrict__ b_a) {
    const int lane = threadIdx.x & 31;
    const int n = blockIdx.x * 8 + (threadIdx.x >> 5);
    if (n >= N_NODESC) return;
    const int beg = g_rowptr[n];
    const int end = g_rowptr[n + 1];

    float2 qd = *(const float2*)&g_q[(size_t)n * DIMC + lane * 2];
    float2 ba = *(const float2*)&b_a[lane * 2];
    float2 ra = *(const float2*)&rel_att[lane * 2];
    const float qdx = qd.x + ba.x, qdy = qd.y + ba.y;
    const __nv_bfloat16* pdbase = g_projb + (size_t)n * DIMC + lane * 4;

    float a0 = 0.f, a1 = 0.f, a2 = 0.f, a3 = 0.f, den = 0.f;

    int e = beg;
    for (; e + 4 <= end; e += 4) {
        int s[4], r[4];
        float2 qs[4];
        uint2 pdw[4], psw[4];
        float4 hs[4];
#pragma unroll
        for (int j = 0; j < 4; j++) {
            int pack = __ldg(&g_epack[e + j]);
            s[j] = pack & 0xFFFF;
            r[j] = pack >> 16;
        }
#pragma unroll
        for (int j = 0; j < 4; j++) {
            qs[j]  = *(const float2*)&g_q[(size_t)s[j] * DIMC + A_DIMC + lane * 2];
            pdw[j] = *(const uint2*)(pdbase + (size_t)r[j] * N_NODESC * DIMC);
            psw[j] = *(const uint2*)(g_projb + ((size_t)(8 + r[j]) * N_NODESC + s[j]) * DIMC + lane * 4);
            hs[j]  = *(const float4*)&h[(size_t)s[j] * DIMC + lane * 4];
        }
        float p[4];
#pragma unroll
        for (int j = 0; j < 4; j++) {
            float u = qdx + qs[j].x, v = qdy + qs[j].y;
            u = fmaxf(u, 0.01f * u);
            v = fmaxf(v, 0.01f * v);
            p[j] = ra.x * u + ra.y * v;
        }
#pragma unroll
        for (int o = 16; o > 0; o >>= 1) {
#pragma unroll
            for (int j = 0; j < 4; j++)
                p[j] += __shfl_xor_sync(0xffffffffu, p[j], o);
        }
#pragma unroll
        for (int j = 0; j < 4; j++) {
            float ex = __expf(p[j]);
            float2 pd0 = __bfloat1622float2(*(__nv_bfloat162*)&pdw[j].x);
            float2 pd1 = __bfloat1622float2(*(__nv_bfloat162*)&pdw[j].y);
            float2 ps0 = __bfloat1622float2(*(__nv_bfloat162*)&psw[j].x);
            float2 ps1 = __bfloat1622float2(*(__nv_bfloat162*)&psw[j].y);
            a0 += hs[j].x * ex * fsig(pd0.x + ps0.x);
            a1 += hs[j].y * ex * fsig(pd0.y + ps0.y);
            a2 += hs[j].z * ex * fsig(pd1.x + ps1.x);
            a3 += hs[j].w * ex * fsig(pd1.y + ps1.y);
            den += ex;
        }
    }
    for (; e < end; e++) {
        int pack = __ldg(&g_epack[e]);
        int s0 = pack & 0xFFFF, r0 = pack >> 16;
        float2 qs0 = *(const float2*)&g_q[(size_t)s0 * DIMC + A_DIMC + lane * 2];
        uint2 pdw0 = *(const uint2*)(pdbase + (size_t)r0 * N_NODESC * DIMC);
        uint2 psw0 = *(const uint2*)(g_projb + ((size_t)(8 + r0) * N_NODESC + s0) * DIMC + lane * 4);
        float4 hs0 = *(const float4*)&h[(size_t)s0 * DIMC + lane * 4];
        float u0 = qdx + qs0.x, v0 = qdy + qs0.y;
        u0 = fmaxf(u0, 0.01f * u0);
        v0 = fmaxf(v0, 0.01f * v0);
        float p0 = ra.x * u0 + ra.y * v0;
#pragma unroll
        for (int o = 16; o > 0; o >>= 1) p0 += __shfl_xor_sync(0xffffffffu, p0, o);
        float ex0 = __expf(p0);
        float2 pd00 = __bfloat1622float2(*(__nv_bfloat162*)&pdw0.x);
        float2 pd01 = __bfloat1622float2(*(__nv_bfloat162*)&pdw0.y);
        float2 ps00 = __bfloat1622float2(*(__nv_bfloat162*)&psw0.x);
        float2 ps01 = __bfloat1622float2(*(__nv_bfloat162*)&psw0.y);
        a0 += hs0.x * ex0 * fsig(pd00.x + ps00.x);
        a1 += hs0.y * ex0 * fsig(pd00.y + ps00.y);
        a2 += hs0.z * ex0 * fsig(pd01.x + ps01.x);
        a3 += hs0.w * ex0 * fsig(pd01.y + ps01.y);
        den += ex0;
    }

    float inv = (den > 0.f) ? __frcp_rn(den) : 0.f;
    float v0 = a0 * inv, v1 = a1 * inv, v2 = a2 * inv, v3 = a3 * inv;

    // split-bf16 store of h_N
    __nv_bfloat16 b0 = __float2bfloat16(v0);
    __nv_bfloat16 b1 = __float2bfloat16(v1);
    __nv_bfloat16 b2 = __float2bfloat16(v2);
    __nv_bfloat16 b3 = __float2bfloat16(v3);
    __nv_bfloat162* ph = (__nv_bfloat162*)&g_hNh[(size_t)n * DIMC + lane * 4];
    ph[0] = __nv_bfloat162(b0, b1);
    ph[1] = __nv_bfloat162(b2, b3);
    __nv_bfloat162* pl = (__nv_bfloat162*)&g_hNl[(size_t)n * DIMC + lane * 4];
    pl[0] = __floats2bfloat162_rn(v0 - __bfloat162float(b0), v1 - __bfloat162float(b1));
    pl[1] = __floats2bfloat162_rn(v2 - __bfloat162float(b2), v3 - __bfloat162float(b3));
}

// ---------------- final GEMM on HMMA: out = leaky([h ; h_N] @ W_lin^T + b_lin) ----------------
// K = 256 as two 128-k-tiles; 3-term bf16 split per tile.
__global__ void __launch_bounds__(256, 1) k_final(float* __restrict__ out,
                                                  const float* __restrict__ b_lin) {
    extern __shared__ char smem[];
    const uint32_t sb = smem_u32(smem);
    const uint32_t sAh = sb, sAl = sb + TILEB, sBh = sb + 2 * TILEB, sBl = sb + 3 * TILEB;

    const int tid = threadIdx.x;
    const int lane = tid & 31;
    const int wid = tid >> 5;
    const int m0 = blockIdx.x * 128;

    const int mb = (wid & 3) * 32;
    const int nb = (wid >> 2) * 64;
    const int a_row = (lane & 7) + 8 * ((lane >> 3) & 1);
    const int a_kh  = (lane >> 4) * 16;
    const int b_row = (lane & 7) + 8 * (lane >> 4);
    const int b_kh  = ((lane >> 3) & 1) * 16;

    float acc[2][8][4];
#pragma unroll
    for (int i = 0; i < 2; i++)
#pragma unroll
        for (int j = 0; j < 8; j++)
#pragma unroll
            for (int v = 0; v < 4; v++) acc[i][j][v] = 0.0f;

    for (int kt = 0; kt < 2; kt++) {
        const __nv_bfloat16* Ah = (kt ? g_hNh : g_hh) + (size_t)m0 * DIMC;
        const __nv_bfloat16* Al = (kt ? g_hNl : g_hl) + (size_t)m0 * DIMC;
        const __nv_bfloat16* Bh = g_Wlh + kt * DIMC * DIMC;
        const __nv_bfloat16* Bl = g_Wll + kt * DIMC * DIMC;
        for (int idx = tid; idx < 2048; idx += 256) {
            int row = idx >> 4, c = idx & 15;
            uint32_t doff = row * ROWB + c * 16;
            size_t soff = (size_t)row * DIMC + c * 8;
            cp16(sAh + doff, Ah + soff);
            cp16(sAl + doff, Al + soff);
            cp16(sBh + doff, Bh + soff);
            cp16(sBl + doff, Bl + soff);
        }
        CP_COMMIT();
        CP_WAIT(0);
        __syncthreads();

#pragma unroll
        for (int k0 = 0; k0 < 8; k0++) {
            const uint32_t kbyte = k0 * 32;
            uint32_t ah[2][4], al[2][4], bh[4][4], bl[4][4];
#pragma unroll
            for (int mt = 0; mt < 2; mt++) {
                uint32_t ar = (mb + mt * 16 + a_row) * ROWB + kbyte + a_kh;
                ldmx4(ah[mt], sAh + ar);
                ldmx4(al[mt], sAl + ar);
            }
#pragma unroll
            for (int q = 0; q < 4; q++) {
                uint32_t br = (nb + q * 16 + b_row) * ROWB + kbyte + b_kh;
                ldmx4(bh[q], sBh + br);
                ldmx4(bl[q], sBl + br);
            }
#pragma unroll
            for (int mt = 0; mt < 2; mt++) {
#pragma unroll
                for (int nf = 0; nf < 8; nf++) {
                    uint32_t h0 = bh[nf >> 1][(nf & 1) * 2], h1 = bh[nf >> 1][(nf & 1) * 2 + 1];
                    uint32_t l0 = bl[nf >> 1][(nf & 1) * 2], l1 = bl[nf >> 1][(nf & 1) * 2 + 1];
                    mma16816(acc[mt][nf], ah[mt], h0, h1);
                    mma16816(acc[mt][nf], ah[mt], l0, l1);
                    mma16816(acc[mt][nf], al[mt], h0, h1);
                }
            }
        }
        __syncthreads();   // finished reading tiles before next kt overwrites
    }

    // epilogue: + b_lin, leaky, write out
    const int rbase = m0 + mb + (lane >> 2);
    const int cbase = nb + 2 * (lane & 3);
#pragma unroll
    for (int mt = 0; mt < 2; mt++) {
#pragma unroll
        for (int pair = 0; pair < 2; pair++) {
            int m = rbase + mt * 16 + pair * 8;
            if (m >= N_NODESC) continue;
            float* cp = out + (size_t)m * DIMC;
#pragma unroll
            for (int nf = 0; nf < 8; nf++) {
                float2 bl2 = *(const float2*)&b_lin[cbase + nf * 8];
                float v0 = acc[mt][nf][pair * 2 + 0] + bl2.x;
                float v1 = acc[mt][nf][pair * 2 + 1] + bl2.y;
                v0 = v0 > 0.f ? v0 : 0.01f * v0;
                v1 = v1 > 0.f ? v1 : 0.01f * v1;
                *(float2*)(cp + cbase + nf * 8) = make_float2(v0, v1);
            }
        }
    }
}

// ---------------- launch ----------------
extern "C" void kernel_launch(void* const* d_in, const int* in_sizes, int n_in,
                              void* d_out, int out_size) {
    const float* h      = (const float*)d_in[0];
    const float* rel    = (const float*)d_in[1];
    const float* relatt = (const float*)d_in[2];
    const float* W_a    = (const float*)d_in[3];
    const float* b_a    = (const float*)d_in[4];
    const float* W_lin  = (const float*)d_in[5];
    const float* b_lin  = (const float*)d_in[6];
    const int* src   = (const int*)d_in[7];
    const int* dst   = (const int*)d_in[8];
    const int* etype = (const int*)d_in[9];
    float* out = (float*)d_out;

    cudaFuncSetAttribute(k_tgemm2, cudaFuncAttributeMaxDynamicSharedMemorySize, SM_GEMM2);
    cudaFuncSetAttribute(k_tgemm3, cudaFuncAttributeMaxDynamicSharedMemorySize, SM_GEMM3);
    cudaFuncSetAttribute(k_final,  cudaFuncAttributeMaxDynamicSharedMemorySize, SM_GEMM3);

    // prep (+ cnt zeroing)
    k_cvtA<<<(N_NODESC * DIMC + 255) / 256, 256>>>(h);
    k_prepB<<<(TCNT * DIMC * DIMC + 255) / 256, 256>>>(rel, W_a, W_lin);

    // CSR build
    k_hist<<<(N_EDGESC + 1023) / 1024, 1024>>>(dst);
    k_scan1<<<SCANBLKS, 512>>>();
    k_scan2<<<1, 32>>>();
    k_scan3<<<SCANBLKS, 512>>>();
    k_scatter<<<(N_EDGESC + 1023) / 1024, 1024>>>(src, dst, etype);

    // GEMMs
    k_tgemm3<<<MBLKS, 256, SM_GEMM3>>>();
    dim3 gg(STRIPS2, 16);
    k_tgemm2<<<gg, 256, SM_GEMM2>>>();

    // message passing (atomic-free, 4-edge ILP, bf16-split h_N)
    k_msg2<<<(N_NODESC + 7) / 8, 256>>>(h, relatt, b_a);

    // final HMMA GEMM
    k_final<<<MBLKS, 256, SM_GEMM3>>>(out, b_lin);
}

// round 13
// speedup vs baseline: 2.3168x; 1.0017x over previous
#include <cuda_runtime.h>
#include <cuda_bf16.h>
#include <cstdint>

#define N_NODESC 50000
#define N_EDGESC 500000
#define DIMC     128
#define A_DIMC   64
#define NPADC    50048      // 391 * 128
#define MBLKS    391
#define STRIPS2  37
#define TCNT     17
#define SCANBLKS 98         // 98 * 512 >= 50000

// ---------------- device scratch ----------------
__device__ __align__(16) __nv_bfloat16 g_hh[(size_t)NPADC * DIMC];
__device__ __align__(16) __nv_bfloat16 g_hl[(size_t)NPADC * DIMC];
__device__ __align__(16) __nv_bfloat16 g_Bh[(size_t)TCNT * DIMC * DIMC]; // [t][n][k]
__device__ __align__(16) __nv_bfloat16 g_Bl[(size_t)TCNT * DIMC * DIMC];
__device__ __align__(16) __nv_bfloat16 g_projb[(size_t)16 * N_NODESC * DIMC]; // 204.8MB
__device__ __align__(16) float g_q[(size_t)N_NODESC * DIMC];
__device__ __align__(16) __nv_bfloat16 g_hNh[(size_t)NPADC * DIMC];  // h_N hi (bf16)
__device__ __align__(16) __nv_bfloat16 g_hNl[(size_t)NPADC * DIMC];  // h_N lo (bf16)
__device__ __align__(16) __nv_bfloat16 g_Wlh[2 * DIMC * DIMC];       // [kt][n][k]
__device__ __align__(16) __nv_bfloat16 g_Wll[2 * DIMC * DIMC];
// CSR scratch
__device__ int g_cnt[N_NODESC];
__device__ int g_rowpre[N_NODESC];
__device__ int g_rowptr[N_NODESC + 1];
__device__ int g_bsum[SCANBLKS];
__device__ int g_epack[N_EDGESC];   // (etype<<16) | src

// ---------------- ptx helpers ----------------
__device__ __forceinline__ uint32_t smem_u32(const void* p) {
    uint32_t a;
    asm("{ .reg .u64 t; cvta.to.shared.u64 t, %1; cvt.u32.u64 %0, t; }" : "=r"(a) : "l"(p));
    return a;
}
__device__ __forceinline__ void cp16(uint32_t dst, const void* src) {
    asm volatile("cp.async.cg.shared.global [%0], [%1], 16;" :: "r"(dst), "l"(src));
}
#define CP_COMMIT() asm volatile("cp.async.commit_group;" ::: "memory")
#define CP_WAIT(n)  asm volatile("cp.async.wait_group %0;" :: "n"(n) : "memory")

__device__ __forceinline__ void ldmx4(uint32_t* r, uint32_t addr) {
    asm volatile("ldmatrix.sync.aligned.m8n8.x4.shared.b16 {%0,%1,%2,%3}, [%4];"
                 : "=r"(r[0]), "=r"(r[1]), "=r"(r[2]), "=r"(r[3]) : "r"(addr));
}
__device__ __forceinline__ void mma16816(float* d, const uint32_t* a, uint32_t b0, uint32_t b1) {
    asm volatile("mma.sync.aligned.m16n8k16.row.col.f32.bf16.bf16.f32 "
                 "{%0,%1,%2,%3}, {%4,%5,%6,%7}, {%8,%9}, {%0,%1,%2,%3};"
                 : "+f"(d[0]), "+f"(d[1]), "+f"(d[2]), "+f"(d[3])
                 : "r"(a[0]), "r"(a[1]), "r"(a[2]), "r"(a[3]), "r"(b0), "r"(b1));
}

__device__ __forceinline__ float fsig(float x) {          // fast sigmoid
    return __frcp_rn(1.0f + __expf(-x));
}

// ---------------- prep kernels ----------------
__global__ void k_cvtA(const float* __restrict__ h) {
    int i = blockIdx.x * 256 + threadIdx.x;
    if (i < N_NODESC * DIMC) {
        float v = h[i];
        __nv_bfloat16 hi = __float2bfloat16(v);
        g_hh[i] = hi;
        g_hl[i] = __float2bfloat16(v - __bfloat162float(hi));
    }
    if (i < N_NODESC) g_cnt[i] = 0;
}

__global__ void k_prepB(const float* __restrict__ rel, const float* __restrict__ W_a,
                        const float* __restrict__ W_lin) {
    int i = blockIdx.x * 256 + threadIdx.x;
    if (i < TCNT * DIMC * DIMC) {
        int t = i >> 14, n = (i >> 7) & 127, k = i & 127;
        float v;
        if (t < 16) {
            int side = t >> 3, r = t & 7;
            v = rel[((size_t)(r * 256 + side * 128 + k)) * 128 + n];
        } else {
            v = (n < A_DIMC) ? W_a[n * 256 + k] : W_a[(n - A_DIMC) * 256 + DIMC + k];
        }
        __nv_bfloat16 hi = __float2bfloat16(v);
        g_Bh[i] = hi;
        g_Bl[i] = __float2bfloat16(v - __bfloat162float(hi));
    }
    if (i < 2 * DIMC * DIMC) {
        int kt = i >> 14, n = (i >> 7) & 127, k = i & 127;
        float v = W_lin[n * 256 + kt * 128 + k];
        __nv_bfloat16 hi = __float2bfloat16(v);
        g_Wlh[i] = hi;
        g_Wll[i] = __float2bfloat16(v - __bfloat162float(hi));
    }
}

// ---------------- CSR build ----------------
__global__ void k_hist(const int* __restrict__ dst) {
    int i = blockIdx.x * 1024 + threadIdx.x;
    if (i < N_EDGESC) atomicAdd(&g_cnt[dst[i]], 1);
}
__global__ void k_scan1() {
    __shared__ int sh[512];
    int i = blockIdx.x * 512 + threadIdx.x;
    int v = (i < N_NODESC) ? g_cnt[i] : 0;
    sh[threadIdx.x] = v;
    __syncthreads();
    for (int off = 1; off < 512; off <<= 1) {
        int t = (threadIdx.x >= off) ? sh[threadIdx.x - off] : 0;
        __syncthreads();
        sh[threadIdx.x] += t;
        __syncthreads();
    }
    if (i < N_NODESC) g_rowpre[i] = sh[threadIdx.x] - v;
    if (threadIdx.x == 511) g_bsum[blockIdx.x] = sh[511];
}
__global__ void k_scan2() {
    if (threadIdx.x == 0) {
        int acc = 0;
        for (int b = 0; b < SCANBLKS; b++) { int v = g_bsum[b]; g_bsum[b] = acc; acc += v; }
        g_rowptr[N_NODESC] = N_EDGESC;
    }
}
__global__ void k_scan3() {
    int i = blockIdx.x * 512 + threadIdx.x;
    if (i < N_NODESC) {
        g_rowptr[i] = g_rowpre[i] + g_bsum[i >> 9];
        g_cnt[i] = 0;
    }
}
__global__ void k_scatter(const int* __restrict__ src, const int* __restrict__ dst,
                          const int* __restrict__ etype) {
    int i = blockIdx.x * 1024 + threadIdx.x;
    if (i < N_EDGESC) {
        int d = dst[i];
        int pos = g_rowptr[d] + atomicAdd(&g_cnt[d], 1);
        g_epack[pos] = (etype[i] << 16) | src[i];
    }
}

#define ROWB 272
#define TILEB 34816
#define SM_GEMM2 (4 * TILEB)   // B(t), B(t+8), A0, A1
#define SM_GEMM3 (4 * TILEB)

// ---------------- gate GEMMs: dual-t per CTA, plain bf16, persistent strips ----------------
// grid (STRIPS2, 8). CTA holds B[t] and B[t+8] resident; each A tile feeds both.
__global__ void __launch_bounds__(256, 1) k_tgemm2() {
    extern __shared__ char smem[];
    const uint32_t sb  = smem_u32(smem);
    const uint32_t sB0  = sb;
    const uint32_t sB1  = sb + TILEB;
    const uint32_t sAh0 = sb + 2 * TILEB;
    const uint32_t sAh1 = sb + 3 * TILEB;

    const int tid = threadIdx.x;
    const int lane = tid & 31;
    const int wid = tid >> 5;
    const int t0 = blockIdx.y;
    const int t1 = t0 + 8;
    const int strip = blockIdx.x;
    const int n_m = (MBLKS - strip + STRIPS2 - 1) / STRIPS2;

    {
        const __nv_bfloat16* B0 = g_Bh + (size_t)t0 * DIMC * DIMC;
        const __nv_bfloat16* B1 = g_Bh + (size_t)t1 * DIMC * DIMC;
        const size_t mbase = (size_t)strip * 128 * DIMC;
        for (int idx = tid; idx < 2048; idx += 256) {
            int row = idx >> 4, c = idx & 15;
            uint32_t doff = row * ROWB + c * 16;
            size_t soff = (size_t)row * DIMC + c * 8;
            cp16(sB0 + doff, B0 + soff);
            cp16(sB1 + doff, B1 + soff);
            cp16(sAh0 + doff, g_hh + mbase + soff);
        }
    }
    CP_COMMIT();

    const int mb = (wid & 3) * 32;
    const int nb = (wid >> 2) * 64;
    const int a_row = (lane & 7) + 8 * ((lane >> 3) & 1);
    const int a_kh  = (lane >> 4) * 16;
    const int b_row = (lane & 7) + 8 * (lane >> 4);
    const int b_kh  = ((lane >> 3) & 1) * 16;
    const int rb_local = mb + (lane >> 2);
    const int cbase = nb + 2 * (lane & 3);

    for (int it = 0; it < n_m; it++) {
        const uint32_t sAh = (it & 1) ? sAh1 : sAh0;

        if (it + 1 < n_m) {
            const uint32_t dAh = (it & 1) ? sAh0 : sAh1;
            const size_t mbase = (size_t)(strip + (it + 1) * STRIPS2) * 128 * DIMC;
            for (int idx = tid; idx < 2048; idx += 256) {
                int row = idx >> 4, c = idx & 15;
                cp16(dAh + row * ROWB + c * 16, g_hh + mbase + (size_t)row * DIMC + c * 8);
            }
            CP_COMMIT();
            CP_WAIT(1);
        } else {
            CP_WAIT(0);
        }
        __syncthreads();

        const int m0 = (strip + it * STRIPS2) * 128;

#pragma unroll
        for (int tt = 0; tt < 2; tt++) {
            const uint32_t sB = tt ? sB1 : sB0;
            const int t = tt ? t1 : t0;

            float acc[2][8][4];
#pragma unroll
            for (int i = 0; i < 2; i++)
#pragma unroll
                for (int j = 0; j < 8; j++)
#pragma unroll
                    for (int v = 0; v < 4; v++) acc[i][j][v] = 0.0f;

#pragma unroll
            for (int k0 = 0; k0 < 8; k0++) {
                const uint32_t kbyte = k0 * 32;
                uint32_t ah[2][4], bh[4][4];
#pragma unroll
                for (int mt = 0; mt < 2; mt++)
                    ldmx4(ah[mt], sAh + (mb + mt * 16 + a_row) * ROWB + kbyte + a_kh);
#pragma unroll
                for (int q = 0; q < 4; q++)
                    ldmx4(bh[q], sB + (nb + q * 16 + b_row) * ROWB + kbyte + b_kh);
#pragma unroll
                for (int mt = 0; mt < 2; mt++) {
#pragma unroll
                    for (int nf = 0; nf < 8; nf++) {
                        mma16816(acc[mt][nf], ah[mt],
                                 bh[nf >> 1][(nf & 1) * 2], bh[nf >> 1][(nf & 1) * 2 + 1]);
                    }
                }
            }

#pragma unroll
            for (int mt = 0; mt < 2; mt++) {
#pragma unroll
                for (int pair = 0; pair < 2; pair++) {
                    int m = m0 + rb_local + mt * 16 + pair * 8;
                    if (m >= N_NODESC) continue;
                    __nv_bfloat16* dp = g_projb + ((size_t)t * N_NODESC + m) * DIMC;
#pragma unroll
                    for (int nf = 0; nf < 8; nf++) {
                        float v0 = acc[mt][nf][pair * 2 + 0];
                        float v1 = acc[mt][nf][pair * 2 + 1];
                        uint32_t pk;
                        asm("cvt.rn.satfinite.bf16x2.f32 %0, %1, %2;" : "=r"(pk) : "f"(v1), "f"(v0));
                        *(uint32_t*)(dp + cbase + nf * 8) = pk;
                    }
                }
            }
        }
        __syncthreads();   // all reads of this A buffer done before refill
    }
}

// ---------------- attention GEMM (t=16), 3-term ----------------
__global__ void __launch_bounds__(256, 1) k_tgemm3() {
    extern __shared__ char smem[];
    const uint32_t sb = smem_u32(smem);
    const uint32_t sAh = sb, sAl = sb + TILEB, sBh = sb + 2 * TILEB, sBl = sb + 3 * TILEB;

    const int tid = threadIdx.x;
    const int lane = tid & 31;
    const int wid = tid >> 5;
    const int m0 = blockIdx.x * 128;

    {
        const __nv_bfloat16* Bh = g_Bh + (size_t)16 * DIMC * DIMC;
        const __nv_bfloat16* Bl = g_Bl + (size_t)16 * DIMC * DIMC;
        const size_t mbase = (size_t)m0 * DIMC;
        for (int idx = tid; idx < 2048; idx += 256) {
            int row = idx >> 4, c = idx & 15;
            uint32_t doff = row * ROWB + c * 16;
            size_t soff = (size_t)row * DIMC + c * 8;
            cp16(sAh + doff, g_hh + mbase + soff);
            cp16(sAl + doff, g_hl + mbase + soff);
            cp16(sBh + doff, Bh + soff);
            cp16(sBl + doff, Bl + soff);
        }
    }
    CP_COMMIT();
    CP_WAIT(0);
    __syncthreads();

    const int mb = (wid & 3) * 32;
    const int nb = (wid >> 2) * 64;
    const int a_row = (lane & 7) + 8 * ((lane >> 3) & 1);
    const int a_kh  = (lane >> 4) * 16;
    const int b_row = (lane & 7) + 8 * (lane >> 4);
    const int b_kh  = ((lane >> 3) & 1) * 16;

    float acc[2][8][4];
#pragma unroll
    for (int i = 0; i < 2; i++)
#pragma unroll
        for (int j = 0; j < 8; j++)
#pragma unroll
            for (int v = 0; v < 4; v++) acc[i][j][v] = 0.0f;

#pragma unroll
    for (int k0 = 0; k0 < 8; k0++) {
        const uint32_t kbyte = k0 * 32;
        uint32_t ah[2][4], al[2][4], bh[4][4], bl[4][4];
#pragma unroll
        for (int mt = 0; mt < 2; mt++) {
            uint32_t ar = (mb + mt * 16 + a_row) * ROWB + kbyte + a_kh;
            ldmx4(ah[mt], sAh + ar);
            ldmx4(al[mt], sAl + ar);
        }
#pragma unroll
        for (int q = 0; q < 4; q++) {
            uint32_t br = (nb + q * 16 + b_row) * ROWB + kbyte + b_kh;
            ldmx4(bh[q], sBh + br);
            ldmx4(bl[q], sBl + br);
        }
#pragma unroll
        for (int mt = 0; mt < 2; mt++) {
#pragma unroll
            for (int nf = 0; nf < 8; nf++) {
                uint32_t h0 = bh[nf >> 1][(nf & 1) * 2], h1 = bh[nf >> 1][(nf & 1) * 2 + 1];
                uint32_t l0 = bl[nf >> 1][(nf & 1) * 2], l1 = bl[nf >> 1][(nf & 1) * 2 + 1];
                mma16816(acc[mt][nf], ah[mt], h0, h1);
                mma16816(acc[mt][nf], ah[mt], l0, l1);
                mma16816(acc[mt][nf], al[mt], h0, h1);
            }
        }
    }

    const int rbase = m0 + mb + (lane >> 2);
    const int cbase = nb + 2 * (lane & 3);
#pragma unroll
    for (int mt = 0; mt < 2; mt++) {
#pragma unroll
        for (int pair = 0; pair < 2; pair++) {
            int m = rbase + mt * 16 + pair * 8;
            if (m >= N_NODESC) continue;
            float* dp = g_q + (size_t)m * DIMC;
#pragma unroll
            for (int nf = 0; nf < 8; nf++)
                *(float2*)(dp + cbase + nf * 8) =
                    make_float2(acc[mt][nf][pair * 2], acc[mt][nf][pair * 2 + 1]);
        }
    }
}

// ---------------- warp-per-node message kernel: 4-edge ILP, bf16-split output ----------------
__global__ void __launch_bounds__(256) k_msg2(const float* __restrict__ h,
                                              const float* __restrict__ rel_att,
                                              const float* __restrict__ b_a) {
    const int lane = threadIdx.x & 31;
    const int n = blockIdx.x * 8 + (threadIdx.x >> 5);
    if (n >= N_NODESC) return;
    const int beg = g_rowptr[n];
    const int end = g_rowptr[n + 1];

    float2 qd = *(const float2*)&g_q[(size_t)n * DIMC + lane * 2];
    float2 ba = *(const float2*)&b_a[lane * 2];
    float2 ra = *(const float2*)&rel_att[lane * 2];
    const float qdx = qd.x + ba.x, qdy = qd.y + ba.y;
    const __nv_bfloat16* pdbase = g_projb + (size_t)n * DIMC + lane * 4;

    float a0 = 0.f, a1 = 0.f, a2 = 0.f, a3 = 0.f, den = 0.f;

    int e = beg;
    for (; e + 4 <= end; e += 4) {
        int s[4], r[4];
        float2 qs[4];
        uint2 pdw[4], psw[4];
        float4 hs[4];
#pragma unroll
        for (int j = 0; j < 4; j++) {
            int pack = __ldg(&g_epack[e + j]);
            s[j] = pack & 0xFFFF;
            r[j] = pack >> 16;
        }
#pragma unroll
        for (int j = 0; j < 4; j++) {
            qs[j]  = *(const float2*)&g_q[(size_t)s[j] * DIMC + A_DIMC + lane * 2];
            pdw[j] = *(const uint2*)(pdbase + (size_t)r[j] * N_NODESC * DIMC);
            psw[j] = *(const uint2*)(g_projb + ((size_t)(8 + r[j]) * N_NODESC + s[j]) * DIMC + lane * 4);
            hs[j]  = *(const float4*)&h[(size_t)s[j] * DIMC + lane * 4];
        }
        float p[4];
#pragma unroll
        for (int j = 0; j < 4; j++) {
            float u = qdx + qs[j].x, v = qdy + qs[j].y;
            u = fmaxf(u, 0.01f * u);
            v = fmaxf(v, 0.01f * v);
            p[j] = ra.x * u + ra.y * v;
        }
#pragma unroll
        for (int o = 16; o > 0; o >>= 1) {
#pragma unroll
            for (int j = 0; j < 4; j++)
                p[j] += __shfl_xor_sync(0xffffffffu, p[j], o);
        }
#pragma unroll
        for (int j = 0; j < 4; j++) {
            float ex = __expf(p[j]);
            float2 pd0 = __bfloat1622float2(*(__nv_bfloat162*)&pdw[j].x);
            float2 pd1 = __bfloat1622float2(*(__nv_bfloat162*)&pdw[j].y);
            float2 ps0 = __bfloat1622float2(*(__nv_bfloat162*)&psw[j].x);
            float2 ps1 = __bfloat1622float2(*(__nv_bfloat162*)&psw[j].y);
            a0 += hs[j].x * ex * fsig(pd0.x + ps0.x);
            a1 += hs[j].y * ex * fsig(pd0.y + ps0.y);
            a2 += hs[j].z * ex * fsig(pd1.x + ps1.x);
            a3 += hs[j].w * ex * fsig(pd1.y + ps1.y);
            den += ex;
        }
    }
    for (; e < end; e++) {
        int pack = __ldg(&g_epack[e]);
        int s0 = pack & 0xFFFF, r0 = pack >> 16;
        float2 qs0 = *(const float2*)&g_q[(size_t)s0 * DIMC + A_DIMC + lane * 2];
        uint2 pdw0 = *(const uint2*)(pdbase + (size_t)r0 * N_NODESC * DIMC);
        uint2 psw0 = *(const uint2*)(g_projb + ((size_t)(8 + r0) * N_NODESC + s0) * DIMC + lane * 4);
        float4 hs0 = *(const float4*)&h[(size_t)s0 * DIMC + lane * 4];
        float u0 = qdx + qs0.x, v0 = qdy + qs0.y;
        u0 = fmaxf(u0, 0.01f * u0);
        v0 = fmaxf(v0, 0.01f * v0);
        float p0 = ra.x * u0 + ra.y * v0;
#pragma unroll
        for (int o = 16; o > 0; o >>= 1) p0 += __shfl_xor_sync(0xffffffffu, p0, o);
        float ex0 = __expf(p0);
        float2 pd00 = __bfloat1622float2(*(__nv_bfloat162*)&pdw0.x);
        float2 pd01 = __bfloat1622float2(*(__nv_bfloat162*)&pdw0.y);
        float2 ps00 = __bfloat1622float2(*(__nv_bfloat162*)&psw0.x);
        float2 ps01 = __bfloat1622float2(*(__nv_bfloat162*)&psw0.y);
        a0 += hs0.x * ex0 * fsig(pd00.x + ps00.x);
        a1 += hs0.y * ex0 * fsig(pd00.y + ps00.y);
        a2 += hs0.z * ex0 * fsig(pd01.x + ps01.x);
        a3 += hs0.w * ex0 * fsig(pd01.y + ps01.y);
        den += ex0;
    }

    float inv = (den > 0.f) ? __frcp_rn(den) : 0.f;
    float v0 = a0 * inv, v1 = a1 * inv, v2 = a2 * inv, v3 = a3 * inv;

    // split-bf16 store of h_N
    __nv_bfloat16 b0 = __float2bfloat16(v0);
    __nv_bfloat16 b1 = __float2bfloat16(v1);
    __nv_bfloat16 b2 = __float2bfloat16(v2);
    __nv_bfloat16 b3 = __float2bfloat16(v3);
    __nv_bfloat162* ph = (__nv_bfloat162*)&g_hNh[(size_t)n * DIMC + lane * 4];
    ph[0] = __nv_bfloat162(b0, b1);
    ph[1] = __nv_bfloat162(b2, b3);
    __nv_bfloat162* pl = (__nv_bfloat162*)&g_hNl[(size_t)n * DIMC + lane * 4];
    pl[0] = __floats2bfloat162_rn(v0 - __bfloat162float(b0), v1 - __bfloat162float(b1));
    pl[1] = __floats2bfloat162_rn(v2 - __bfloat162float(b2), v3 - __bfloat162float(b3));
}

// ---------------- final GEMM on HMMA: out = leaky([h ; h_N] @ W_lin^T + b_lin) ----------------
__global__ void __launch_bounds__(256, 1) k_final(float* __restrict__ out,
                                                  const float* __restrict__ b_lin) {
    extern __shared__ char smem[];
    const uint32_t sb = smem_u32(smem);
    const uint32_t sAh = sb, sAl = sb + TILEB, sBh = sb + 2 * TILEB, sBl = sb + 3 * TILEB;

    const int tid = threadIdx.x;
    const int lane = tid & 31;
    const int wid = tid >> 5;
    const int m0 = blockIdx.x * 128;

    const int mb = (wid & 3) * 32;
    const int nb = (wid >> 2) * 64;
    const int a_row = (lane & 7) + 8 * ((lane >> 3) & 1);
    const int a_kh  = (lane >> 4) * 16;
    const int b_row = (lane & 7) + 8 * (lane >> 4);
    const int b_kh  = ((lane >> 3) & 1) * 16;

    float acc[2][8][4];
#pragma unroll
    for (int i = 0; i < 2; i++)
#pragma unroll
        for (int j = 0; j < 8; j++)
#pragma unroll
            for (int v = 0; v < 4; v++) acc[i][j][v] = 0.0f;

    for (int kt = 0; kt < 2; kt++) {
        const __nv_bfloat16* Ah = (kt ? g_hNh : g_hh) + (size_t)m0 * DIMC;
        const __nv_bfloat16* Al = (kt ? g_hNl : g_hl) + (size_t)m0 * DIMC;
        const __nv_bfloat16* Bh = g_Wlh + kt * DIMC * DIMC;
        const __nv_bfloat16* Bl = g_Wll + kt * DIMC * DIMC;
        for (int idx = tid; idx < 2048; idx += 256) {
            int row = idx >> 4, c = idx & 15;
            uint32_t doff = row * ROWB + c * 16;
            size_t soff = (size_t)row * DIMC + c * 8;
            cp16(sAh + doff, Ah + soff);
            cp16(sAl + doff, Al + soff);
            cp16(sBh + doff, Bh + soff);
            cp16(sBl + doff, Bl + soff);
        }
        CP_COMMIT();
        CP_WAIT(0);
        __syncthreads();

#pragma unroll
        for (int k0 = 0; k0 < 8; k0++) {
            const uint32_t kbyte = k0 * 32;
            uint32_t ah[2][4], al[2][4], bh[4][4], bl[4][4];
#pragma unroll
            for (int mt = 0; mt < 2; mt++) {
                uint32_t ar = (mb + mt * 16 + a_row) * ROWB + kbyte + a_kh;
                ldmx4(ah[mt], sAh + ar);
                ldmx4(al[mt], sAl + ar);
            }
#pragma unroll
            for (int q = 0; q < 4; q++) {
                uint32_t br = (nb + q * 16 + b_row) * ROWB + kbyte + b_kh;
                ldmx4(bh[q], sBh + br);
                ldmx4(bl[q], sBl + br);
            }
#pragma unroll
            for (int mt = 0; mt < 2; mt++) {
#pragma unroll
                for (int nf = 0; nf < 8; nf++) {
                    uint32_t h0 = bh[nf >> 1][(nf & 1) * 2], h1 = bh[nf >> 1][(nf & 1) * 2 + 1];
                    uint32_t l0 = bl[nf >> 1][(nf & 1) * 2], l1 = bl[nf >> 1][(nf & 1) * 2 + 1];
                    mma16816(acc[mt][nf], ah[mt], h0, h1);
                    mma16816(acc[mt][nf], ah[mt], l0, l1);
                    mma16816(acc[mt][nf], al[mt], h0, h1);
                }
            }
        }
        __syncthreads();
    }

    const int rbase = m0 + mb + (lane >> 2);
    const int cbase = nb + 2 * (lane & 3);
#pragma unroll
    for (int mt = 0; mt < 2; mt++) {
#pragma unroll
        for (int pair = 0; pair < 2; pair++) {
            int m = rbase + mt * 16 + pair * 8;
            if (m >= N_NODESC) continue;
            float* cp = out + (size_t)m * DIMC;
#pragma unroll
            for (int nf = 0; nf < 8; nf++) {
                float2 bl2 = *(const float2*)&b_lin[cbase + nf * 8];
                float v0 = acc[mt][nf][pair * 2 + 0] + bl2.x;
                float v1 = acc[mt][nf][pair * 2 + 1] + bl2.y;
                v0 = v0 > 0.f ? v0 : 0.01f * v0;
                v1 = v1 > 0.f ? v1 : 0.01f * v1;
                *(float2*)(cp + cbase + nf * 8) = make_float2(v0, v1);
            }
        }
    }
}

// ---------------- launch ----------------
extern "C" void kernel_launch(void* const* d_in, const int* in_sizes, int n_in,
                              void* d_out, int out_size) {
    const float* h      = (const float*)d_in[0];
    const float* rel    = (const float*)d_in[1];
    const float* relatt = (const float*)d_in[2];
    const float* W_a    = (const float*)d_in[3];
    const float* b_a    = (const float*)d_in[4];
    const float* W_lin  = (const float*)d_in[5];
    const float* b_lin  = (const float*)d_in[6];
    const int* src   = (const int*)d_in[7];
    const int* dst   = (const int*)d_in[8];
    const int* etype = (const int*)d_in[9];
    float* out = (float*)d_out;

    cudaFuncSetAttribute(k_tgemm2, cudaFuncAttributeMaxDynamicSharedMemorySize, SM_GEMM2);
    cudaFuncSetAttribute(k_tgemm3, cudaFuncAttributeMaxDynamicSharedMemorySize, SM_GEMM3);
    cudaFuncSetAttribute(k_final,  cudaFuncAttributeMaxDynamicSharedMemorySize, SM_GEMM3);

    // prep (+ cnt zeroing)
    k_cvtA<<<(N_NODESC * DIMC + 255) / 256, 256>>>(h);
    k_prepB<<<(TCNT * DIMC * DIMC + 255) / 256, 256>>>(rel, W_a, W_lin);

    // CSR build
    k_hist<<<(N_EDGESC + 1023) / 1024, 1024>>>(dst);
    k_scan1<<<SCANBLKS, 512>>>();
    k_scan2<<<1, 32>>>();
    k_scan3<<<SCANBLKS, 512>>>();
    k_scatter<<<(N_EDGESC + 1023) / 1024, 1024>>>(src, dst, etype);

    // GEMMs
    k_tgemm3<<<MBLKS, 256, SM_GEMM3>>>();
    dim3 gg(STRIPS2, 8);
    k_tgemm2<<<gg, 256, SM_GEMM2>>>();

    // message passing (atomic-free, 4-edge ILP, bf16-split h_N)
    k_msg2<<<(N_NODESC + 7) / 8, 256>>>(h, relatt, b_a);

    // final HMMA GEMM
    k_final<<<MBLKS, 256, SM_GEMM3>>>(out, b_lin);
}

// round 15
// speedup vs baseline: 2.4553x; 1.0598x over previous
#include <cuda_runtime.h>
#include <cuda_bf16.h>
#include <cstdint>

#define N_NODESC 50000
#define N_EDGESC 500000
#define DIMC     128
#define A_DIMC   64
#define NPADC    50048      // 391 * 128
#define MBLKS    391
#define STRIPS2  37
#define TCNT     17
#define SCANBLKS 98         // 98 * 512 >= 50000

// ---------------- device scratch ----------------
__device__ __align__(16) __nv_bfloat16 g_hh[(size_t)NPADC * DIMC];
__device__ __align__(16) __nv_bfloat16 g_hl[(size_t)NPADC * DIMC];
__device__ __align__(16) __nv_bfloat16 g_Bh[(size_t)TCNT * DIMC * DIMC]; // [t][n][k]
__device__ __align__(16) __nv_bfloat16 g_Bl[(size_t)TCNT * DIMC * DIMC];
__device__ __align__(16) __nv_bfloat16 g_projb[(size_t)16 * N_NODESC * DIMC]; // 204.8MB
__device__ __align__(16) float g_q[(size_t)N_NODESC * DIMC];
__device__ __align__(16) __nv_bfloat16 g_hNh[(size_t)NPADC * DIMC];  // h_N hi (bf16)
__device__ __align__(16) __nv_bfloat16 g_hNl[(size_t)NPADC * DIMC];  // h_N lo (bf16)
__device__ __align__(16) __nv_bfloat16 g_Wlh[2 * DIMC * DIMC];       // [kt][n][k]
__device__ __align__(16) __nv_bfloat16 g_Wll[2 * DIMC * DIMC];
// CSR scratch
__device__ int g_cnt[N_NODESC];
__device__ int g_rowpre[N_NODESC];
__device__ int g_rowptr[N_NODESC + 1];
__device__ int g_bsum[SCANBLKS];
__device__ int g_epack[N_EDGESC];   // (etype<<16) | src

// ---------------- ptx helpers ----------------
__device__ __forceinline__ uint32_t smem_u32(const void* p) {
    uint32_t a;
    asm("{ .reg .u64 t; cvta.to.shared.u64 t, %1; cvt.u32.u64 %0, t; }" : "=r"(a) : "l"(p));
    return a;
}
__device__ __forceinline__ void cp16(uint32_t dst, const void* src) {
    asm volatile("cp.async.cg.shared.global [%0], [%1], 16;" :: "r"(dst), "l"(src));
}
#define CP_COMMIT() asm volatile("cp.async.commit_group;" ::: "memory")
#define CP_WAIT(n)  asm volatile("cp.async.wait_group %0;" :: "n"(n) : "memory")

__device__ __forceinline__ void ldmx4(uint32_t* r, uint32_t addr) {
    asm volatile("ldmatrix.sync.aligned.m8n8.x4.shared.b16 {%0,%1,%2,%3}, [%4];"
                 : "=r"(r[0]), "=r"(r[1]), "=r"(r[2]), "=r"(r[3]) : "r"(addr));
}
__device__ __forceinline__ void mma16816(float* d, const uint32_t* a, uint32_t b0, uint32_t b1) {
    asm volatile("mma.sync.aligned.m16n8k16.row.col.f32.bf16.bf16.f32 "
                 "{%0,%1,%2,%3}, {%4,%5,%6,%7}, {%8,%9}, {%0,%1,%2,%3};"
                 : "+f"(d[0]), "+f"(d[1]), "+f"(d[2]), "+f"(d[3])
                 : "r"(a[0]), "r"(a[1]), "r"(a[2]), "r"(a[3]), "r"(b0), "r"(b1));
}

__device__ __forceinline__ float fsig(float x) {          // fast sigmoid
    return __frcp_rn(1.0f + __expf(-x));
}

// ---------------- prep kernels ----------------
__global__ void k_cvtA(const float* __restrict__ h) {
    int i = blockIdx.x * 256 + threadIdx.x;
    if (i < N_NODESC * DIMC) {
        float v = h[i];
        __nv_bfloat16 hi = __float2bfloat16(v);
        g_hh[i] = hi;
        g_hl[i] = __float2bfloat16(v - __bfloat162float(hi));
    }
}

__global__ void k_prepB(const float* __restrict__ rel, const float* __restrict__ W_a,
                        const float* __restrict__ W_lin) {
    int i = blockIdx.x * 256 + threadIdx.x;
    if (i < TCNT * DIMC * DIMC) {
        int t = i >> 14, n = (i >> 7) & 127, k = i & 127;
        float v;
        if (t < 16) {
            int side = t >> 3, r = t & 7;
            v = rel[((size_t)(r * 256 + side * 128 + k)) * 128 + n];
        } else {
            v = (n < A_DIMC) ? W_a[n * 256 + k] : W_a[(n - A_DIMC) * 256 + DIMC + k];
        }
        __nv_bfloat16 hi = __float2bfloat16(v);
        g_Bh[i] = hi;
        g_Bl[i] = __float2bfloat16(v - __bfloat162float(hi));
    }
    if (i < 2 * DIMC * DIMC) {
        int kt = i >> 14, n = (i >> 7) & 127, k = i & 127;
        float v = W_lin[n * 256 + kt * 128 + k];
        __nv_bfloat16 hi = __float2bfloat16(v);
        g_Wlh[i] = hi;
        g_Wll[i] = __float2bfloat16(v - __bfloat162float(hi));
    }
}

// ---------------- CSR build (side stream) ----------------
__global__ void k_csr0() {
    int i = blockIdx.x * 1024 + threadIdx.x;
    if (i < N_NODESC) g_cnt[i] = 0;
}
__global__ void k_hist(const int* __restrict__ dst) {
    int i = blockIdx.x * 1024 + threadIdx.x;
    if (i < N_EDGESC) atomicAdd(&g_cnt[dst[i]], 1);
}
__global__ void k_scan1() {
    __shared__ int sh[512];
    int i = blockIdx.x * 512 + threadIdx.x;
    int v = (i < N_NODESC) ? g_cnt[i] : 0;
    sh[threadIdx.x] = v;
    __syncthreads();
    for (int off = 1; off < 512; off <<= 1) {
        int t = (threadIdx.x >= off) ? sh[threadIdx.x - off] : 0;
        __syncthreads();
        sh[threadIdx.x] += t;
        __syncthreads();
    }
    if (i < N_NODESC) g_rowpre[i] = sh[threadIdx.x] - v;
    if (threadIdx.x == 511) g_bsum[blockIdx.x] = sh[511];
}
__global__ void k_scan2() {
    if (threadIdx.x == 0) {
        int acc = 0;
        for (int b = 0; b < SCANBLKS; b++) { int v = g_bsum[b]; g_bsum[b] = acc; acc += v; }
        g_rowptr[N_NODESC] = N_EDGESC;
    }
}
__global__ void k_scan3() {
    int i = blockIdx.x * 512 + threadIdx.x;
    if (i < N_NODESC) {
        g_rowptr[i] = g_rowpre[i] + g_bsum[i >> 9];
        g_cnt[i] = 0;
    }
}
__global__ void k_scatter(const int* __restrict__ src, const int* __restrict__ dst,
                          const int* __restrict__ etype) {
    int i = blockIdx.x * 1024 + threadIdx.x;
    if (i < N_EDGESC) {
        int d = dst[i];
        int pos = g_rowptr[d] + atomicAdd(&g_cnt[d], 1);
        g_epack[pos] = (etype[i] << 16) | src[i];
    }
}

#define ROWB 272
#define TILEB 34816
#define SM_GEMM2 (4 * TILEB)   // B(t), B(t+8), A0, A1
#define SM_GEMM3 (4 * TILEB)

// ---------------- gate GEMMs: dual-t per CTA, plain bf16, persistent strips ----------------
__global__ void __launch_bounds__(256, 1) k_tgemm2() {
    extern __shared__ char smem[];
    const uint32_t sb  = smem_u32(smem);
    const uint32_t sB0  = sb;
    const uint32_t sB1  = sb + TILEB;
    const uint32_t sAh0 = sb + 2 * TILEB;
    const uint32_t sAh1 = sb + 3 * TILEB;

    const int tid = threadIdx.x;
    const int lane = tid & 31;
    const int wid = tid >> 5;
    const int t0 = blockIdx.y;
    const int t1 = t0 + 8;
    const int strip = blockIdx.x;
    const int n_m = (MBLKS - strip + STRIPS2 - 1) / STRIPS2;

    {
        const __nv_bfloat16* B0 = g_Bh + (size_t)t0 * DIMC * DIMC;
        const __nv_bfloat16* B1 = g_Bh + (size_t)t1 * DIMC * DIMC;
        const size_t mbase = (size_t)strip * 128 * DIMC;
        for (int idx = tid; idx < 2048; idx += 256) {
            int row = idx >> 4, c = idx & 15;
            uint32_t doff = row * ROWB + c * 16;
            size_t soff = (size_t)row * DIMC + c * 8;
            cp16(sB0 + doff, B0 + soff);
            cp16(sB1 + doff, B1 + soff);
            cp16(sAh0 + doff, g_hh + mbase + soff);
        }
    }
    CP_COMMIT();

    const int mb = (wid & 3) * 32;
    const int nb = (wid >> 2) * 64;
    const int a_row = (lane & 7) + 8 * ((lane >> 3) & 1);
    const int a_kh  = (lane >> 4) * 16;
    const int b_row = (lane & 7) + 8 * (lane >> 4);
    const int b_kh  = ((lane >> 3) & 1) * 16;
    const int rb_local = mb + (lane >> 2);
    const int cbase = nb + 2 * (lane & 3);

    for (int it = 0; it < n_m; it++) {
        const uint32_t sAh = (it & 1) ? sAh1 : sAh0;

        if (it + 1 < n_m) {
            const uint32_t dAh = (it & 1) ? sAh0 : sAh1;
            const size_t mbase = (size_t)(strip + (it + 1) * STRIPS2) * 128 * DIMC;
            for (int idx = tid; idx < 2048; idx += 256) {
                int row = idx >> 4, c = idx & 15;
                cp16(dAh + row * ROWB + c * 16, g_hh + mbase + (size_t)row * DIMC + c * 8);
            }
            CP_COMMIT();
            CP_WAIT(1);
        } else {
            CP_WAIT(0);
        }
        __syncthreads();

        const int m0 = (strip + it * STRIPS2) * 128;

#pragma unroll
        for (int tt = 0; tt < 2; tt++) {
            const uint32_t sB = tt ? sB1 : sB0;
            const int t = tt ? t1 : t0;

            float acc[2][8][4];
#pragma unroll
            for (int i = 0; i < 2; i++)
#pragma unroll
                for (int j = 0; j < 8; j++)
#pragma unroll
                    for (int v = 0; v < 4; v++) acc[i][j][v] = 0.0f;

#pragma unroll
            for (int k0 = 0; k0 < 8; k0++) {
                const uint32_t kbyte = k0 * 32;
                uint32_t ah[2][4], bh[4][4];
#pragma unroll
                for (int mt = 0; mt < 2; mt++)
                    ldmx4(ah[mt], sAh + (mb + mt * 16 + a_row) * ROWB + kbyte + a_kh);
#pragma unroll
                for (int q = 0; q < 4; q++)
                    ldmx4(bh[q], sB + (nb + q * 16 + b_row) * ROWB + kbyte + b_kh);
#pragma unroll
                for (int mt = 0; mt < 2; mt++) {
#pragma unroll
                    for (int nf = 0; nf < 8; nf++) {
                        mma16816(acc[mt][nf], ah[mt],
                                 bh[nf >> 1][(nf & 1) * 2], bh[nf >> 1][(nf & 1) * 2 + 1]);
                    }
                }
            }

#pragma unroll
            for (int mt = 0; mt < 2; mt++) {
#pragma unroll
                for (int pair = 0; pair < 2; pair++) {
                    int m = m0 + rb_local + mt * 16 + pair * 8;
                    if (m >= N_NODESC) continue;
                    __nv_bfloat16* dp = g_projb + ((size_t)t * N_NODESC + m) * DIMC;
#pragma unroll
                    for (int nf = 0; nf < 8; nf++) {
                        float v0 = acc[mt][nf][pair * 2 + 0];
                        float v1 = acc[mt][nf][pair * 2 + 1];
                        uint32_t pk;
                        asm("cvt.rn.satfinite.bf16x2.f32 %0, %1, %2;" : "=r"(pk) : "f"(v1), "f"(v0));
                        *(uint32_t*)(dp + cbase + nf * 8) = pk;
                    }
                }
            }
        }
        __syncthreads();   // all reads of this A buffer done before refill
    }
}

// ---------------- attention GEMM (t=16), 3-term ----------------
__global__ void __launch_bounds__(256, 1) k_tgemm3() {
    extern __shared__ char smem[];
    const uint32_t sb = smem_u32(smem);
    const uint32_t sAh = sb, sAl = sb + TILEB, sBh = sb + 2 * TILEB, sBl = sb + 3 * TILEB;

    const int tid = threadIdx.x;
    const int lane = tid & 31;
    const int wid = tid >> 5;
    const int m0 = blockIdx.x * 128;

    {
        const __nv_bfloat16* Bh = g_Bh + (size_t)16 * DIMC * DIMC;
        const __nv_bfloat16* Bl = g_Bl + (size_t)16 * DIMC * DIMC;
        const size_t mbase = (size_t)m0 * DIMC;
        for (int idx = tid; idx < 2048; idx += 256) {
            int row = idx >> 4, c = idx & 15;
            uint32_t doff = row * ROWB + c * 16;
            size_t soff = (size_t)row * DIMC + c * 8;
            cp16(sAh + doff, g_hh + mbase + soff);
            cp16(sAl + doff, g_hl + mbase + soff);
            cp16(sBh + doff, Bh + soff);
            cp16(sBl + doff, Bl + soff);
        }
    }
    CP_COMMIT();
    CP_WAIT(0);
    __syncthreads();

    const int mb = (wid & 3) * 32;
    const int nb = (wid >> 2) * 64;
    const int a_row = (lane & 7) + 8 * ((lane >> 3) & 1);
    const int a_kh  = (lane >> 4) * 16;
    const int b_row = (lane & 7) + 8 * (lane >> 4);
    const int b_kh  = ((lane >> 3) & 1) * 16;

    float acc[2][8][4];
#pragma unroll
    for (int i = 0; i < 2; i++)
#pragma unroll
        for (int j = 0; j < 8; j++)
#pragma unroll
            for (int v = 0; v < 4; v++) acc[i][j][v] = 0.0f;

#pragma unroll
    for (int k0 = 0; k0 < 8; k0++) {
        const uint32_t kbyte = k0 * 32;
        uint32_t ah[2][4], al[2][4], bh[4][4], bl[4][4];
#pragma unroll
        for (int mt = 0; mt < 2; mt++) {
            uint32_t ar = (mb + mt * 16 + a_row) * ROWB + kbyte + a_kh;
            ldmx4(ah[mt], sAh + ar);
            ldmx4(al[mt], sAl + ar);
        }
#pragma unroll
        for (int q = 0; q < 4; q++) {
            uint32_t br = (nb + q * 16 + b_row) * ROWB + kbyte + b_kh;
            ldmx4(bh[q], sBh + br);
            ldmx4(bl[q], sBl + br);
        }
#pragma unroll
        for (int mt = 0; mt < 2; mt++) {
#pragma unroll
            for (int nf = 0; nf < 8; nf++) {
                uint32_t h0 = bh[nf >> 1][(nf & 1) * 2], h1 = bh[nf >> 1][(nf & 1) * 2 + 1];
                uint32_t l0 = bl[nf >> 1][(nf & 1) * 2], l1 = bl[nf >> 1][(nf & 1) * 2 + 1];
                mma16816(acc[mt][nf], ah[mt], h0, h1);
                mma16816(acc[mt][nf], ah[mt], l0, l1);
                mma16816(acc[mt][nf], al[mt], h0, h1);
            }
        }
    }

    const int rbase = m0 + mb + (lane >> 2);
    const int cbase = nb + 2 * (lane & 3);
#pragma unroll
    for (int mt = 0; mt < 2; mt++) {
#pragma unroll
        for (int pair = 0; pair < 2; pair++) {
            int m = rbase + mt * 16 + pair * 8;
            if (m >= N_NODESC) continue;
            float* dp = g_q + (size_t)m * DIMC;
#pragma unroll
            for (int nf = 0; nf < 8; nf++)
                *(float2*)(dp + cbase + nf * 8) =
                    make_float2(acc[mt][nf][pair * 2], acc[mt][nf][pair * 2 + 1]);
        }
    }
}

// ---------------- warp-per-node message kernel: 4-edge ILP, bf16-split output ----------------
__global__ void __launch_bounds__(256) k_msg2(const float* __restrict__ h,
                                              const float* __restrict__ rel_att,
                                              const float* __restrict__ b_a) {
    const int lane = threadIdx.x & 31;
    const int n = blockIdx.x * 8 + (threadIdx.x >> 5);
    if (n >= N_NODESC) return;
    const int beg = g_rowptr[n];
    const int end = g_rowptr[n + 1];

    float2 qd = *(const float2*)&g_q[(size_t)n * DIMC + lane * 2];
    float2 ba = *(const float2*)&b_a[lane * 2];
    float2 ra = *(const float2*)&rel_att[lane * 2];
    const float qdx = qd.x + ba.x, qdy = qd.y + ba.y;
    const __nv_bfloat16* pdbase = g_projb + (size_t)n * DIMC + lane * 4;

    float a0 = 0.f, a1 = 0.f, a2 = 0.f, a3 = 0.f, den = 0.f;

    int e = beg;
    for (; e + 4 <= end; e += 4) {
        int s[4], r[4];
        float2 qs[4];
        uint2 pdw[4], psw[4];
        float4 hs[4];
#pragma unroll
        for (int j = 0; j < 4; j++) {
            int pack = __ldg(&g_epack[e + j]);
            s[j] = pack & 0xFFFF;
            r[j] = pack >> 16;
        }
#pragma unroll
        for (int j = 0; j < 4; j++) {
            qs[j]  = *(const float2*)&g_q[(size_t)s[j] * DIMC + A_DIMC + lane * 2];
            pdw[j] = *(const uint2*)(pdbase + (size_t)r[j] * N_NODESC * DIMC);
            psw[j] = *(const uint2*)(g_projb + ((size_t)(8 + r[j]) * N_NODESC + s[j]) * DIMC + lane * 4);
            hs[j]  = *(const float4*)&h[(size_t)s[j] * DIMC + lane * 4];
        }
        float p[4];
#pragma unroll
        for (int j = 0; j < 4; j++) {
            float u = qdx + qs[j].x, v = qdy + qs[j].y;
            u = fmaxf(u, 0.01f * u);
            v = fmaxf(v, 0.01f * v);
            p[j] = ra.x * u + ra.y * v;
        }
#pragma unroll
        for (int o = 16; o > 0; o >>= 1) {
#pragma unroll
            for (int j = 0; j < 4; j++)
                p[j] += __shfl_xor_sync(0xffffffffu, p[j], o);
        }
#pragma unroll
        for (int j = 0; j < 4; j++) {
            float ex = __expf(p[j]);
            float2 pd0 = __bfloat1622float2(*(__nv_bfloat162*)&pdw[j].x);
            float2 pd1 = __bfloat1622float2(*(__nv_bfloat162*)&pdw[j].y);
            float2 ps0 = __bfloat1622float2(*(__nv_bfloat162*)&psw[j].x);
            float2 ps1 = __bfloat1622float2(*(__nv_bfloat162*)&psw[j].y);
            a0 += hs[j].x * ex * fsig(pd0.x + ps0.x);
            a1 += hs[j].y * ex * fsig(pd0.y + ps0.y);
            a2 += hs[j].z * ex * fsig(pd1.x + ps1.x);
            a3 += hs[j].w * ex * fsig(pd1.y + ps1.y);
            den += ex;
        }
    }
    for (; e < end; e++) {
        int pack = __ldg(&g_epack[e]);
        int s0 = pack & 0xFFFF, r0 = pack >> 16;
        float2 qs0 = *(const float2*)&g_q[(size_t)s0 * DIMC + A_DIMC + lane * 2];
        uint2 pdw0 = *(const uint2*)(pdbase + (size_t)r0 * N_NODESC * DIMC);
        uint2 psw0 = *(const uint2*)(g_projb + ((size_t)(8 + r0) * N_NODESC + s0) * DIMC + lane * 4);
        float4 hs0 = *(const float4*)&h[(size_t)s0 * DIMC + lane * 4];
        float u0 = qdx + qs0.x, v0 = qdy + qs0.y;
        u0 = fmaxf(u0, 0.01f * u0);
        v0 = fmaxf(v0, 0.01f * v0);
        float p0 = ra.x * u0 + ra.y * v0;
#pragma unroll
        for (int o = 16; o > 0; o >>= 1) p0 += __shfl_xor_sync(0xffffffffu, p0, o);
        float ex0 = __expf(p0);
        float2 pd00 = __bfloat1622float2(*(__nv_bfloat162*)&pdw0.x);
        float2 pd01 = __bfloat1622float2(*(__nv_bfloat162*)&pdw0.y);
        float2 ps00 = __bfloat1622float2(*(__nv_bfloat162*)&psw0.x);
        float2 ps01 = __bfloat1622float2(*(__nv_bfloat162*)&psw0.y);
        a0 += hs0.x * ex0 * fsig(pd00.x + ps00.x);
        a1 += hs0.y * ex0 * fsig(pd00.y + ps00.y);
        a2 += hs0.z * ex0 * fsig(pd01.x + ps01.x);
        a3 += hs0.w * ex0 * fsig(pd01.y + ps01.y);
        den += ex0;
    }

    float inv = (den > 0.f) ? __frcp_rn(den) : 0.f;
    float v0 = a0 * inv, v1 = a1 * inv, v2 = a2 * inv, v3 = a3 * inv;

    __nv_bfloat16 b0 = __float2bfloat16(v0);
    __nv_bfloat16 b1 = __float2bfloat16(v1);
    __nv_bfloat16 b2 = __float2bfloat16(v2);
    __nv_bfloat16 b3 = __float2bfloat16(v3);
    __nv_bfloat162* ph = (__nv_bfloat162*)&g_hNh[(size_t)n * DIMC + lane * 4];
    ph[0] = __nv_bfloat162(b0, b1);
    ph[1] = __nv_bfloat162(b2, b3);
    __nv_bfloat162* pl = (__nv_bfloat162*)&g_hNl[(size_t)n * DIMC + lane * 4];
    pl[0] = __floats2bfloat162_rn(v0 - __bfloat162float(b0), v1 - __bfloat162float(b1));
    pl[1] = __floats2bfloat162_rn(v2 - __bfloat162float(b2), v3 - __bfloat162float(b3));
}

// ---------------- final GEMM on HMMA: out = leaky([h ; h_N] @ W_lin^T + b_lin) ----------------
__global__ void __launch_bounds__(256, 1) k_final(float* __restrict__ out,
                                                  const float* __restrict__ b_lin) {
    extern __shared__ char smem[];
    const uint32_t sb = smem_u32(smem);
    const uint32_t sAh = sb, sAl = sb + TILEB, sBh = sb + 2 * TILEB, sBl = sb + 3 * TILEB;

    const int tid = threadIdx.x;
    const int lane = tid & 31;
    const int wid = tid >> 5;
    const int m0 = blockIdx.x * 128;

    const int mb = (wid & 3) * 32;
    const int nb = (wid >> 2) * 64;
    const int a_row = (lane & 7) + 8 * ((lane >> 3) & 1);
    const int a_kh  = (lane >> 4) * 16;
    const int b_row = (lane & 7) + 8 * (lane >> 4);
    const int b_kh  = ((lane >> 3) & 1) * 16;

    float acc[2][8][4];
#pragma unroll
    for (int i = 0; i < 2; i++)
#pragma unroll
        for (int j = 0; j < 8; j++)
#pragma unroll
            for (int v = 0; v < 4; v++) acc[i][j][v] = 0.0f;

    for (int kt = 0; kt < 2; kt++) {
        const __nv_bfloat16* Ah = (kt ? g_hNh : g_hh) + (size_t)m0 * DIMC;
        const __nv_bfloat16* Al = (kt ? g_hNl : g_hl) + (size_t)m0 * DIMC;
        const __nv_bfloat16* Bh = g_Wlh + kt * DIMC * DIMC;
        const __nv_bfloat16* Bl = g_Wll + kt * DIMC * DIMC;
        for (int idx = tid; idx < 2048; idx += 256) {
            int row = idx >> 4, c = idx & 15;
            uint32_t doff = row * ROWB + c * 16;
            size_t soff = (size_t)row * DIMC + c * 8;
            cp16(sAh + doff, Ah + soff);
            cp16(sAl + doff, Al + soff);
            cp16(sBh + doff, Bh + soff);
            cp16(sBl + doff, Bl + soff);
        }
        CP_COMMIT();
        CP_WAIT(0);
        __syncthreads();

#pragma unroll
        for (int k0 = 0; k0 < 8; k0++) {
            const uint32_t kbyte = k0 * 32;
            uint32_t ah[2][4], al[2][4], bh[4][4], bl[4][4];
#pragma unroll
            for (int mt = 0; mt < 2; mt++) {
                uint32_t ar = (mb + mt * 16 + a_row) * ROWB + kbyte + a_kh;
                ldmx4(ah[mt], sAh + ar);
                ldmx4(al[mt], sAl + ar);
            }
#pragma unroll
            for (int q = 0; q < 4; q++) {
                uint32_t br = (nb + q * 16 + b_row) * ROWB + kbyte + b_kh;
                ldmx4(bh[q], sBh + br);
                ldmx4(bl[q], sBl + br);
            }
#pragma unroll
            for (int mt = 0; mt < 2; mt++) {
#pragma unroll
                for (int nf = 0; nf < 8; nf++) {
                    uint32_t h0 = bh[nf >> 1][(nf & 1) * 2], h1 = bh[nf >> 1][(nf & 1) * 2 + 1];
                    uint32_t l0 = bl[nf >> 1][(nf & 1) * 2], l1 = bl[nf >> 1][(nf & 1) * 2 + 1];
                    mma16816(acc[mt][nf], ah[mt], h0, h1);
                    mma16816(acc[mt][nf], ah[mt], l0, l1);
                    mma16816(acc[mt][nf], al[mt], h0, h1);
                }
            }
        }
        __syncthreads();
    }

    const int rbase = m0 + mb + (lane >> 2);
    const int cbase = nb + 2 * (lane & 3);
#pragma unroll
    for (int mt = 0; mt < 2; mt++) {
#pragma unroll
        for (int pair = 0; pair < 2; pair++) {
            int m = rbase + mt * 16 + pair * 8;
            if (m >= N_NODESC) continue;
            float* cp = out + (size_t)m * DIMC;
#pragma unroll
            for (int nf = 0; nf < 8; nf++) {
                float2 bl2 = *(const float2*)&b_lin[cbase + nf * 8];
                float v0 = acc[mt][nf][pair * 2 + 0] + bl2.x;
                float v1 = acc[mt][nf][pair * 2 + 1] + bl2.y;
                v0 = v0 > 0.f ? v0 : 0.01f * v0;
                v1 = v1 > 0.f ? v1 : 0.01f * v1;
                *(float2*)(cp + cbase + nf * 8) = make_float2(v0, v1);
            }
        }
    }
}

// ---------------- persistent stream/event context (created once, reused) ----------------
struct Ctx {
    cudaStream_t sA, sB;
    cudaEvent_t eRoot, eP, eCSR, eT3;
    Ctx() {
        cudaStreamCreateWithFlags(&sA, cudaStreamNonBlocking);
        cudaStreamCreateWithFlags(&sB, cudaStreamNonBlocking);
        cudaEventCreateWithFlags(&eRoot, cudaEventDisableTiming);
        cudaEventCreateWithFlags(&eP,    cudaEventDisableTiming);
        cudaEventCreateWithFlags(&eCSR,  cudaEventDisableTiming);
        cudaEventCreateWithFlags(&eT3,   cudaEventDisableTiming);
        cudaFuncSetAttribute(k_tgemm2, cudaFuncAttributeMaxDynamicSharedMemorySize, SM_GEMM2);
        cudaFuncSetAttribute(k_tgemm3, cudaFuncAttributeMaxDynamicSharedMemorySize, SM_GEMM3);
        cudaFuncSetAttribute(k_final,  cudaFuncAttributeMaxDynamicSharedMemorySize, SM_GEMM3);
    }
};

// ---------------- launch (fork CSR + tgemm3 onto side streams) ----------------
extern "C" void kernel_launch(void* const* d_in, const int* in_sizes, int n_in,
                              void* d_out, int out_size) {
    const float* h      = (const float*)d_in[0];
    const float* rel    = (const float*)d_in[1];
    const float* relatt = (const float*)d_in[2];
    const float* W_a    = (const float*)d_in[3];
    const float* b_a    = (const float*)d_in[4];
    const float* W_lin  = (const float*)d_in[5];
    const float* b_lin  = (const float*)d_in[6];
    const int* src   = (const int*)d_in[7];
    const int* dst   = (const int*)d_in[8];
    const int* etype = (const int*)d_in[9];
    float* out = (float*)d_out;

    // created exactly once (first call = correctness run, before capture baseline);
    // reused on every subsequent call -> no allocation during capture or replay.
    static Ctx ctx;

    // fork side streams off the main (capture) stream
    cudaEventRecord(ctx.eRoot, 0);
    cudaStreamWaitEvent(ctx.sA, ctx.eRoot, 0);
    cudaStreamWaitEvent(ctx.sB, ctx.eRoot, 0);

    // --- CSR build on sA (independent of prep) ---
    k_csr0<<<(N_NODESC + 1023) / 1024, 1024, 0, ctx.sA>>>();
    k_hist<<<(N_EDGESC + 1023) / 1024, 1024, 0, ctx.sA>>>(dst);
    k_scan1<<<SCANBLKS, 512, 0, ctx.sA>>>();
    k_scan2<<<1, 32, 0, ctx.sA>>>();
    k_scan3<<<SCANBLKS, 512, 0, ctx.sA>>>();
    k_scatter<<<(N_EDGESC + 1023) / 1024, 1024, 0, ctx.sA>>>(src, dst, etype);
    cudaEventRecord(ctx.eCSR, ctx.sA);

    // --- prep on main stream ---
    k_cvtA<<<(N_NODESC * DIMC + 255) / 256, 256>>>(h);
    k_prepB<<<(TCNT * DIMC * DIMC + 255) / 256, 256>>>(rel, W_a, W_lin);
    cudaEventRecord(ctx.eP, 0);

    // --- attention GEMM on sB (after prep) ---
    cudaStreamWaitEvent(ctx.sB, ctx.eP, 0);
    k_tgemm3<<<MBLKS, 256, SM_GEMM3, ctx.sB>>>();
    cudaEventRecord(ctx.eT3, ctx.sB);

    // --- gate GEMMs on main stream ---
    dim3 gg(STRIPS2, 8);
    k_tgemm2<<<gg, 256, SM_GEMM2>>>();

    // --- join before message passing ---
    cudaStreamWaitEvent(0, ctx.eCSR, 0);
    cudaStreamWaitEvent(0, ctx.eT3, 0);

    k_msg2<<<(N_NODESC + 7) / 8, 256>>>(h, relatt, b_a);
    k_final<<<MBLKS, 256, SM_GEMM3>>>(out, b_lin);
}